// round 7
// baseline (speedup 1.0000x reference)
#include <cuda_runtime.h>
#include <cuda_bf16.h>
#include <cstdint>

#define TT 1024
#define RR 64
#define SS 16
#define MMEM 16
#define BB 8
#define DD 512
#define HH 8
#define DHH 64
#define TQ_ 1104
#define TK_ 1104
#define SCALE_ 0.125f
#define NEGINF_ (-1.0e8f)

typedef __nv_bfloat16 bf16;

// ---------------- scratch (device globals; allocation-free rule) ----------------
__device__ bf16 g_qin_hi [(size_t)TQ_ * BB * DD];
__device__ bf16 g_qin_lo [(size_t)TQ_ * BB * DD];
__device__ bf16 g_kvin_hi[(size_t)TK_ * BB * DD];
__device__ bf16 g_kvin_lo[(size_t)TK_ * BB * DD];
__device__ bf16 g_w_hi[(size_t)2048 * DD];   // Wq | Wkv | Wo rows
__device__ bf16 g_w_lo[(size_t)2048 * DD];
__device__ bf16 g_q_hi[(size_t)TQ_ * BB * DD];
__device__ bf16 g_q_lo[(size_t)TQ_ * BB * DD];
__device__ bf16 g_k_hi[(size_t)TK_ * BB * DD];
__device__ bf16 g_k_lo[(size_t)TK_ * BB * DD];
__device__ bf16 g_v_hi[(size_t)TK_ * BB * DD];
__device__ bf16 g_v_lo[(size_t)TK_ * BB * DD];
__device__ bf16 g_a_hi[(size_t)TQ_ * BB * DD];
__device__ bf16 g_a_lo[(size_t)TQ_ * BB * DD];
__device__ unsigned char g_mask[(size_t)TQ_ * TK_];
__device__ int g_mask_mode;

__device__ __forceinline__ float neg_inf_f() { return __int_as_float(0xff800000); }

// ---------------- low-level helpers (sm_80-era only; no 'a' features) ----------------
__device__ __forceinline__ uint32_t smem_to_u32(const void* p) {
    uint32_t a;
    asm("{ .reg .u64 t; cvta.to.shared.u64 t, %1; cvt.u32.u64 %0, t; }" : "=r"(a) : "l"(p));
    return a;
}
__device__ __forceinline__ void ldmat4(uint32_t r[4], uint32_t addr) {
    asm volatile("ldmatrix.sync.aligned.m8n8.x4.shared.b16 {%0,%1,%2,%3}, [%4];"
                 : "=r"(r[0]), "=r"(r[1]), "=r"(r[2]), "=r"(r[3]) : "r"(addr));
}
__device__ __forceinline__ void ldmat4t(uint32_t r[4], uint32_t addr) {
    asm volatile("ldmatrix.sync.aligned.m8n8.x4.trans.shared.b16 {%0,%1,%2,%3}, [%4];"
                 : "=r"(r[0]), "=r"(r[1]), "=r"(r[2]), "=r"(r[3]) : "r"(addr));
}
__device__ __forceinline__ void mma16816(float d[4], const uint32_t a[4],
                                         uint32_t b0, uint32_t b1) {
    asm volatile("mma.sync.aligned.m16n8k16.row.col.f32.bf16.bf16.f32 "
                 "{%0,%1,%2,%3}, {%4,%5,%6,%7}, {%8,%9}, {%0,%1,%2,%3};"
                 : "+f"(d[0]), "+f"(d[1]), "+f"(d[2]), "+f"(d[3])
                 : "r"(a[0]), "r"(a[1]), "r"(a[2]), "r"(a[3]), "r"(b0), "r"(b1));
}
__device__ __forceinline__ void cp16(uint32_t dst, const void* src, int bytes) {
    asm volatile("cp.async.cg.shared.global [%0], [%1], 16, %2;"
                 :: "r"(dst), "l"(src), "r"(bytes));
}
#define CP_COMMIT() asm volatile("cp.async.commit_group;" ::: "memory")
#define CP_WAIT0()  asm volatile("cp.async.wait_group 0;" ::: "memory")
#define CP_WAIT1()  asm volatile("cp.async.wait_group 1;" ::: "memory")

#define SWZ(o) ((o) ^ (((o) >> 3) & 0x70))

__device__ __forceinline__ uint32_t pk2(bf16 a, bf16 b) {
    return ((uint32_t)__bfloat16_as_ushort(b) << 16) | __bfloat16_as_ushort(a);
}
__device__ __forceinline__ uint32_t pk_hi(float a, float b) {
    return pk2(__float2bfloat16(a), __float2bfloat16(b));
}
__device__ __forceinline__ uint32_t pk_lo(float a, float b) {
    bf16 ha = __float2bfloat16(a), hb = __float2bfloat16(b);
    return pk2(__float2bfloat16(a - __bfloat162float(ha)),
               __float2bfloat16(b - __bfloat162float(hb)));
}

// ---------------- mask dtype detect + canonicalize ----------------
__global__ void detect_mask_mode_kernel(const unsigned char* __restrict__ buf)
{
    __shared__ int s_large, s_nzoff;
    if (threadIdx.x == 0) { s_large = 0; s_nzoff = 0; }
    __syncthreads();
    const int N = 1 << 18;
    int l = 0, z = 0;
    for (int i = threadIdx.x; i < N; i += blockDim.x) {
        unsigned char v = buf[i];
        if (v > 1) l = 1;
        if ((i & 3) && v != 0) z = 1;
    }
    if (l) atomicOr(&s_large, 1);
    if (z) atomicOr(&s_nzoff, 1);
    __syncthreads();
    if (threadIdx.x == 0) g_mask_mode = s_large ? 2 : (s_nzoff ? 0 : 1);
}
__global__ void convert_mask_kernel(const unsigned char* __restrict__ buf)
{
    const int idx = blockIdx.x * blockDim.x + threadIdx.x;
    if (idx >= TQ_ * TK_) return;
    const int mode = g_mask_mode;
    unsigned char m;
    if (mode == 0)      m = buf[idx] ? 1 : 0;
    else if (mode == 1) m = (((const int*)buf)[idx] != 0) ? 1 : 0;
    else                m = (((const float*)buf)[idx] != 0.f) ? 1 : 0;
    g_mask[idx] = m;
}

// ---------------- prepass: fp32 -> split bf16 ----------------
__global__ void __launch_bounds__(256) convert_in_kernel(
    const float* __restrict__ utt, const float* __restrict__ rc,
    const float* __restrict__ smr, const float* __restrict__ mem)
{
    const size_t e = ((size_t)blockIdx.x * blockDim.x + threadIdx.x) * 4;
    if (e >= (size_t)TQ_ * BB * DD) return;
    const int r = (int)(e >> 9);
    const int k = (int)(e & 511);
    const int t = r >> 3, b = r & 7;
    const float* src;
    if (blockIdx.y == 0) {
        if (t < RR)           src = rc  + ((size_t)t * BB + b) * DD;
        else if (t < RR + TT) src = utt + ((size_t)(t - RR) * BB + b) * DD;
        else                  src = smr + ((size_t)(t - RR - TT) * BB + b) * DD;
    } else {
        if (t < MMEM)           src = mem + ((size_t)t * BB + b) * DD;
        else if (t < MMEM + RR) src = rc  + ((size_t)(t - MMEM) * BB + b) * DD;
        else                    src = utt + ((size_t)(t - MMEM - RR) * BB + b) * DD;
    }
    float4 v = *(const float4*)(src + k);
    bf16* dh = blockIdx.y ? g_kvin_hi : g_qin_hi;
    bf16* dl = blockIdx.y ? g_kvin_lo : g_qin_lo;
    *(uint2*)&dh[e] = make_uint2(pk_hi(v.x, v.y), pk_hi(v.z, v.w));
    *(uint2*)&dl[e] = make_uint2(pk_lo(v.x, v.y), pk_lo(v.z, v.w));
}

__global__ void __launch_bounds__(256) convert_w_kernel(
    const float* __restrict__ Wq, const float* __restrict__ Wkv, const float* __restrict__ Wo)
{
    const size_t e = ((size_t)blockIdx.x * blockDim.x + threadIdx.x) * 4;
    if (e >= (size_t)2048 * DD) return;
    const int r = (int)(e >> 9);
    const int k = (int)(e & 511);
    const float* src;
    if (r < 512)       src = Wq  + (size_t)r * DD;
    else if (r < 1536) src = Wkv + (size_t)(r - 512) * DD;
    else               src = Wo  + (size_t)(r - 1536) * DD;
    float4 v = *(const float4*)(src + k);
    *(uint2*)&g_w_hi[e] = make_uint2(pk_hi(v.x, v.y), pk_hi(v.z, v.w));
    *(uint2*)&g_w_lo[e] = make_uint2(pk_lo(v.x, v.y), pk_lo(v.z, v.w));
}

// ---------------------------------------------------------------------------
// HMMA split-bf16 GEMM (UNCHANGED from Round 4 — known good):
// D[64m x 64n] = A[m,k]*B[n,k]^T + bias, K=512.
// 128 threads / 4 warps (2x2), warp tile 32m x 32n, k-step 16, 3-MMA split.
// cp.async double-buffered stages of K=64. dyn smem = 64KB.
// ---------------------------------------------------------------------------
template <int MODE>
__global__ void __launch_bounds__(128) tc_gemm(
    const bf16* __restrict__ a_hi, const bf16* __restrict__ a_lo,
    const bf16* __restrict__ b_hi, const bf16* __restrict__ b_lo,
    const float* __restrict__ bias, float* __restrict__ dout)
{
    extern __shared__ char smc[];
    const uint32_t smb = smem_to_u32(smc);
    const int tid = threadIdx.x, w = tid >> 5, lane = tid & 31;
    const int wm = w >> 1, wn = w & 1;
    const int m0 = blockIdx.y * 64, n0 = blockIdx.x * 64;

    const bf16* srcs[4] = { a_hi + (size_t)m0 * DD, a_lo + (size_t)m0 * DD,
                            b_hi + (size_t)n0 * DD, b_lo + (size_t)n0 * DD };
    const int ldrow = tid >> 1;          // 0..63
    const int ldc0  = (tid & 1) * 4;     // 16B segment base

    auto issue_stage = [&](int kc, int buf) {
#pragma unroll
        for (int t = 0; t < 4; t++) {
            const bf16* src = srcs[t] + (size_t)ldrow * DD + kc * 64 + ldc0 * 8;
            uint32_t db = smb + buf * 32768 + t * 8192;
#pragma unroll
            for (int i = 0; i < 4; i++)
                cp16(db + SWZ((uint32_t)(ldrow * 128 + (ldc0 + i) * 16)), src + i * 8, 16);
        }
        CP_COMMIT();
    };

    float acc[2][4][4];
#pragma unroll
    for (int a = 0; a < 2; a++)
#pragma unroll
        for (int c = 0; c < 4; c++)
#pragma unroll
            for (int d = 0; d < 4; d++) acc[a][c][d] = 0.f;

    const int rr  = (lane & 7) + ((lane >> 3) & 1) * 8;
    const int kk8 = (lane >> 4) * 8;

    issue_stage(0, 0);
    for (int c = 0; c < 8; c++) {
        if (c < 7) { issue_stage(c + 1, (c + 1) & 1); CP_WAIT1(); }
        else       { CP_WAIT0(); }
        __syncthreads();
        const uint32_t base = smb + (c & 1) * 32768;
#pragma unroll
        for (int kd = 0; kd < 4; kd++) {
            const uint32_t ko = (uint32_t)((kd * 16 + kk8) * 2);
            uint32_t ah[2][4], al[2][4], bh[2][4], bl[2][4];
#pragma unroll
            for (int mt = 0; mt < 2; mt++) {
                uint32_t off = SWZ((uint32_t)((wm * 32 + mt * 16 + rr) * 128) + ko);
                ldmat4(ah[mt], base + off);
                ldmat4(al[mt], base + 8192 + off);
            }
#pragma unroll
            for (int p = 0; p < 2; p++) {
                uint32_t off = SWZ((uint32_t)((wn * 32 + p * 16 + rr) * 128) + ko);
                ldmat4(bh[p], base + 16384 + off);
                ldmat4(bl[p], base + 24576 + off);
            }
#pragma unroll
            for (int mt = 0; mt < 2; mt++)
#pragma unroll
                for (int nt = 0; nt < 4; nt++) {
                    uint32_t b0h = bh[nt >> 1][nt & 1], b1h = bh[nt >> 1][2 + (nt & 1)];
                    uint32_t b0l = bl[nt >> 1][nt & 1], b1l = bl[nt >> 1][2 + (nt & 1)];
                    mma16816(acc[mt][nt], ah[mt], b0h, b1h);
                    mma16816(acc[mt][nt], ah[mt], b0l, b1l);
                    mma16816(acc[mt][nt], al[mt], b0h, b1h);
                }
        }
        __syncthreads();
    }

    // epilogue
    const int lq = lane >> 2, lc = (lane & 3) * 2;
#pragma unroll
    for (int mt = 0; mt < 2; mt++) {
#pragma unroll
        for (int nt = 0; nt < 4; nt++) {
            const int col = n0 + wn * 32 + nt * 8 + lc;
            const float b0 = bias[col], b1 = bias[col + 1];
#pragma unroll
            for (int hrow = 0; hrow < 2; hrow++) {
                const int m = m0 + wm * 32 + mt * 16 + lq + hrow * 8;
                float v0 = acc[mt][nt][hrow * 2 + 0] + b0;
                float v1 = acc[mt][nt][hrow * 2 + 1] + b1;
                if (MODE == 0) {
                    v0 *= SCALE_; v1 *= SCALE_;
                    *(uint32_t*)&g_q_hi[(size_t)m * DD + col] = pk_hi(v0, v1);
                    *(uint32_t*)&g_q_lo[(size_t)m * DD + col] = pk_lo(v0, v1);
                } else if (MODE == 1) {
                    if (col < DD) {
                        *(uint32_t*)&g_k_hi[(size_t)m * DD + col] = pk_hi(v0, v1);
                        *(uint32_t*)&g_k_lo[(size_t)m * DD + col] = pk_lo(v0, v1);
                    } else {
                        *(uint32_t*)&g_v_hi[(size_t)m * DD + col - DD] = pk_hi(v0, v1);
                        *(uint32_t*)&g_v_lo[(size_t)m * DD + col - DD] = pk_lo(v0, v1);
                    }
                } else {
                    const int tt = m >> 3, rb = m & 7;
                    if (tt < TQ_ - SS) {
                        *(float2*)&dout[(size_t)m * DD + col] = make_float2(v0, v1);
                    } else if (tt < TQ_ - 1) {
                        v0 = fminf(10.f, fmaxf(-10.f, v0));
                        v1 = fminf(10.f, fmaxf(-10.f, v1));
                        *(float2*)&dout[(size_t)(TQ_ - SS) * BB * DD +
                                        ((size_t)(tt - (TQ_ - SS)) * BB + rb) * DD + col] =
                            make_float2(v0, v1);
                    }
                }
            }
        }
    }
}

// ---------------------------------------------------------------------------
// HMMA flash attention, double-buffered K/V staging. CTA = (q-tile 64, b, h).
// 128 threads / 4 warps, warp owns 16 q rows.
// FIX vs R5/R6: ntiles uses ceil-div — TK_=1104 is NOT a multiple of 64, so
// (min(TK_, align64(klen)))>>6 dropped the final partial tile (keys 1088..1103)
// whenever klen > 1088.
// smem: Qh 8K | Ql 8K | stage0 32K | stage1 32K = 80KB.
// ---------------------------------------------------------------------------
__global__ void __launch_bounds__(128) attn_kernel(const int* __restrict__ lengths)
{
    extern __shared__ char smc[];
    const uint32_t smb = smem_to_u32(smc);
    const uint32_t Qh = smb, Ql = smb + 8192;

    const int tid = threadIdx.x, w = tid >> 5, lane = tid & 31;
    const int b = blockIdx.y >> 3, h = blockIdx.y & 7;
    const int q0 = blockIdx.x * 64;

    int maxlen = 0;
#pragma unroll
    for (int i = 0; i < BB; i++) maxlen = max(maxlen, lengths[i]);
    const int klen = lengths[b] + MMEM + (TQ_ - maxlen - SS);
    const int kend = min(TK_, (klen + 63) & ~63);
    const int ntiles = (kend + 63) >> 6;    // CEIL: partial last tile included

    const int ldrow = tid >> 1;          // 0..63
    const int ldc0  = (tid & 1) * 4;

    auto stage = [&](int c) {
        const uint32_t sb = smb + 16384 + (c & 1) * 32768;
        const int tk = c * 64 + ldrow;
        const int bytes = (tk < TK_) ? 16 : 0;
        const size_t go = ((size_t)tk * BB + b) * DD + h * DHH + ldc0 * 8;
#pragma unroll
        for (int i = 0; i < 4; i++) {
            uint32_t so = SWZ((uint32_t)(ldrow * 128 + (ldc0 + i) * 16));
            cp16(sb + so,         g_k_hi + go + i * 8, bytes);
            cp16(sb + 8192 + so,  g_k_lo + go + i * 8, bytes);
            cp16(sb + 16384 + so, g_v_hi + go + i * 8, bytes);
            cp16(sb + 24576 + so, g_v_lo + go + i * 8, bytes);
        }
        CP_COMMIT();
    };

    // stage Q (hi/lo), then stage(0) — overlapped; WAIT1 drains Q group only
    {
        const int q = q0 + ldrow;
        const int bytes = (q < TQ_) ? 16 : 0;
        const size_t go = ((size_t)q * BB + b) * DD + h * DHH + ldc0 * 8;
#pragma unroll
        for (int i = 0; i < 4; i++) {
            uint32_t so = SWZ((uint32_t)(ldrow * 128 + (ldc0 + i) * 16));
            cp16(Qh + so, g_q_hi + go + i * 8, bytes);
            cp16(Ql + so, g_q_lo + go + i * 8, bytes);
        }
        CP_COMMIT();
    }
    stage(0);
    CP_WAIT1();          // Q group complete; stage(0) may still fly
    __syncthreads();

    const int rr  = (lane & 7) + ((lane >> 3) & 1) * 8;
    const int kk8 = (lane >> 4) * 8;

    uint32_t qh[4][4], ql[4][4];
#pragma unroll
    for (int kd = 0; kd < 4; kd++) {
        uint32_t off = SWZ((uint32_t)((16 * w + rr) * 128 + (kd * 16 + kk8) * 2));
        ldmat4(qh[kd], Qh + off);
        ldmat4(ql[kd], Ql + off);
    }

    float o[8][4];
#pragma unroll
    for (int j = 0; j < 8; j++)
#pragma unroll
        for (int d = 0; d < 4; d++) o[j][d] = 0.f;
    float mr0 = neg_inf_f(), mr1 = neg_inf_f(), lr0 = 0.f, lr1 = 0.f;

    const int lq = lane >> 2, lc = (lane & 3) * 2;
    const int qr0 = q0 + 16 * w + lq, qr1 = qr0 + 8;

    for (int c = 0; c < ntiles; c++) {
        if (c + 1 < ntiles) { stage(c + 1); CP_WAIT1(); }
        else                { CP_WAIT0(); }
        __syncthreads();

        const uint32_t Kh = smb + 16384 + (c & 1) * 32768;
        const uint32_t Kl = Kh + 8192, Vh = Kh + 16384, Vl = Kh + 24576;
        const int k0 = c * 64;

        // ---- S = Q K^T ----
        float s[8][4];
#pragma unroll
        for (int j = 0; j < 8; j++)
#pragma unroll
            for (int d = 0; d < 4; d++) s[j][d] = 0.f;

#pragma unroll
        for (int kd = 0; kd < 4; kd++) {
            const uint32_t ko = (uint32_t)((kd * 16 + kk8) * 2);
#pragma unroll
            for (int p = 0; p < 4; p++) {
                uint32_t kh4[4], kl4[4];
                uint32_t off = SWZ((uint32_t)((p * 16 + rr) * 128) + ko);
                ldmat4(kh4, Kh + off);
                ldmat4(kl4, Kl + off);
                mma16816(s[2 * p],     qh[kd], kh4[0], kh4[2]);
                mma16816(s[2 * p],     qh[kd], kl4[0], kl4[2]);
                mma16816(s[2 * p],     ql[kd], kh4[0], kh4[2]);
                mma16816(s[2 * p + 1], qh[kd], kh4[1], kh4[3]);
                mma16816(s[2 * p + 1], qh[kd], kl4[1], kl4[3]);
                mma16816(s[2 * p + 1], ql[kd], kh4[1], kh4[3]);
            }
        }

        // ---- mask ----
#pragma unroll
        for (int j = 0; j < 8; j++) {
            const int kc = k0 + 8 * j + lc;
            const bool in_k = (kc < TK_ - 1);   // kc even; pair fits iff kc <= 1102
            uchar2 mA = make_uchar2(1, 1), mB = make_uchar2(1, 1);
            if (in_k && qr0 < TQ_) mA = *(const uchar2*)&g_mask[(size_t)qr0 * TK_ + kc];
            if (in_k && qr1 < TQ_) mB = *(const uchar2*)&g_mask[(size_t)qr1 * TK_ + kc];
            if (kc >= TK_) {
                s[j][0] = s[j][2] = neg_inf_f();
            } else if (mA.x || kc >= klen) s[j][0] = NEGINF_;
            if (kc >= TK_) { /* handled */ }
            if (kc < TK_ && (mB.x || kc >= klen)) s[j][2] = NEGINF_;
            if (kc + 1 >= TK_) {
                s[j][1] = s[j][3] = neg_inf_f();
            } else {
                if (mA.y || kc + 1 >= klen) s[j][1] = NEGINF_;
                if (mB.y || kc + 1 >= klen) s[j][3] = NEGINF_;
            }
        }

        // ---- online softmax (rows qr0, qr1; quad-lane reductions) ----
        float mx0 = NEGINF_, mx1 = NEGINF_;
#pragma unroll
        for (int j = 0; j < 8; j++) {
            mx0 = fmaxf(mx0, fmaxf(s[j][0], s[j][1]));
            mx1 = fmaxf(mx1, fmaxf(s[j][2], s[j][3]));
        }
        mx0 = fmaxf(mx0, __shfl_xor_sync(0xffffffffu, mx0, 1));
        mx0 = fmaxf(mx0, __shfl_xor_sync(0xffffffffu, mx0, 2));
        mx1 = fmaxf(mx1, __shfl_xor_sync(0xffffffffu, mx1, 1));
        mx1 = fmaxf(mx1, __shfl_xor_sync(0xffffffffu, mx1, 2));
        const float mn0 = fmaxf(mr0, mx0), mn1 = fmaxf(mr1, mx1);
        const float a0 = __expf(mr0 - mn0), a1 = __expf(mr1 - mn1);
        float su0 = 0.f, su1 = 0.f;
#pragma unroll
        for (int j = 0; j < 8; j++) {
            s[j][0] = __expf(s[j][0] - mn0);
            s[j][1] = __expf(s[j][1] - mn0);
            s[j][2] = __expf(s[j][2] - mn1);
            s[j][3] = __expf(s[j][3] - mn1);
            su0 += s[j][0] + s[j][1];
            su1 += s[j][2] + s[j][3];
        }
        su0 += __shfl_xor_sync(0xffffffffu, su0, 1);
        su0 += __shfl_xor_sync(0xffffffffu, su0, 2);
        su1 += __shfl_xor_sync(0xffffffffu, su1, 1);
        su1 += __shfl_xor_sync(0xffffffffu, su1, 2);
        lr0 = lr0 * a0 + su0;  mr0 = mn0;
        lr1 = lr1 * a1 + su1;  mr1 = mn1;
#pragma unroll
        for (int j = 0; j < 8; j++) {
            o[j][0] *= a0; o[j][1] *= a0;
            o[j][2] *= a1; o[j][3] *= a1;
        }

        // ---- P -> bf16 hi/lo (accumulator layout == A-fragment layout) ----
        uint32_t ph0[8], pl0[8], ph1[8], pl1[8];
#pragma unroll
        for (int j = 0; j < 8; j++) {
            ph0[j] = pk_hi(s[j][0], s[j][1]);
            pl0[j] = pk_lo(s[j][0], s[j][1]);
            ph1[j] = pk_hi(s[j][2], s[j][3]);
            pl1[j] = pk_lo(s[j][2], s[j][3]);
        }

        // ---- O += P V ----
#pragma unroll
        for (int kd = 0; kd < 4; kd++) {
            const uint32_t pah[4] = {ph0[2 * kd], ph1[2 * kd], ph0[2 * kd + 1], ph1[2 * kd + 1]};
            const uint32_t pal[4] = {pl0[2 * kd], pl1[2 * kd], pl0[2 * kd + 1], pl1[2 * kd + 1]};
#pragma unroll
            for (int p = 0; p < 4; p++) {
                uint32_t vh4[4], vl4[4];
                uint32_t off = SWZ((uint32_t)((kd * 16 + rr) * 128 + (p * 16 + kk8) * 2));
                ldmat4t(vh4, Vh + off);
                ldmat4t(vl4, Vl + off);
                mma16816(o[2 * p],     pah, vh4[0], vh4[1]);
                mma16816(o[2 * p],     pah, vl4[0], vl4[1]);
                mma16816(o[2 * p],     pal, vh4[0], vh4[1]);
                mma16816(o[2 * p + 1], pah, vh4[2], vh4[3]);
                mma16816(o[2 * p + 1], pah, vl4[2], vl4[3]);
                mma16816(o[2 * p + 1], pal, vh4[2], vh4[3]);
            }
        }
        __syncthreads();   // all ldmatrix reads of this buffer done before reuse
    }

    // ---- epilogue: o / l -> split bf16 for the O projection ----
    const float inv0 = 1.f / lr0, inv1 = 1.f / lr1;
#pragma unroll
    for (int j = 0; j < 8; j++) {
        const int dh = h * DHH + 8 * j + lc;
        if (qr0 < TQ_) {
            const float v0 = o[j][0] * inv0, v1 = o[j][1] * inv0;
            const size_t ad = ((size_t)qr0 * BB + b) * DD + dh;
            *(uint32_t*)&g_a_hi[ad] = pk_hi(v0, v1);
            *(uint32_t*)&g_a_lo[ad] = pk_lo(v0, v1);
        }
        if (qr1 < TQ_) {
            const float v0 = o[j][2] * inv1, v1 = o[j][3] * inv1;
            const size_t ad = ((size_t)qr1 * BB + b) * DD + dh;
            *(uint32_t*)&g_a_hi[ad] = pk_hi(v0, v1);
            *(uint32_t*)&g_a_lo[ad] = pk_lo(v0, v1);
        }
    }
}

// ---------------------------------------------------------------------------
extern "C" void kernel_launch(void* const* d_in, const int* in_sizes, int n_in,
                              void* d_out, int out_size)
{
    const float* utt = (const float*)d_in[0];
    const float* rc  = (const float*)d_in[1];
    const float* smr = (const float*)d_in[2];
    const float* mem = (const float*)d_in[3];
    const float* Wq  = (const float*)d_in[4];
    const float* bq  = (const float*)d_in[5];
    const float* Wkv = (const float*)d_in[6];
    const float* bkv = (const float*)d_in[7];
    const float* Wo  = (const float*)d_in[8];
    const float* bo  = (const float*)d_in[9];
    const int*   len = (const int*)d_in[10];
    const unsigned char* am = (const unsigned char*)d_in[11];
    float* out = (float*)d_out;

    const int gemm_smem = 65536;
    const int attn_smem = 81920;   // Q 16KB + 2 stages x 32KB
    cudaFuncSetAttribute(tc_gemm<0>, cudaFuncAttributeMaxDynamicSharedMemorySize, gemm_smem);
    cudaFuncSetAttribute(tc_gemm<1>, cudaFuncAttributeMaxDynamicSharedMemorySize, gemm_smem);
    cudaFuncSetAttribute(tc_gemm<2>, cudaFuncAttributeMaxDynamicSharedMemorySize, gemm_smem);
    cudaFuncSetAttribute(attn_kernel, cudaFuncAttributeMaxDynamicSharedMemorySize, attn_smem);

    detect_mask_mode_kernel<<<1, 256>>>(am);
    convert_mask_kernel<<<(TQ_ * TK_ + 255) / 256, 256>>>(am);
    convert_in_kernel<<<dim3((TQ_ * BB * DD / 4 + 255) / 256, 2), 256>>>(utt, rc, smr, mem);
    convert_w_kernel<<<(2048 * DD / 4 + 255) / 256, 256>>>(Wq, Wkv, Wo);

    bf16 *qinh, *qinl, *kvinh, *kvinl, *ah, *al, *wh, *wl;
    cudaGetSymbolAddress((void**)&qinh,  g_qin_hi);
    cudaGetSymbolAddress((void**)&qinl,  g_qin_lo);
    cudaGetSymbolAddress((void**)&kvinh, g_kvin_hi);
    cudaGetSymbolAddress((void**)&kvinl, g_kvin_lo);
    cudaGetSymbolAddress((void**)&ah,    g_a_hi);
    cudaGetSymbolAddress((void**)&al,    g_a_lo);
    cudaGetSymbolAddress((void**)&wh,    g_w_hi);
    cudaGetSymbolAddress((void**)&wl,    g_w_lo);

    // 8832 = 138 * 64
    tc_gemm<0><<<dim3(8, 138), 128, gemm_smem>>>(qinh, qinl, wh, wl, bq, nullptr);
    tc_gemm<1><<<dim3(16, 138), 128, gemm_smem>>>(kvinh, kvinl, wh + (size_t)512 * DD,
                                                  wl + (size_t)512 * DD, bkv, nullptr);
    attn_kernel<<<dim3(18, 64), 128, attn_smem>>>(len);
    tc_gemm<2><<<dim3(8, 138), 128, gemm_smem>>>(ah, al, wh + (size_t)1536 * DD,
                                                 wl + (size_t)1536 * DD, bo, out);
}

// round 8
// speedup vs baseline: 1.1636x; 1.1636x over previous
#include <cuda_runtime.h>
#include <cuda_bf16.h>
#include <cstdint>

#define TT 1024
#define RR 64
#define SS 16
#define MMEM 16
#define BB 8
#define DD 512
#define HH 8
#define DHH 64
#define TQ_ 1104
#define TK_ 1104
#define SCALE_ 0.125f
#define NEGINF_ (-1.0e8f)

typedef __nv_bfloat16 bf16;

// ---------------- scratch (device globals; allocation-free rule) ----------------
__device__ bf16 g_qin_hi [(size_t)TQ_ * BB * DD];
__device__ bf16 g_qin_lo [(size_t)TQ_ * BB * DD];
__device__ bf16 g_kvin_hi[(size_t)TK_ * BB * DD];
__device__ bf16 g_kvin_lo[(size_t)TK_ * BB * DD];
__device__ bf16 g_w_hi[(size_t)2048 * DD];   // Wq | Wkv | Wo rows
__device__ bf16 g_w_lo[(size_t)2048 * DD];
__device__ bf16 g_q_hi[(size_t)TQ_ * BB * DD];
__device__ bf16 g_q_lo[(size_t)TQ_ * BB * DD];
__device__ bf16 g_k_hi[(size_t)TK_ * BB * DD];
__device__ bf16 g_k_lo[(size_t)TK_ * BB * DD];
__device__ bf16 g_v_hi[(size_t)TK_ * BB * DD];
__device__ bf16 g_v_lo[(size_t)TK_ * BB * DD];
__device__ bf16 g_a_hi[(size_t)TQ_ * BB * DD];
__device__ bf16 g_a_lo[(size_t)TQ_ * BB * DD];
__device__ unsigned char g_mask[(size_t)TQ_ * TK_];

__device__ __forceinline__ float neg_inf_f() { return __int_as_float(0xff800000); }

// ---------------- low-level helpers (sm_80-era only; no 'a' features) ----------------
__device__ __forceinline__ uint32_t smem_to_u32(const void* p) {
    uint32_t a;
    asm("{ .reg .u64 t; cvta.to.shared.u64 t, %1; cvt.u32.u64 %0, t; }" : "=r"(a) : "l"(p));
    return a;
}
__device__ __forceinline__ void ldmat4(uint32_t r[4], uint32_t addr) {
    asm volatile("ldmatrix.sync.aligned.m8n8.x4.shared.b16 {%0,%1,%2,%3}, [%4];"
                 : "=r"(r[0]), "=r"(r[1]), "=r"(r[2]), "=r"(r[3]) : "r"(addr));
}
__device__ __forceinline__ void ldmat4t(uint32_t r[4], uint32_t addr) {
    asm volatile("ldmatrix.sync.aligned.m8n8.x4.trans.shared.b16 {%0,%1,%2,%3}, [%4];"
                 : "=r"(r[0]), "=r"(r[1]), "=r"(r[2]), "=r"(r[3]) : "r"(addr));
}
__device__ __forceinline__ void mma16816(float d[4], const uint32_t a[4],
                                         uint32_t b0, uint32_t b1) {
    asm volatile("mma.sync.aligned.m16n8k16.row.col.f32.bf16.bf16.f32 "
                 "{%0,%1,%2,%3}, {%4,%5,%6,%7}, {%8,%9}, {%0,%1,%2,%3};"
                 : "+f"(d[0]), "+f"(d[1]), "+f"(d[2]), "+f"(d[3])
                 : "r"(a[0]), "r"(a[1]), "r"(a[2]), "r"(a[3]), "r"(b0), "r"(b1));
}
__device__ __forceinline__ void cp16(uint32_t dst, const void* src, int bytes) {
    asm volatile("cp.async.cg.shared.global [%0], [%1], 16, %2;"
                 :: "r"(dst), "l"(src), "r"(bytes));
}
#define CP_COMMIT() asm volatile("cp.async.commit_group;" ::: "memory")
#define CP_WAIT0()  asm volatile("cp.async.wait_group 0;" ::: "memory")
#define CP_WAIT1()  asm volatile("cp.async.wait_group 1;" ::: "memory")

#define SWZ(o) ((o) ^ (((o) >> 3) & 0x70))

__device__ __forceinline__ uint32_t pk2(bf16 a, bf16 b) {
    return ((uint32_t)__bfloat16_as_ushort(b) << 16) | __bfloat16_as_ushort(a);
}
__device__ __forceinline__ uint32_t pk_hi(float a, float b) {
    return pk2(__float2bfloat16(a), __float2bfloat16(b));
}
__device__ __forceinline__ uint32_t pk_lo(float a, float b) {
    bf16 ha = __float2bfloat16(a), hb = __float2bfloat16(b);
    return pk2(__float2bfloat16(a - __bfloat162float(ha)),
               __float2bfloat16(b - __bfloat162float(hb)));
}

// ---------------------------------------------------------------------------
// LAUNCH 1: mask detect + canonicalize in one kernel.
// Each block sniffs the first 4KB to classify dtype (u8 / i32 / f32):
// prob of misclassifying a 30%-density bool mask is ~0.7^1024 ~ 0.
// ---------------------------------------------------------------------------
__global__ void __launch_bounds__(256) mask_kernel(const unsigned char* __restrict__ buf)
{
    __shared__ int s_large, s_nzoff;
    if (threadIdx.x == 0) { s_large = 0; s_nzoff = 0; }
    __syncthreads();
    int l = 0, z = 0;
    {
        const int base = threadIdx.x * 16;   // 256 threads x 16B = 4096B
#pragma unroll
        for (int j = 0; j < 16; j++) {
            unsigned char v = buf[base + j];
            if (v > 1) l = 1;
            if (((base + j) & 3) && v != 0) z = 1;
        }
    }
    if (l) atomicOr(&s_large, 1);
    if (z) atomicOr(&s_nzoff, 1);
    __syncthreads();
    const int mode = s_large ? 2 : (s_nzoff ? 0 : 1);   // 0=u8, 1=i32, 2=f32

    const int idx = blockIdx.x * blockDim.x + threadIdx.x;
    if (idx >= TQ_ * TK_) return;
    unsigned char m;
    if (mode == 0)      m = buf[idx] ? 1 : 0;
    else if (mode == 1) m = (((const int*)buf)[idx] != 0) ? 1 : 0;
    else                m = (((const float*)buf)[idx] != 0.f) ? 1 : 0;
    g_mask[idx] = m;
}

// ---------------------------------------------------------------------------
// LAUNCH 2: all fp32 -> split-bf16 conversions in one kernel.
// blockIdx.y: 0 = q_in gather, 1 = kv_in gather, 2 = weights.
// ---------------------------------------------------------------------------
__global__ void __launch_bounds__(256) convert_all_kernel(
    const float* __restrict__ utt, const float* __restrict__ rc,
    const float* __restrict__ smr, const float* __restrict__ mem,
    const float* __restrict__ Wq, const float* __restrict__ Wkv,
    const float* __restrict__ Wo)
{
    const int y = blockIdx.y;
    const size_t e = ((size_t)blockIdx.x * blockDim.x + threadIdx.x) * 4;
    if (y < 2) {
        if (e >= (size_t)TQ_ * BB * DD) return;
        const int r = (int)(e >> 9);
        const int k = (int)(e & 511);
        const int t = r >> 3, b = r & 7;
        const float* src;
        if (y == 0) {
            if (t < RR)           src = rc  + ((size_t)t * BB + b) * DD;
            else if (t < RR + TT) src = utt + ((size_t)(t - RR) * BB + b) * DD;
            else                  src = smr + ((size_t)(t - RR - TT) * BB + b) * DD;
        } else {
            if (t < MMEM)           src = mem + ((size_t)t * BB + b) * DD;
            else if (t < MMEM + RR) src = rc  + ((size_t)(t - MMEM) * BB + b) * DD;
            else                    src = utt + ((size_t)(t - MMEM - RR) * BB + b) * DD;
        }
        float4 v = *(const float4*)(src + k);
        bf16* dh = y ? g_kvin_hi : g_qin_hi;
        bf16* dl = y ? g_kvin_lo : g_qin_lo;
        *(uint2*)&dh[e] = make_uint2(pk_hi(v.x, v.y), pk_hi(v.z, v.w));
        *(uint2*)&dl[e] = make_uint2(pk_lo(v.x, v.y), pk_lo(v.z, v.w));
    } else {
        if (e >= (size_t)2048 * DD) return;
        const int r = (int)(e >> 9);
        const int k = (int)(e & 511);
        const float* src;
        if (r < 512)       src = Wq  + (size_t)r * DD;
        else if (r < 1536) src = Wkv + (size_t)(r - 512) * DD;
        else               src = Wo  + (size_t)(r - 1536) * DD;
        float4 v = *(const float4*)(src + k);
        *(uint2*)&g_w_hi[e] = make_uint2(pk_hi(v.x, v.y), pk_hi(v.z, v.w));
        *(uint2*)&g_w_lo[e] = make_uint2(pk_lo(v.x, v.y), pk_lo(v.z, v.w));
    }
}

// ---------------------------------------------------------------------------
// Shared GEMM core (R4-proven): D[64m x 64n] = A[m,k]*B[n,k]^T + bias, K=512.
// 128 threads / 4 warps (2x2), warp tile 32m x 32n, k-step 16, 3-MMA split.
// cp.async double-buffered stages of K=64. dyn smem = 64KB.
// Epilogue mode: 0 -> g_q (xSCALE), 1 -> g_k/g_v split, 2 -> dout packing.
// ---------------------------------------------------------------------------
__device__ __forceinline__ void gemm_core(
    const bf16* __restrict__ a_hi, const bf16* __restrict__ a_lo,
    const bf16* __restrict__ b_hi, const bf16* __restrict__ b_lo,
    const float* __restrict__ bias, float* __restrict__ dout,
    int mode, int m0, int n0, char* smc)
{
    const uint32_t smb = smem_to_u32(smc);
    const int tid = threadIdx.x, w = tid >> 5, lane = tid & 31;
    const int wm = w >> 1, wn = w & 1;

    const bf16* srcs[4] = { a_hi + (size_t)m0 * DD, a_lo + (size_t)m0 * DD,
                            b_hi + (size_t)n0 * DD, b_lo + (size_t)n0 * DD };
    const int ldrow = tid >> 1;
    const int ldc0  = (tid & 1) * 4;

    auto issue_stage = [&](int kc, int buf) {
#pragma unroll
        for (int t = 0; t < 4; t++) {
            const bf16* src = srcs[t] + (size_t)ldrow * DD + kc * 64 + ldc0 * 8;
            uint32_t db = smb + buf * 32768 + t * 8192;
#pragma unroll
            for (int i = 0; i < 4; i++)
                cp16(db + SWZ((uint32_t)(ldrow * 128 + (ldc0 + i) * 16)), src + i * 8, 16);
        }
        CP_COMMIT();
    };

    float acc[2][4][4];
#pragma unroll
    for (int a = 0; a < 2; a++)
#pragma unroll
        for (int c = 0; c < 4; c++)
#pragma unroll
            for (int d = 0; d < 4; d++) acc[a][c][d] = 0.f;

    const int rr  = (lane & 7) + ((lane >> 3) & 1) * 8;
    const int kk8 = (lane >> 4) * 8;

    issue_stage(0, 0);
    for (int c = 0; c < 8; c++) {
        if (c < 7) { issue_stage(c + 1, (c + 1) & 1); CP_WAIT1(); }
        else       { CP_WAIT0(); }
        __syncthreads();
        const uint32_t base = smb + (c & 1) * 32768;
#pragma unroll
        for (int kd = 0; kd < 4; kd++) {
            const uint32_t ko = (uint32_t)((kd * 16 + kk8) * 2);
            uint32_t ah[2][4], al[2][4], bh[2][4], bl[2][4];
#pragma unroll
            for (int mt = 0; mt < 2; mt++) {
                uint32_t off = SWZ((uint32_t)((wm * 32 + mt * 16 + rr) * 128) + ko);
                ldmat4(ah[mt], base + off);
                ldmat4(al[mt], base + 8192 + off);
            }
#pragma unroll
            for (int p = 0; p < 2; p++) {
                uint32_t off = SWZ((uint32_t)((wn * 32 + p * 16 + rr) * 128) + ko);
                ldmat4(bh[p], base + 16384 + off);
                ldmat4(bl[p], base + 24576 + off);
            }
#pragma unroll
            for (int mt = 0; mt < 2; mt++)
#pragma unroll
                for (int nt = 0; nt < 4; nt++) {
                    uint32_t b0h = bh[nt >> 1][nt & 1], b1h = bh[nt >> 1][2 + (nt & 1)];
                    uint32_t b0l = bl[nt >> 1][nt & 1], b1l = bl[nt >> 1][2 + (nt & 1)];
                    mma16816(acc[mt][nt], ah[mt], b0h, b1h);
                    mma16816(acc[mt][nt], ah[mt], b0l, b1l);
                    mma16816(acc[mt][nt], al[mt], b0h, b1h);
                }
        }
        __syncthreads();
    }

    const int lq = lane >> 2, lc = (lane & 3) * 2;
#pragma unroll
    for (int mt = 0; mt < 2; mt++) {
#pragma unroll
        for (int nt = 0; nt < 4; nt++) {
            const int col = n0 + wn * 32 + nt * 8 + lc;
            const float b0 = bias[col], b1 = bias[col + 1];
#pragma unroll
            for (int hrow = 0; hrow < 2; hrow++) {
                const int m = m0 + wm * 32 + mt * 16 + lq + hrow * 8;
                float v0 = acc[mt][nt][hrow * 2 + 0] + b0;
                float v1 = acc[mt][nt][hrow * 2 + 1] + b1;
                if (mode == 0) {
                    v0 *= SCALE_; v1 *= SCALE_;
                    *(uint32_t*)&g_q_hi[(size_t)m * DD + col] = pk_hi(v0, v1);
                    *(uint32_t*)&g_q_lo[(size_t)m * DD + col] = pk_lo(v0, v1);
                } else if (mode == 1) {
                    if (col < DD) {
                        *(uint32_t*)&g_k_hi[(size_t)m * DD + col] = pk_hi(v0, v1);
                        *(uint32_t*)&g_k_lo[(size_t)m * DD + col] = pk_lo(v0, v1);
                    } else {
                        *(uint32_t*)&g_v_hi[(size_t)m * DD + col - DD] = pk_hi(v0, v1);
                        *(uint32_t*)&g_v_lo[(size_t)m * DD + col - DD] = pk_lo(v0, v1);
                    }
                } else {
                    const int tt = m >> 3, rb = m & 7;
                    if (tt < TQ_ - SS) {
                        *(float2*)&dout[(size_t)m * DD + col] = make_float2(v0, v1);
                    } else if (tt < TQ_ - 1) {
                        v0 = fminf(10.f, fmaxf(-10.f, v0));
                        v1 = fminf(10.f, fmaxf(-10.f, v1));
                        *(float2*)&dout[(size_t)(TQ_ - SS) * BB * DD +
                                        ((size_t)(tt - (TQ_ - SS)) * BB + rb) * DD + col] =
                            make_float2(v0, v1);
                    }
                }
            }
        }
    }
}

// LAUNCH 3: Q-proj (z=0) + KV-proj (z=1) merged into one launch.
__global__ void __launch_bounds__(128) qkv_gemm(
    const bf16* __restrict__ qinh, const bf16* __restrict__ qinl,
    const bf16* __restrict__ kvinh, const bf16* __restrict__ kvinl,
    const bf16* __restrict__ wh, const bf16* __restrict__ wl,
    const float* __restrict__ bq, const float* __restrict__ bkv)
{
    extern __shared__ char smc[];
    const int z = blockIdx.z;
    if (z == 0 && blockIdx.x >= 8) return;   // Q proj: 8 n-tiles only
    const bf16* a_hi = z ? kvinh : qinh;
    const bf16* a_lo = z ? kvinl : qinl;
    const bf16* b_hi = wh + (z ? (size_t)512 * DD : 0);
    const bf16* b_lo = wl + (z ? (size_t)512 * DD : 0);
    const float* bias = z ? bkv : bq;
    gemm_core(a_hi, a_lo, b_hi, b_lo, bias, nullptr, z,
              blockIdx.y * 64, blockIdx.x * 64, smc);
}

// LAUNCH 5: O projection -> packed output.
__global__ void __launch_bounds__(128) o_gemm(
    const bf16* __restrict__ ah, const bf16* __restrict__ al,
    const bf16* __restrict__ bh, const bf16* __restrict__ bl,
    const float* __restrict__ bias, float* __restrict__ dout)
{
    extern __shared__ char smc[];
    gemm_core(ah, al, bh, bl, bias, dout, 2, blockIdx.y * 64, blockIdx.x * 64, smc);
}

// ---------------------------------------------------------------------------
// LAUNCH 4: HMMA flash attention — R4 version verbatim (known fastest):
// synchronous K/V staging, 48KB smem (4 CTAs/SM), kend loop (correct ceil
// semantics since the loop condition is k0 < kend with 64-step).
// ---------------------------------------------------------------------------
__global__ void __launch_bounds__(128) attn_kernel(const int* __restrict__ lengths)
{
    extern __shared__ char smc[];
    const uint32_t smb = smem_to_u32(smc);
    const uint32_t Qh = smb, Ql = smb + 8192, Kh = smb + 16384, Kl = smb + 24576;
    const uint32_t Vh = smb + 32768, Vl = smb + 40960;

    const int tid = threadIdx.x, w = tid >> 5, lane = tid & 31;
    const int b = blockIdx.y >> 3, h = blockIdx.y & 7;
    const int q0 = blockIdx.x * 64;

    int maxlen = 0;
#pragma unroll
    for (int i = 0; i < BB; i++) maxlen = max(maxlen, lengths[i]);
    const int klen = lengths[b] + MMEM + (TQ_ - maxlen - SS);
    const int kend = min(TK_, (klen + 63) & ~63);

    const int ldrow = tid >> 1;
    const int ldc0  = (tid & 1) * 4;

    // stage Q (hi/lo), zero-fill rows >= TQ_
    {
        const int q = q0 + ldrow;
        const int bytes = (q < TQ_) ? 16 : 0;
        const size_t go = ((size_t)q * BB + b) * DD + h * DHH + ldc0 * 8;
#pragma unroll
        for (int i = 0; i < 4; i++) {
            uint32_t so = SWZ((uint32_t)(ldrow * 128 + (ldc0 + i) * 16));
            cp16(Qh + so, g_q_hi + go + i * 8, bytes);
            cp16(Ql + so, g_q_lo + go + i * 8, bytes);
        }
        CP_COMMIT(); CP_WAIT0();
    }
    __syncthreads();

    const int rr  = (lane & 7) + ((lane >> 3) & 1) * 8;
    const int kk8 = (lane >> 4) * 8;

    uint32_t qh[4][4], ql[4][4];
#pragma unroll
    for (int kd = 0; kd < 4; kd++) {
        uint32_t off = SWZ((uint32_t)((16 * w + rr) * 128 + (kd * 16 + kk8) * 2));
        ldmat4(qh[kd], Qh + off);
        ldmat4(ql[kd], Ql + off);
    }

    float o[8][4];
#pragma unroll
    for (int j = 0; j < 8; j++)
#pragma unroll
        for (int d = 0; d < 4; d++) o[j][d] = 0.f;
    float mr0 = neg_inf_f(), mr1 = neg_inf_f(), lr0 = 0.f, lr1 = 0.f;

    const int lq = lane >> 2, lc = (lane & 3) * 2;
    const int qr0 = q0 + 16 * w + lq, qr1 = qr0 + 8;

    for (int k0 = 0; k0 < kend; k0 += 64) {
        __syncthreads();   // previous tile's ldmatrix reads complete
        {
            const int tk = k0 + ldrow;
            const int bytes = (tk < TK_) ? 16 : 0;
            const size_t go = ((size_t)tk * BB + b) * DD + h * DHH + ldc0 * 8;
#pragma unroll
            for (int i = 0; i < 4; i++) {
                uint32_t so = SWZ((uint32_t)(ldrow * 128 + (ldc0 + i) * 16));
                cp16(Kh + so, g_k_hi + go + i * 8, bytes);
                cp16(Kl + so, g_k_lo + go + i * 8, bytes);
                cp16(Vh + so, g_v_hi + go + i * 8, bytes);
                cp16(Vl + so, g_v_lo + go + i * 8, bytes);
            }
            CP_COMMIT(); CP_WAIT0();
        }
        __syncthreads();

        // ---- S = Q K^T ----
        float s[8][4];
#pragma unroll
        for (int j = 0; j < 8; j++)
#pragma unroll
            for (int d = 0; d < 4; d++) s[j][d] = 0.f;

#pragma unroll
        for (int kd = 0; kd < 4; kd++) {
            const uint32_t ko = (uint32_t)((kd * 16 + kk8) * 2);
#pragma unroll
            for (int p = 0; p < 4; p++) {
                uint32_t kh4[4], kl4[4];
                uint32_t off = SWZ((uint32_t)((p * 16 + rr) * 128) + ko);
                ldmat4(kh4, Kh + off);
                ldmat4(kl4, Kl + off);
                mma16816(s[2 * p],     qh[kd], kh4[0], kh4[2]);
                mma16816(s[2 * p],     qh[kd], kl4[0], kl4[2]);
                mma16816(s[2 * p],     ql[kd], kh4[0], kh4[2]);
                mma16816(s[2 * p + 1], qh[kd], kh4[1], kh4[3]);
                mma16816(s[2 * p + 1], qh[kd], kl4[1], kl4[3]);
                mma16816(s[2 * p + 1], ql[kd], kh4[1], kh4[3]);
            }
        }

        // ---- mask ----
#pragma unroll
        for (int j = 0; j < 8; j++) {
            const int kc = k0 + 8 * j + lc;
            const bool in_k = (kc < TK_ - 1);
            uchar2 mA = make_uchar2(1, 1), mB = make_uchar2(1, 1);
            if (in_k && qr0 < TQ_) mA = *(const uchar2*)&g_mask[(size_t)qr0 * TK_ + kc];
            if (in_k && qr1 < TQ_) mB = *(const uchar2*)&g_mask[(size_t)qr1 * TK_ + kc];
            if (kc >= TK_) {
                s[j][0] = s[j][2] = neg_inf_f();
            } else {
                if (mA.x || kc >= klen) s[j][0] = NEGINF_;
                if (mB.x || kc >= klen) s[j][2] = NEGINF_;
            }
            if (kc + 1 >= TK_) {
                s[j][1] = s[j][3] = neg_inf_f();
            } else {
                if (mA.y || kc + 1 >= klen) s[j][1] = NEGINF_;
                if (mB.y || kc + 1 >= klen) s[j][3] = NEGINF_;
            }
        }

        // ---- online softmax ----
        float mx0 = NEGINF_, mx1 = NEGINF_;
#pragma unroll
        for (int j = 0; j < 8; j++) {
            mx0 = fmaxf(mx0, fmaxf(s[j][0], s[j][1]));
            mx1 = fmaxf(mx1, fmaxf(s[j][2], s[j][3]));
        }
        mx0 = fmaxf(mx0, __shfl_xor_sync(0xffffffffu, mx0, 1));
        mx0 = fmaxf(mx0, __shfl_xor_sync(0xffffffffu, mx0, 2));
        mx1 = fmaxf(mx1, __shfl_xor_sync(0xffffffffu, mx1, 1));
        mx1 = fmaxf(mx1, __shfl_xor_sync(0xffffffffu, mx1, 2));
        const float mn0 = fmaxf(mr0, mx0), mn1 = fmaxf(mr1, mx1);
        const float a0 = __expf(mr0 - mn0), a1 = __expf(mr1 - mn1);
        float su0 = 0.f, su1 = 0.f;
#pragma unroll
        for (int j = 0; j < 8; j++) {
            s[j][0] = __expf(s[j][0] - mn0);
            s[j][1] = __expf(s[j][1] - mn0);
            s[j][2] = __expf(s[j][2] - mn1);
            s[j][3] = __expf(s[j][3] - mn1);
            su0 += s[j][0] + s[j][1];
            su1 += s[j][2] + s[j][3];
        }
        su0 += __shfl_xor_sync(0xffffffffu, su0, 1);
        su0 += __shfl_xor_sync(0xffffffffu, su0, 2);
        su1 += __shfl_xor_sync(0xffffffffu, su1, 1);
        su1 += __shfl_xor_sync(0xffffffffu, su1, 2);
        lr0 = lr0 * a0 + su0;  mr0 = mn0;
        lr1 = lr1 * a1 + su1;  mr1 = mn1;
#pragma unroll
        for (int j = 0; j < 8; j++) {
            o[j][0] *= a0; o[j][1] *= a0;
            o[j][2] *= a1; o[j][3] *= a1;
        }

        // ---- P -> bf16 hi/lo ----
        uint32_t ph0[8], pl0[8], ph1[8], pl1[8];
#pragma unroll
        for (int j = 0; j < 8; j++) {
            ph0[j] = pk_hi(s[j][0], s[j][1]);
            pl0[j] = pk_lo(s[j][0], s[j][1]);
            ph1[j] = pk_hi(s[j][2], s[j][3]);
            pl1[j] = pk_lo(s[j][2], s[j][3]);
        }

        // ---- O += P V ----
#pragma unroll
        for (int kd = 0; kd < 4; kd++) {
            const uint32_t pah[4] = {ph0[2 * kd], ph1[2 * kd], ph0[2 * kd + 1], ph1[2 * kd + 1]};
            const uint32_t pal[4] = {pl0[2 * kd], pl1[2 * kd], pl0[2 * kd + 1], pl1[2 * kd + 1]};
#pragma unroll
            for (int p = 0; p < 4; p++) {
                uint32_t vh4[4], vl4[4];
                uint32_t off = SWZ((uint32_t)((kd * 16 + rr) * 128 + (p * 16 + kk8) * 2));
                ldmat4t(vh4, Vh + off);
                ldmat4t(vl4, Vl + off);
                mma16816(o[2 * p],     pah, vh4[0], vh4[1]);
                mma16816(o[2 * p],     pah, vl4[0], vl4[1]);
                mma16816(o[2 * p],     pal, vh4[0], vh4[1]);
                mma16816(o[2 * p + 1], pah, vh4[2], vh4[3]);
                mma16816(o[2 * p + 1], pah, vl4[2], vl4[3]);
                mma16816(o[2 * p + 1], pal, vh4[2], vh4[3]);
            }
        }
    }

    // ---- epilogue: o / l -> split bf16 for the O projection ----
    const float inv0 = 1.f / lr0, inv1 = 1.f / lr1;
#pragma unroll
    for (int j = 0; j < 8; j++) {
        const int dh = h * DHH + 8 * j + lc;
        if (qr0 < TQ_) {
            const float v0 = o[j][0] * inv0, v1 = o[j][1] * inv0;
            const size_t ad = ((size_t)qr0 * BB + b) * DD + dh;
            *(uint32_t*)&g_a_hi[ad] = pk_hi(v0, v1);
            *(uint32_t*)&g_a_lo[ad] = pk_lo(v0, v1);
        }
        if (qr1 < TQ_) {
            const float v0 = o[j][2] * inv1, v1 = o[j][3] * inv1;
            const size_t ad = ((size_t)qr1 * BB + b) * DD + dh;
            *(uint32_t*)&g_a_hi[ad] = pk_hi(v0, v1);
            *(uint32_t*)&g_a_lo[ad] = pk_lo(v0, v1);
        }
    }
}

// ---------------------------------------------------------------------------
extern "C" void kernel_launch(void* const* d_in, const int* in_sizes, int n_in,
                              void* d_out, int out_size)
{
    const float* utt = (const float*)d_in[0];
    const float* rc  = (const float*)d_in[1];
    const float* smr = (const float*)d_in[2];
    const float* mem = (const float*)d_in[3];
    const float* Wq  = (const float*)d_in[4];
    const float* bq  = (const float*)d_in[5];
    const float* Wkv = (const float*)d_in[6];
    const float* bkv = (const float*)d_in[7];
    const float* Wo  = (const float*)d_in[8];
    const float* bo  = (const float*)d_in[9];
    const int*   len = (const int*)d_in[10];
    const unsigned char* am = (const unsigned char*)d_in[11];
    float* out = (float*)d_out;

    const int gemm_smem = 65536;
    const int attn_smem = 49152;
    cudaFuncSetAttribute(qkv_gemm, cudaFuncAttributeMaxDynamicSharedMemorySize, gemm_smem);
    cudaFuncSetAttribute(o_gemm,   cudaFuncAttributeMaxDynamicSharedMemorySize, gemm_smem);
    cudaFuncSetAttribute(attn_kernel, cudaFuncAttributeMaxDynamicSharedMemorySize, attn_smem);

    bf16 *qinh, *qinl, *kvinh, *kvinl, *ah, *al, *wh, *wl;
    cudaGetSymbolAddress((void**)&qinh,  g_qin_hi);
    cudaGetSymbolAddress((void**)&qinl,  g_qin_lo);
    cudaGetSymbolAddress((void**)&kvinh, g_kvin_hi);
    cudaGetSymbolAddress((void**)&kvinl, g_kvin_lo);
    cudaGetSymbolAddress((void**)&ah,    g_a_hi);
    cudaGetSymbolAddress((void**)&al,    g_a_lo);
    cudaGetSymbolAddress((void**)&wh,    g_w_hi);
    cudaGetSymbolAddress((void**)&wl,    g_w_lo);

    // LAUNCH 1: mask
    mask_kernel<<<(TQ_ * TK_ + 255) / 256, 256>>>(am);
    // LAUNCH 2: all conversions
    convert_all_kernel<<<dim3((TQ_ * BB * DD / 4 + 255) / 256, 3), 256>>>(
        utt, rc, smr, mem, Wq, Wkv, Wo);
    // LAUNCH 3: Q + KV projections (merged)
    qkv_gemm<<<dim3(16, 138, 2), 128, gemm_smem>>>(qinh, qinl, kvinh, kvinl, wh, wl, bq, bkv);
    // LAUNCH 4: attention (profiled slot)
    attn_kernel<<<dim3(18, 64), 128, attn_smem>>>(len);
    // LAUNCH 5: O projection
    o_gemm<<<dim3(8, 138), 128, gemm_smem>>>(ah, al, wh + (size_t)1536 * DD,
                                             wl + (size_t)1536 * DD, bo, out);
}

// round 9
// speedup vs baseline: 1.2670x; 1.0889x over previous
#include <cuda_runtime.h>
#include <cuda_bf16.h>
#include <cstdint>

#define TT 1024
#define RR 64
#define SS 16
#define MMEM 16
#define BB 8
#define DD 512
#define HH 8
#define DHH 64
#define TQ_ 1104
#define TK_ 1104
#define SCALE_ 0.125f
#define NEGINF_ (-1.0e8f)

typedef __nv_bfloat16 bf16;

// ---------------- scratch (device globals; allocation-free rule) ----------------
__device__ bf16 g_qin_hi [(size_t)TQ_ * BB * DD];
__device__ bf16 g_qin_lo [(size_t)TQ_ * BB * DD];
__device__ bf16 g_kvin_hi[(size_t)TK_ * BB * DD];
__device__ bf16 g_kvin_lo[(size_t)TK_ * BB * DD];
__device__ bf16 g_w_hi[(size_t)2048 * DD];   // Wq | Wkv | Wo rows
__device__ bf16 g_w_lo[(size_t)2048 * DD];
__device__ bf16 g_q_hi[(size_t)TQ_ * BB * DD];
__device__ bf16 g_q_lo[(size_t)TQ_ * BB * DD];
__device__ bf16 g_k_hi[(size_t)TK_ * BB * DD];
__device__ bf16 g_k_lo[(size_t)TK_ * BB * DD];
__device__ bf16 g_v_hi[(size_t)TK_ * BB * DD];
__device__ bf16 g_v_lo[(size_t)TK_ * BB * DD];
__device__ bf16 g_a_hi[(size_t)TQ_ * BB * DD];
__device__ bf16 g_a_lo[(size_t)TQ_ * BB * DD];
__device__ unsigned char g_mask[(size_t)TQ_ * TK_];

__device__ __forceinline__ float neg_inf_f() { return __int_as_float(0xff800000); }

// ---------------- low-level helpers (sm_80-era only; no 'a' features) ----------------
__device__ __forceinline__ uint32_t smem_to_u32(const void* p) {
    uint32_t a;
    asm("{ .reg .u64 t; cvta.to.shared.u64 t, %1; cvt.u32.u64 %0, t; }" : "=r"(a) : "l"(p));
    return a;
}
__device__ __forceinline__ void ldmat4(uint32_t r[4], uint32_t addr) {
    asm volatile("ldmatrix.sync.aligned.m8n8.x4.shared.b16 {%0,%1,%2,%3}, [%4];"
                 : "=r"(r[0]), "=r"(r[1]), "=r"(r[2]), "=r"(r[3]) : "r"(addr));
}
__device__ __forceinline__ void ldmat4t(uint32_t r[4], uint32_t addr) {
    asm volatile("ldmatrix.sync.aligned.m8n8.x4.trans.shared.b16 {%0,%1,%2,%3}, [%4];"
                 : "=r"(r[0]), "=r"(r[1]), "=r"(r[2]), "=r"(r[3]) : "r"(addr));
}
__device__ __forceinline__ void mma16816(float d[4], const uint32_t a[4],
                                         uint32_t b0, uint32_t b1) {
    asm volatile("mma.sync.aligned.m16n8k16.row.col.f32.bf16.bf16.f32 "
                 "{%0,%1,%2,%3}, {%4,%5,%6,%7}, {%8,%9}, {%0,%1,%2,%3};"
                 : "+f"(d[0]), "+f"(d[1]), "+f"(d[2]), "+f"(d[3])
                 : "r"(a[0]), "r"(a[1]), "r"(a[2]), "r"(a[3]), "r"(b0), "r"(b1));
}
__device__ __forceinline__ void cp16(uint32_t dst, const void* src, int bytes) {
    asm volatile("cp.async.cg.shared.global [%0], [%1], 16, %2;"
                 :: "r"(dst), "l"(src), "r"(bytes));
}
#define CP_COMMIT() asm volatile("cp.async.commit_group;" ::: "memory")
#define CP_WAIT0()  asm volatile("cp.async.wait_group 0;" ::: "memory")
#define CP_WAIT1()  asm volatile("cp.async.wait_group 1;" ::: "memory")

#define SWZ(o) ((o) ^ (((o) >> 3) & 0x70))

__device__ __forceinline__ uint32_t pk2(bf16 a, bf16 b) {
    return ((uint32_t)__bfloat16_as_ushort(b) << 16) | __bfloat16_as_ushort(a);
}
__device__ __forceinline__ uint32_t pk_hi(float a, float b) {
    return pk2(__float2bfloat16(a), __float2bfloat16(b));
}
__device__ __forceinline__ uint32_t pk_lo(float a, float b) {
    bf16 ha = __float2bfloat16(a), hb = __float2bfloat16(b);
    return pk2(__float2bfloat16(a - __bfloat162float(ha)),
               __float2bfloat16(b - __bfloat162float(hb)));
}

// ---------------------------------------------------------------------------
// LAUNCH 1: mask detect + canonicalize in one kernel (unchanged from R8).
// ---------------------------------------------------------------------------
__global__ void __launch_bounds__(256) mask_kernel(const unsigned char* __restrict__ buf)
{
    __shared__ int s_large, s_nzoff;
    if (threadIdx.x == 0) { s_large = 0; s_nzoff = 0; }
    __syncthreads();
    int l = 0, z = 0;
    {
        const int base = threadIdx.x * 16;
#pragma unroll
        for (int j = 0; j < 16; j++) {
            unsigned char v = buf[base + j];
            if (v > 1) l = 1;
            if (((base + j) & 3) && v != 0) z = 1;
        }
    }
    if (l) atomicOr(&s_large, 1);
    if (z) atomicOr(&s_nzoff, 1);
    __syncthreads();
    const int mode = s_large ? 2 : (s_nzoff ? 0 : 1);

    const int idx = blockIdx.x * blockDim.x + threadIdx.x;
    if (idx >= TQ_ * TK_) return;
    unsigned char m;
    if (mode == 0)      m = buf[idx] ? 1 : 0;
    else if (mode == 1) m = (((const int*)buf)[idx] != 0) ? 1 : 0;
    else                m = (((const float*)buf)[idx] != 0.f) ? 1 : 0;
    g_mask[idx] = m;
}

// ---------------------------------------------------------------------------
// LAUNCH 2: all fp32 -> split-bf16 conversions (unchanged from R8).
// ---------------------------------------------------------------------------
__global__ void __launch_bounds__(256) convert_all_kernel(
    const float* __restrict__ utt, const float* __restrict__ rc,
    const float* __restrict__ smr, const float* __restrict__ mem,
    const float* __restrict__ Wq, const float* __restrict__ Wkv,
    const float* __restrict__ Wo)
{
    const int y = blockIdx.y;
    const size_t e = ((size_t)blockIdx.x * blockDim.x + threadIdx.x) * 4;
    if (y < 2) {
        if (e >= (size_t)TQ_ * BB * DD) return;
        const int r = (int)(e >> 9);
        const int k = (int)(e & 511);
        const int t = r >> 3, b = r & 7;
        const float* src;
        if (y == 0) {
            if (t < RR)           src = rc  + ((size_t)t * BB + b) * DD;
            else if (t < RR + TT) src = utt + ((size_t)(t - RR) * BB + b) * DD;
            else                  src = smr + ((size_t)(t - RR - TT) * BB + b) * DD;
        } else {
            if (t < MMEM)           src = mem + ((size_t)t * BB + b) * DD;
            else if (t < MMEM + RR) src = rc  + ((size_t)(t - MMEM) * BB + b) * DD;
            else                    src = utt + ((size_t)(t - MMEM - RR) * BB + b) * DD;
        }
        float4 v = *(const float4*)(src + k);
        bf16* dh = y ? g_kvin_hi : g_qin_hi;
        bf16* dl = y ? g_kvin_lo : g_qin_lo;
        *(uint2*)&dh[e] = make_uint2(pk_hi(v.x, v.y), pk_hi(v.z, v.w));
        *(uint2*)&dl[e] = make_uint2(pk_lo(v.x, v.y), pk_lo(v.z, v.w));
    } else {
        if (e >= (size_t)2048 * DD) return;
        const int r = (int)(e >> 9);
        const int k = (int)(e & 511);
        const float* src;
        if (r < 512)       src = Wq  + (size_t)r * DD;
        else if (r < 1536) src = Wkv + (size_t)(r - 512) * DD;
        else               src = Wo  + (size_t)(r - 1536) * DD;
        float4 v = *(const float4*)(src + k);
        *(uint2*)&g_w_hi[e] = make_uint2(pk_hi(v.x, v.y), pk_hi(v.z, v.w));
        *(uint2*)&g_w_lo[e] = make_uint2(pk_lo(v.x, v.y), pk_lo(v.z, v.w));
    }
}

// ---------------------------------------------------------------------------
// Shared GEMM core (R4-proven, unchanged): D[64m x 64n], K=512, 3-MMA split.
// ---------------------------------------------------------------------------
__device__ __forceinline__ void gemm_core(
    const bf16* __restrict__ a_hi, const bf16* __restrict__ a_lo,
    const bf16* __restrict__ b_hi, const bf16* __restrict__ b_lo,
    const float* __restrict__ bias, float* __restrict__ dout,
    int mode, int m0, int n0, char* smc)
{
    const uint32_t smb = smem_to_u32(smc);
    const int tid = threadIdx.x, w = tid >> 5, lane = tid & 31;
    const int wm = w >> 1, wn = w & 1;

    const bf16* srcs[4] = { a_hi + (size_t)m0 * DD, a_lo + (size_t)m0 * DD,
                            b_hi + (size_t)n0 * DD, b_lo + (size_t)n0 * DD };
    const int ldrow = tid >> 1;
    const int ldc0  = (tid & 1) * 4;

    auto issue_stage = [&](int kc, int buf) {
#pragma unroll
        for (int t = 0; t < 4; t++) {
            const bf16* src = srcs[t] + (size_t)ldrow * DD + kc * 64 + ldc0 * 8;
            uint32_t db = smb + buf * 32768 + t * 8192;
#pragma unroll
            for (int i = 0; i < 4; i++)
                cp16(db + SWZ((uint32_t)(ldrow * 128 + (ldc0 + i) * 16)), src + i * 8, 16);
        }
        CP_COMMIT();
    };

    float acc[2][4][4];
#pragma unroll
    for (int a = 0; a < 2; a++)
#pragma unroll
        for (int c = 0; c < 4; c++)
#pragma unroll
            for (int d = 0; d < 4; d++) acc[a][c][d] = 0.f;

    const int rr  = (lane & 7) + ((lane >> 3) & 1) * 8;
    const int kk8 = (lane >> 4) * 8;

    issue_stage(0, 0);
    for (int c = 0; c < 8; c++) {
        if (c < 7) { issue_stage(c + 1, (c + 1) & 1); CP_WAIT1(); }
        else       { CP_WAIT0(); }
        __syncthreads();
        const uint32_t base = smb + (c & 1) * 32768;
#pragma unroll
        for (int kd = 0; kd < 4; kd++) {
            const uint32_t ko = (uint32_t)((kd * 16 + kk8) * 2);
            uint32_t ah[2][4], al[2][4], bh[2][4], bl[2][4];
#pragma unroll
            for (int mt = 0; mt < 2; mt++) {
                uint32_t off = SWZ((uint32_t)((wm * 32 + mt * 16 + rr) * 128) + ko);
                ldmat4(ah[mt], base + off);
                ldmat4(al[mt], base + 8192 + off);
            }
#pragma unroll
            for (int p = 0; p < 2; p++) {
                uint32_t off = SWZ((uint32_t)((wn * 32 + p * 16 + rr) * 128) + ko);
                ldmat4(bh[p], base + 16384 + off);
                ldmat4(bl[p], base + 24576 + off);
            }
#pragma unroll
            for (int mt = 0; mt < 2; mt++)
#pragma unroll
                for (int nt = 0; nt < 4; nt++) {
                    uint32_t b0h = bh[nt >> 1][nt & 1], b1h = bh[nt >> 1][2 + (nt & 1)];
                    uint32_t b0l = bl[nt >> 1][nt & 1], b1l = bl[nt >> 1][2 + (nt & 1)];
                    mma16816(acc[mt][nt], ah[mt], b0h, b1h);
                    mma16816(acc[mt][nt], ah[mt], b0l, b1l);
                    mma16816(acc[mt][nt], al[mt], b0h, b1h);
                }
        }
        __syncthreads();
    }

    const int lq = lane >> 2, lc = (lane & 3) * 2;
#pragma unroll
    for (int mt = 0; mt < 2; mt++) {
#pragma unroll
        for (int nt = 0; nt < 4; nt++) {
            const int col = n0 + wn * 32 + nt * 8 + lc;
            const float b0 = bias[col], b1 = bias[col + 1];
#pragma unroll
            for (int hrow = 0; hrow < 2; hrow++) {
                const int m = m0 + wm * 32 + mt * 16 + lq + hrow * 8;
                float v0 = acc[mt][nt][hrow * 2 + 0] + b0;
                float v1 = acc[mt][nt][hrow * 2 + 1] + b1;
                if (mode == 0) {
                    v0 *= SCALE_; v1 *= SCALE_;
                    *(uint32_t*)&g_q_hi[(size_t)m * DD + col] = pk_hi(v0, v1);
                    *(uint32_t*)&g_q_lo[(size_t)m * DD + col] = pk_lo(v0, v1);
                } else if (mode == 1) {
                    if (col < DD) {
                        *(uint32_t*)&g_k_hi[(size_t)m * DD + col] = pk_hi(v0, v1);
                        *(uint32_t*)&g_k_lo[(size_t)m * DD + col] = pk_lo(v0, v1);
                    } else {
                        *(uint32_t*)&g_v_hi[(size_t)m * DD + col - DD] = pk_hi(v0, v1);
                        *(uint32_t*)&g_v_lo[(size_t)m * DD + col - DD] = pk_lo(v0, v1);
                    }
                } else {
                    const int tt = m >> 3, rb = m & 7;
                    if (tt < TQ_ - SS) {
                        *(float2*)&dout[(size_t)m * DD + col] = make_float2(v0, v1);
                    } else if (tt < TQ_ - 1) {
                        v0 = fminf(10.f, fmaxf(-10.f, v0));
                        v1 = fminf(10.f, fmaxf(-10.f, v1));
                        *(float2*)&dout[(size_t)(TQ_ - SS) * BB * DD +
                                        ((size_t)(tt - (TQ_ - SS)) * BB + rb) * DD + col] =
                            make_float2(v0, v1);
                    }
                }
            }
        }
    }
}

// LAUNCH 3: Q-proj (z=0) + KV-proj (z=1) merged (unchanged).
__global__ void __launch_bounds__(128) qkv_gemm(
    const bf16* __restrict__ qinh, const bf16* __restrict__ qinl,
    const bf16* __restrict__ kvinh, const bf16* __restrict__ kvinl,
    const bf16* __restrict__ wh, const bf16* __restrict__ wl,
    const float* __restrict__ bq, const float* __restrict__ bkv)
{
    extern __shared__ char smc[];
    const int z = blockIdx.z;
    if (z == 0 && blockIdx.x >= 8) return;
    const bf16* a_hi = z ? kvinh : qinh;
    const bf16* a_lo = z ? kvinl : qinl;
    const bf16* b_hi = wh + (z ? (size_t)512 * DD : 0);
    const bf16* b_lo = wl + (z ? (size_t)512 * DD : 0);
    const float* bias = z ? bkv : bq;
    gemm_core(a_hi, a_lo, b_hi, b_lo, bias, nullptr, z,
              blockIdx.y * 64, blockIdx.x * 64, smc);
}

// LAUNCH 5: O projection (unchanged).
__global__ void __launch_bounds__(128) o_gemm(
    const bf16* __restrict__ ah, const bf16* __restrict__ al,
    const bf16* __restrict__ bh, const bf16* __restrict__ bl,
    const float* __restrict__ bias, float* __restrict__ dout)
{
    extern __shared__ char smc[];
    gemm_core(ah, al, bh, bl, bias, dout, 2, blockIdx.y * 64, blockIdx.x * 64, smc);
}

// ---------------------------------------------------------------------------
// LAUNCH 4: HMMA flash attention — R8 math, TWO changes:
//  (a) split K/V staging: V(c) loads during S(c) MMAs, K(c+1) loads during
//      PV(c) MMAs; smem stays 48KB (Q|K|V single-buffered, no conflicts:
//      V overwrite fenced by top-of-loop sync, K overwrite by post-S sync).
//  (b) __launch_bounds__(128, 3): reg cap 170 -> 3 CTAs/SM (was 2 @ 177 regs).
// ---------------------------------------------------------------------------
__global__ void __launch_bounds__(128, 3) attn_kernel(const int* __restrict__ lengths)
{
    extern __shared__ char smc[];
    const uint32_t smb = smem_to_u32(smc);
    const uint32_t Qh = smb, Ql = smb + 8192, Kh = smb + 16384, Kl = smb + 24576;
    const uint32_t Vh = smb + 32768, Vl = smb + 40960;

    const int tid = threadIdx.x, w = tid >> 5, lane = tid & 31;
    const int b = blockIdx.y >> 3, h = blockIdx.y & 7;
    const int q0 = blockIdx.x * 64;

    int maxlen = 0;
#pragma unroll
    for (int i = 0; i < BB; i++) maxlen = max(maxlen, lengths[i]);
    const int klen = lengths[b] + MMEM + (TQ_ - maxlen - SS);
    const int kend = min(TK_, (klen + 63) & ~63);   // loop k0 < kend covers partial tail

    const int ldrow = tid >> 1;
    const int ldc0  = (tid & 1) * 4;

    auto stageK = [&](int k0c) {
        const int tk = k0c + ldrow;
        const int bytes = (tk < TK_) ? 16 : 0;
        const size_t go = ((size_t)tk * BB + b) * DD + h * DHH + ldc0 * 8;
#pragma unroll
        for (int i = 0; i < 4; i++) {
            uint32_t so = SWZ((uint32_t)(ldrow * 128 + (ldc0 + i) * 16));
            cp16(Kh + so, g_k_hi + go + i * 8, bytes);
            cp16(Kl + so, g_k_lo + go + i * 8, bytes);
        }
        CP_COMMIT();
    };
    auto stageV = [&](int k0c) {
        const int tk = k0c + ldrow;
        const int bytes = (tk < TK_) ? 16 : 0;
        const size_t go = ((size_t)tk * BB + b) * DD + h * DHH + ldc0 * 8;
#pragma unroll
        for (int i = 0; i < 4; i++) {
            uint32_t so = SWZ((uint32_t)(ldrow * 128 + (ldc0 + i) * 16));
            cp16(Vh + so, g_v_hi + go + i * 8, bytes);
            cp16(Vl + so, g_v_lo + go + i * 8, bytes);
        }
        CP_COMMIT();
    };

    // stage Q (group 1), stage K(0) (group 2); WAIT1 drains Q only
    {
        const int q = q0 + ldrow;
        const int bytes = (q < TQ_) ? 16 : 0;
        const size_t go = ((size_t)q * BB + b) * DD + h * DHH + ldc0 * 8;
#pragma unroll
        for (int i = 0; i < 4; i++) {
            uint32_t so = SWZ((uint32_t)(ldrow * 128 + (ldc0 + i) * 16));
            cp16(Qh + so, g_q_hi + go + i * 8, bytes);
            cp16(Ql + so, g_q_lo + go + i * 8, bytes);
        }
        CP_COMMIT();
    }
    stageK(0);
    CP_WAIT1();
    __syncthreads();

    const int rr  = (lane & 7) + ((lane >> 3) & 1) * 8;
    const int kk8 = (lane >> 4) * 8;

    uint32_t qh[4][4], ql[4][4];
#pragma unroll
    for (int kd = 0; kd < 4; kd++) {
        uint32_t off = SWZ((uint32_t)((16 * w + rr) * 128 + (kd * 16 + kk8) * 2));
        ldmat4(qh[kd], Qh + off);
        ldmat4(ql[kd], Ql + off);
    }

    float o[8][4];
#pragma unroll
    for (int j = 0; j < 8; j++)
#pragma unroll
        for (int d = 0; d < 4; d++) o[j][d] = 0.f;
    float mr0 = neg_inf_f(), mr1 = neg_inf_f(), lr0 = 0.f, lr1 = 0.f;

    const int lq = lane >> 2, lc = (lane & 3) * 2;
    const int qr0 = q0 + 16 * w + lq, qr1 = qr0 + 8;

    for (int k0 = 0; k0 < kend; k0 += 64) {
        CP_WAIT0();          // K(k0) ready (and prior V drained)
        __syncthreads();     // all warps past PV(k0-64): V buffer free
        stageV(k0);          // async V load overlaps S MMAs

        // ---- S = Q K^T ----
        float s[8][4];
#pragma unroll
        for (int j = 0; j < 8; j++)
#pragma unroll
            for (int d = 0; d < 4; d++) s[j][d] = 0.f;

#pragma unroll
        for (int kd = 0; kd < 4; kd++) {
            const uint32_t ko = (uint32_t)((kd * 16 + kk8) * 2);
#pragma unroll
            for (int p = 0; p < 4; p++) {
                uint32_t kh4[4], kl4[4];
                uint32_t off = SWZ((uint32_t)((p * 16 + rr) * 128) + ko);
                ldmat4(kh4, Kh + off);
                ldmat4(kl4, Kl + off);
                mma16816(s[2 * p],     qh[kd], kh4[0], kh4[2]);
                mma16816(s[2 * p],     qh[kd], kl4[0], kl4[2]);
                mma16816(s[2 * p],     ql[kd], kh4[0], kh4[2]);
                mma16816(s[2 * p + 1], qh[kd], kh4[1], kh4[3]);
                mma16816(s[2 * p + 1], qh[kd], kl4[1], kl4[3]);
                mma16816(s[2 * p + 1], ql[kd], kh4[1], kh4[3]);
            }
        }

        CP_WAIT0();          // V(k0) ready
        __syncthreads();     // all warps past S: K buffer free

        // ---- mask ----
#pragma unroll
        for (int j = 0; j < 8; j++) {
            const int kc = k0 + 8 * j + lc;
            const bool in_k = (kc < TK_ - 1);
            uchar2 mA = make_uchar2(1, 1), mB = make_uchar2(1, 1);
            if (in_k && qr0 < TQ_) mA = *(const uchar2*)&g_mask[(size_t)qr0 * TK_ + kc];
            if (in_k && qr1 < TQ_) mB = *(const uchar2*)&g_mask[(size_t)qr1 * TK_ + kc];
            if (kc >= TK_) {
                s[j][0] = s[j][2] = neg_inf_f();
            } else {
                if (mA.x || kc >= klen) s[j][0] = NEGINF_;
                if (mB.x || kc >= klen) s[j][2] = NEGINF_;
            }
            if (kc + 1 >= TK_) {
                s[j][1] = s[j][3] = neg_inf_f();
            } else {
                if (mA.y || kc + 1 >= klen) s[j][1] = NEGINF_;
                if (mB.y || kc + 1 >= klen) s[j][3] = NEGINF_;
            }
        }

        // ---- online softmax ----
        float mx0 = NEGINF_, mx1 = NEGINF_;
#pragma unroll
        for (int j = 0; j < 8; j++) {
            mx0 = fmaxf(mx0, fmaxf(s[j][0], s[j][1]));
            mx1 = fmaxf(mx1, fmaxf(s[j][2], s[j][3]));
        }
        mx0 = fmaxf(mx0, __shfl_xor_sync(0xffffffffu, mx0, 1));
        mx0 = fmaxf(mx0, __shfl_xor_sync(0xffffffffu, mx0, 2));
        mx1 = fmaxf(mx1, __shfl_xor_sync(0xffffffffu, mx1, 1));
        mx1 = fmaxf(mx1, __shfl_xor_sync(0xffffffffu, mx1, 2));
        const float mn0 = fmaxf(mr0, mx0), mn1 = fmaxf(mr1, mx1);
        const float a0 = __expf(mr0 - mn0), a1 = __expf(mr1 - mn1);
        float su0 = 0.f, su1 = 0.f;
#pragma unroll
        for (int j = 0; j < 8; j++) {
            s[j][0] = __expf(s[j][0] - mn0);
            s[j][1] = __expf(s[j][1] - mn0);
            s[j][2] = __expf(s[j][2] - mn1);
            s[j][3] = __expf(s[j][3] - mn1);
            su0 += s[j][0] + s[j][1];
            su1 += s[j][2] + s[j][3];
        }
        su0 += __shfl_xor_sync(0xffffffffu, su0, 1);
        su0 += __shfl_xor_sync(0xffffffffu, su0, 2);
        su1 += __shfl_xor_sync(0xffffffffu, su1, 1);
        su1 += __shfl_xor_sync(0xffffffffu, su1, 2);
        lr0 = lr0 * a0 + su0;  mr0 = mn0;
        lr1 = lr1 * a1 + su1;  mr1 = mn1;
#pragma unroll
        for (int j = 0; j < 8; j++) {
            o[j][0] *= a0; o[j][1] *= a0;
            o[j][2] *= a1; o[j][3] *= a1;
        }

        // ---- P -> bf16 hi/lo ----
        uint32_t ph0[8], pl0[8], ph1[8], pl1[8];
#pragma unroll
        for (int j = 0; j < 8; j++) {
            ph0[j] = pk_hi(s[j][0], s[j][1]);
            pl0[j] = pk_lo(s[j][0], s[j][1]);
            ph1[j] = pk_hi(s[j][2], s[j][3]);
            pl1[j] = pk_lo(s[j][2], s[j][3]);
        }

        if (k0 + 64 < kend) stageK(k0 + 64);   // async K load overlaps PV MMAs

        // ---- O += P V ----
#pragma unroll
        for (int kd = 0; kd < 4; kd++) {
            const uint32_t pah[4] = {ph0[2 * kd], ph1[2 * kd], ph0[2 * kd + 1], ph1[2 * kd + 1]};
            const uint32_t pal[4] = {pl0[2 * kd], pl1[2 * kd], pl0[2 * kd + 1], pl1[2 * kd + 1]};
#pragma unroll
            for (int p = 0; p < 4; p++) {
                uint32_t vh4[4], vl4[4];
                uint32_t off = SWZ((uint32_t)((kd * 16 + rr) * 128 + (p * 16 + kk8) * 2));
                ldmat4t(vh4, Vh + off);
                ldmat4t(vl4, Vl + off);
                mma16816(o[2 * p],     pah, vh4[0], vh4[1]);
                mma16816(o[2 * p],     pah, vl4[0], vl4[1]);
                mma16816(o[2 * p],     pal, vh4[0], vh4[1]);
                mma16816(o[2 * p + 1], pah, vh4[2], vh4[3]);
                mma16816(o[2 * p + 1], pah, vl4[2], vl4[3]);
                mma16816(o[2 * p + 1], pal, vh4[2], vh4[3]);
            }
        }
    }

    // ---- epilogue: o / l -> split bf16 for the O projection ----
    const float inv0 = 1.f / lr0, inv1 = 1.f / lr1;
#pragma unroll
    for (int j = 0; j < 8; j++) {
        const int dh = h * DHH + 8 * j + lc;
        if (qr0 < TQ_) {
            const float v0 = o[j][0] * inv0, v1 = o[j][1] * inv0;
            const size_t ad = ((size_t)qr0 * BB + b) * DD + dh;
            *(uint32_t*)&g_a_hi[ad] = pk_hi(v0, v1);
            *(uint32_t*)&g_a_lo[ad] = pk_lo(v0, v1);
        }
        if (qr1 < TQ_) {
            const float v0 = o[j][2] * inv1, v1 = o[j][3] * inv1;
            const size_t ad = ((size_t)qr1 * BB + b) * DD + dh;
            *(uint32_t*)&g_a_hi[ad] = pk_hi(v0, v1);
            *(uint32_t*)&g_a_lo[ad] = pk_lo(v0, v1);
        }
    }
}

// ---------------------------------------------------------------------------
extern "C" void kernel_launch(void* const* d_in, const int* in_sizes, int n_in,
                              void* d_out, int out_size)
{
    const float* utt = (const float*)d_in[0];
    const float* rc  = (const float*)d_in[1];
    const float* smr = (const float*)d_in[2];
    const float* mem = (const float*)d_in[3];
    const float* Wq  = (const float*)d_in[4];
    const float* bq  = (const float*)d_in[5];
    const float* Wkv = (const float*)d_in[6];
    const float* bkv = (const float*)d_in[7];
    const float* Wo  = (const float*)d_in[8];
    const float* bo  = (const float*)d_in[9];
    const int*   len = (const int*)d_in[10];
    const unsigned char* am = (const unsigned char*)d_in[11];
    float* out = (float*)d_out;

    const int gemm_smem = 65536;
    const int attn_smem = 49152;
    cudaFuncSetAttribute(qkv_gemm, cudaFuncAttributeMaxDynamicSharedMemorySize, gemm_smem);
    cudaFuncSetAttribute(o_gemm,   cudaFuncAttributeMaxDynamicSharedMemorySize, gemm_smem);
    cudaFuncSetAttribute(attn_kernel, cudaFuncAttributeMaxDynamicSharedMemorySize, attn_smem);

    bf16 *qinh, *qinl, *kvinh, *kvinl, *ah, *al, *wh, *wl;
    cudaGetSymbolAddress((void**)&qinh,  g_qin_hi);
    cudaGetSymbolAddress((void**)&qinl,  g_qin_lo);
    cudaGetSymbolAddress((void**)&kvinh, g_kvin_hi);
    cudaGetSymbolAddress((void**)&kvinl, g_kvin_lo);
    cudaGetSymbolAddress((void**)&ah,    g_a_hi);
    cudaGetSymbolAddress((void**)&al,    g_a_lo);
    cudaGetSymbolAddress((void**)&wh,    g_w_hi);
    cudaGetSymbolAddress((void**)&wl,    g_w_lo);

    // LAUNCH 1: mask
    mask_kernel<<<(TQ_ * TK_ + 255) / 256, 256>>>(am);
    // LAUNCH 2: all conversions
    convert_all_kernel<<<dim3((TQ_ * BB * DD / 4 + 255) / 256, 3), 256>>>(
        utt, rc, smr, mem, Wq, Wkv, Wo);
    // LAUNCH 3: Q + KV projections (merged)
    qkv_gemm<<<dim3(16, 138, 2), 128, gemm_smem>>>(qinh, qinl, kvinh, kvinl, wh, wl, bq, bkv);
    // LAUNCH 4: attention (profiled slot)
    attn_kernel<<<dim3(18, 64), 128, attn_smem>>>(len);
    // LAUNCH 5: O projection
    o_gemm<<<dim3(8, 138), 128, gemm_smem>>>(ah, al, wh + (size_t)1536 * DD,
                                             wl + (size_t)1536 * DD, bo, out);
}

// round 10
// speedup vs baseline: 1.4787x; 1.1670x over previous
#include <cuda_runtime.h>
#include <cuda_bf16.h>
#include <cstdint>

#define TT 1024
#define RR 64
#define SS 16
#define MMEM 16
#define BB 8
#define DD 512
#define HH 8
#define DHH 64
#define TQ_ 1104
#define TK_ 1104
#define SCALE_ 0.125f
#define NEGINF_ (-1.0e8f)

typedef __nv_bfloat16 bf16;

// ---------------- scratch (device globals; allocation-free rule) ----------------
__device__ bf16 g_qin_hi [(size_t)TQ_ * BB * DD];
__device__ bf16 g_qin_lo [(size_t)TQ_ * BB * DD];
__device__ bf16 g_kvin_hi[(size_t)TK_ * BB * DD];
__device__ bf16 g_kvin_lo[(size_t)TK_ * BB * DD];
__device__ bf16 g_w_hi[(size_t)2048 * DD];   // Wq | Wkv | Wo rows
__device__ bf16 g_w_lo[(size_t)2048 * DD];
__device__ bf16 g_q_hi[(size_t)TQ_ * BB * DD];
__device__ bf16 g_q_lo[(size_t)TQ_ * BB * DD];
__device__ bf16 g_k_hi[(size_t)TK_ * BB * DD];
__device__ bf16 g_k_lo[(size_t)TK_ * BB * DD];
__device__ bf16 g_v_hi[(size_t)TK_ * BB * DD];
__device__ bf16 g_v_lo[(size_t)TK_ * BB * DD];
__device__ bf16 g_a_hi[(size_t)TQ_ * BB * DD];
__device__ bf16 g_a_lo[(size_t)TQ_ * BB * DD];
__device__ unsigned char g_mask[(size_t)TQ_ * TK_];

__device__ __forceinline__ float neg_inf_f() { return __int_as_float(0xff800000); }

// ---------------- low-level helpers (sm_80-era only; no 'a' features) ----------------
__device__ __forceinline__ uint32_t smem_to_u32(const void* p) {
    uint32_t a;
    asm("{ .reg .u64 t; cvta.to.shared.u64 t, %1; cvt.u32.u64 %0, t; }" : "=r"(a) : "l"(p));
    return a;
}
__device__ __forceinline__ void ldmat4(uint32_t r[4], uint32_t addr) {
    asm volatile("ldmatrix.sync.aligned.m8n8.x4.shared.b16 {%0,%1,%2,%3}, [%4];"
                 : "=r"(r[0]), "=r"(r[1]), "=r"(r[2]), "=r"(r[3]) : "r"(addr));
}
__device__ __forceinline__ void ldmat4t(uint32_t r[4], uint32_t addr) {
    asm volatile("ldmatrix.sync.aligned.m8n8.x4.trans.shared.b16 {%0,%1,%2,%3}, [%4];"
                 : "=r"(r[0]), "=r"(r[1]), "=r"(r[2]), "=r"(r[3]) : "r"(addr));
}
__device__ __forceinline__ void mma16816(float d[4], const uint32_t a[4],
                                         uint32_t b0, uint32_t b1) {
    asm volatile("mma.sync.aligned.m16n8k16.row.col.f32.bf16.bf16.f32 "
                 "{%0,%1,%2,%3}, {%4,%5,%6,%7}, {%8,%9}, {%0,%1,%2,%3};"
                 : "+f"(d[0]), "+f"(d[1]), "+f"(d[2]), "+f"(d[3])
                 : "r"(a[0]), "r"(a[1]), "r"(a[2]), "r"(a[3]), "r"(b0), "r"(b1));
}
__device__ __forceinline__ void cp16(uint32_t dst, const void* src, int bytes) {
    asm volatile("cp.async.cg.shared.global [%0], [%1], 16, %2;"
                 :: "r"(dst), "l"(src), "r"(bytes));
}
#define CP_COMMIT() asm volatile("cp.async.commit_group;" ::: "memory")
#define CP_WAIT0()  asm volatile("cp.async.wait_group 0;" ::: "memory")
#define CP_WAIT1()  asm volatile("cp.async.wait_group 1;" ::: "memory")

#define SWZ(o) ((o) ^ (((o) >> 3) & 0x70))

__device__ __forceinline__ uint32_t pk2(bf16 a, bf16 b) {
    return ((uint32_t)__bfloat16_as_ushort(b) << 16) | __bfloat16_as_ushort(a);
}
__device__ __forceinline__ uint32_t pk_hi(float a, float b) {
    return pk2(__float2bfloat16(a), __float2bfloat16(b));
}
__device__ __forceinline__ uint32_t pk_lo(float a, float b) {
    bf16 ha = __float2bfloat16(a), hb = __float2bfloat16(b);
    return pk2(__float2bfloat16(a - __bfloat162float(ha)),
               __float2bfloat16(b - __bfloat162float(hb)));
}

// ---------------------------------------------------------------------------
// LAUNCH 1: mask detect + canonicalize (unchanged from R8).
// ---------------------------------------------------------------------------
__global__ void __launch_bounds__(256) mask_kernel(const unsigned char* __restrict__ buf)
{
    __shared__ int s_large, s_nzoff;
    if (threadIdx.x == 0) { s_large = 0; s_nzoff = 0; }
    __syncthreads();
    int l = 0, z = 0;
    {
        const int base = threadIdx.x * 16;
#pragma unroll
        for (int j = 0; j < 16; j++) {
            unsigned char v = buf[base + j];
            if (v > 1) l = 1;
            if (((base + j) & 3) && v != 0) z = 1;
        }
    }
    if (l) atomicOr(&s_large, 1);
    if (z) atomicOr(&s_nzoff, 1);
    __syncthreads();
    const int mode = s_large ? 2 : (s_nzoff ? 0 : 1);

    const int idx = blockIdx.x * blockDim.x + threadIdx.x;
    if (idx >= TQ_ * TK_) return;
    unsigned char m;
    if (mode == 0)      m = buf[idx] ? 1 : 0;
    else if (mode == 1) m = (((const int*)buf)[idx] != 0) ? 1 : 0;
    else                m = (((const float*)buf)[idx] != 0.f) ? 1 : 0;
    g_mask[idx] = m;
}

// ---------------------------------------------------------------------------
// LAUNCH 2: all fp32 -> split-bf16 conversions (unchanged from R8).
// ---------------------------------------------------------------------------
__global__ void __launch_bounds__(256) convert_all_kernel(
    const float* __restrict__ utt, const float* __restrict__ rc,
    const float* __restrict__ smr, const float* __restrict__ mem,
    const float* __restrict__ Wq, const float* __restrict__ Wkv,
    const float* __restrict__ Wo)
{
    const int y = blockIdx.y;
    const size_t e = ((size_t)blockIdx.x * blockDim.x + threadIdx.x) * 4;
    if (y < 2) {
        if (e >= (size_t)TQ_ * BB * DD) return;
        const int r = (int)(e >> 9);
        const int k = (int)(e & 511);
        const int t = r >> 3, b = r & 7;
        const float* src;
        if (y == 0) {
            if (t < RR)           src = rc  + ((size_t)t * BB + b) * DD;
            else if (t < RR + TT) src = utt + ((size_t)(t - RR) * BB + b) * DD;
            else                  src = smr + ((size_t)(t - RR - TT) * BB + b) * DD;
        } else {
            if (t < MMEM)           src = mem + ((size_t)t * BB + b) * DD;
            else if (t < MMEM + RR) src = rc  + ((size_t)(t - MMEM) * BB + b) * DD;
            else                    src = utt + ((size_t)(t - MMEM - RR) * BB + b) * DD;
        }
        float4 v = *(const float4*)(src + k);
        bf16* dh = y ? g_kvin_hi : g_qin_hi;
        bf16* dl = y ? g_kvin_lo : g_qin_lo;
        *(uint2*)&dh[e] = make_uint2(pk_hi(v.x, v.y), pk_hi(v.z, v.w));
        *(uint2*)&dl[e] = make_uint2(pk_lo(v.x, v.y), pk_lo(v.z, v.w));
    } else {
        if (e >= (size_t)2048 * DD) return;
        const int r = (int)(e >> 9);
        const int k = (int)(e & 511);
        const float* src;
        if (r < 512)       src = Wq  + (size_t)r * DD;
        else if (r < 1536) src = Wkv + (size_t)(r - 512) * DD;
        else               src = Wo  + (size_t)(r - 1536) * DD;
        float4 v = *(const float4*)(src + k);
        *(uint2*)&g_w_hi[e] = make_uint2(pk_hi(v.x, v.y), pk_hi(v.z, v.w));
        *(uint2*)&g_w_lo[e] = make_uint2(pk_lo(v.x, v.y), pk_lo(v.z, v.w));
    }
}

// ---------------------------------------------------------------------------
// GEMM core — R5-proven 128m x 64n, 256 threads / 8 warps (4m x 2n), K=512,
// 3-MMA split, double-buffered K-chunks of 64 (wait0 -> sync -> stage-next).
// Outputs bit-identical to the 64x64 core (proven by R5==R6 forensics).
// smem/stage: Ah 16K | Al 16K | Bh 8K | Bl 8K = 48KB; 2 stages = 96KB.
// ---------------------------------------------------------------------------
__device__ __forceinline__ void gemm_core(
    const bf16* __restrict__ a_hi, const bf16* __restrict__ a_lo,
    const bf16* __restrict__ b_hi, const bf16* __restrict__ b_lo,
    const float* __restrict__ bias, float* __restrict__ dout,
    int mode, int m0, int n0, char* smc)
{
    const uint32_t smb = smem_to_u32(smc);
    const int tid = threadIdx.x, w = tid >> 5, lane = tid & 31;
    const int wm = w >> 1, wn = w & 1;

    const int ra  = tid >> 1;          // 0..127 (A rows)
    const int ca0 = (tid & 1) * 4;     // 4 chunks of 16B
    const int rb  = tid >> 2;          // 0..63  (B rows)
    const int cb0 = (tid & 3) * 2;     // 2 chunks of 16B

    auto stage = [&](int kc) {
        const uint32_t sb = smb + (kc & 1) * 49152;
        const bf16* As_h = a_hi + (size_t)(m0 + ra) * DD + kc * 64 + ca0 * 8;
        const bf16* As_l = a_lo + (size_t)(m0 + ra) * DD + kc * 64 + ca0 * 8;
#pragma unroll
        for (int i = 0; i < 4; i++) {
            uint32_t so = SWZ((uint32_t)(ra * 128 + (ca0 + i) * 16));
            cp16(sb + so,         As_h + i * 8, 16);
            cp16(sb + 16384 + so, As_l + i * 8, 16);
        }
        const bf16* Bs_h = b_hi + (size_t)(n0 + rb) * DD + kc * 64 + cb0 * 8;
        const bf16* Bs_l = b_lo + (size_t)(n0 + rb) * DD + kc * 64 + cb0 * 8;
#pragma unroll
        for (int i = 0; i < 2; i++) {
            uint32_t so = SWZ((uint32_t)(rb * 128 + (cb0 + i) * 16));
            cp16(sb + 32768 + so, Bs_h + i * 8, 16);
            cp16(sb + 40960 + so, Bs_l + i * 8, 16);
        }
        CP_COMMIT();
    };

    float acc[2][4][4];
#pragma unroll
    for (int a = 0; a < 2; a++)
#pragma unroll
        for (int c = 0; c < 4; c++)
#pragma unroll
            for (int d = 0; d < 4; d++) acc[a][c][d] = 0.f;

    const int rr  = (lane & 7) + ((lane >> 3) & 1) * 8;
    const int kk8 = (lane >> 4) * 8;

    stage(0);
    for (int c = 0; c < 8; c++) {
        CP_WAIT0();
        __syncthreads();
        if (c < 7) stage(c + 1);
        const uint32_t sb = smb + (c & 1) * 49152;
#pragma unroll
        for (int kd = 0; kd < 4; kd++) {
            const uint32_t ko = (uint32_t)((kd * 16 + kk8) * 2);
            uint32_t ah[2][4], al[2][4], bh[2][4], bl[2][4];
#pragma unroll
            for (int mt = 0; mt < 2; mt++) {
                uint32_t off = SWZ((uint32_t)((wm * 32 + mt * 16 + rr) * 128) + ko);
                ldmat4(ah[mt], sb + off);
                ldmat4(al[mt], sb + 16384 + off);
            }
#pragma unroll
            for (int p = 0; p < 2; p++) {
                uint32_t off = SWZ((uint32_t)((wn * 32 + p * 16 + rr) * 128) + ko);
                ldmat4(bh[p], sb + 32768 + off);
                ldmat4(bl[p], sb + 40960 + off);
            }
#pragma unroll
            for (int mt = 0; mt < 2; mt++)
#pragma unroll
                for (int nt = 0; nt < 4; nt++) {
                    uint32_t b0h = bh[nt >> 1][nt & 1], b1h = bh[nt >> 1][2 + (nt & 1)];
                    uint32_t b0l = bl[nt >> 1][nt & 1], b1l = bl[nt >> 1][2 + (nt & 1)];
                    mma16816(acc[mt][nt], ah[mt], b0h, b1h);
                    mma16816(acc[mt][nt], ah[mt], b0l, b1l);
                    mma16816(acc[mt][nt], al[mt], b0h, b1h);
                }
        }
        // no trailing sync: next iteration's wait0+sync precedes buffer reuse
    }

    const int lq = lane >> 2, lc = (lane & 3) * 2;
#pragma unroll
    for (int mt = 0; mt < 2; mt++) {
#pragma unroll
        for (int nt = 0; nt < 4; nt++) {
            const int col = n0 + wn * 32 + nt * 8 + lc;
            const float b0 = bias[col], b1 = bias[col + 1];
#pragma unroll
            for (int hrow = 0; hrow < 2; hrow++) {
                const int m = m0 + wm * 32 + mt * 16 + lq + hrow * 8;
                float v0 = acc[mt][nt][hrow * 2 + 0] + b0;
                float v1 = acc[mt][nt][hrow * 2 + 1] + b1;
                if (mode == 0) {
                    v0 *= SCALE_; v1 *= SCALE_;
                    *(uint32_t*)&g_q_hi[(size_t)m * DD + col] = pk_hi(v0, v1);
                    *(uint32_t*)&g_q_lo[(size_t)m * DD + col] = pk_lo(v0, v1);
                } else if (mode == 1) {
                    if (col < DD) {
                        *(uint32_t*)&g_k_hi[(size_t)m * DD + col] = pk_hi(v0, v1);
                        *(uint32_t*)&g_k_lo[(size_t)m * DD + col] = pk_lo(v0, v1);
                    } else {
                        *(uint32_t*)&g_v_hi[(size_t)m * DD + col - DD] = pk_hi(v0, v1);
                        *(uint32_t*)&g_v_lo[(size_t)m * DD + col - DD] = pk_lo(v0, v1);
                    }
                } else {
                    const int tt = m >> 3, rbb = m & 7;
                    if (tt < TQ_ - SS) {
                        *(float2*)&dout[(size_t)m * DD + col] = make_float2(v0, v1);
                    } else if (tt < TQ_ - 1) {
                        v0 = fminf(10.f, fmaxf(-10.f, v0));
                        v1 = fminf(10.f, fmaxf(-10.f, v1));
                        *(float2*)&dout[(size_t)(TQ_ - SS) * BB * DD +
                                        ((size_t)(tt - (TQ_ - SS)) * BB + rbb) * DD + col] =
                            make_float2(v0, v1);
                    }
                }
            }
        }
    }
}

// LAUNCH 3: Q-proj (z=0) + KV-proj (z=1) merged; 128-row m-tiles (69 of them).
__global__ void __launch_bounds__(256, 2) qkv_gemm(
    const bf16* __restrict__ qinh, const bf16* __restrict__ qinl,
    const bf16* __restrict__ kvinh, const bf16* __restrict__ kvinl,
    const bf16* __restrict__ wh, const bf16* __restrict__ wl,
    const float* __restrict__ bq, const float* __restrict__ bkv)
{
    extern __shared__ char smc[];
    const int z = blockIdx.z;
    if (z == 0 && blockIdx.x >= 8) return;
    const bf16* a_hi = z ? kvinh : qinh;
    const bf16* a_lo = z ? kvinl : qinl;
    const bf16* b_hi = wh + (z ? (size_t)512 * DD : 0);
    const bf16* b_lo = wl + (z ? (size_t)512 * DD : 0);
    const float* bias = z ? bkv : bq;
    gemm_core(a_hi, a_lo, b_hi, b_lo, bias, nullptr, z,
              blockIdx.y * 128, blockIdx.x * 64, smc);
}

// LAUNCH 5: O projection.
__global__ void __launch_bounds__(256, 2) o_gemm(
    const bf16* __restrict__ ah, const bf16* __restrict__ al,
    const bf16* __restrict__ bh, const bf16* __restrict__ bl,
    const float* __restrict__ bias, float* __restrict__ dout)
{
    extern __shared__ char smc[];
    gemm_core(ah, al, bh, bl, bias, dout, 2, blockIdx.y * 128, blockIdx.x * 64, smc);
}

// ---------------------------------------------------------------------------
// LAUNCH 4: HMMA flash attention — R9 structure, ONE change: mask LDGs hoisted
// above the S-MMA block (issued right after stageV), packed into 8 uint regs.
// Their ~250-580cyc latency is now hidden behind 96 MMAs instead of exposed.
// ---------------------------------------------------------------------------
__global__ void __launch_bounds__(128, 3) attn_kernel(const int* __restrict__ lengths)
{
    extern __shared__ char smc[];
    const uint32_t smb = smem_to_u32(smc);
    const uint32_t Qh = smb, Ql = smb + 8192, Kh = smb + 16384, Kl = smb + 24576;
    const uint32_t Vh = smb + 32768, Vl = smb + 40960;

    const int tid = threadIdx.x, w = tid >> 5, lane = tid & 31;
    const int b = blockIdx.y >> 3, h = blockIdx.y & 7;
    const int q0 = blockIdx.x * 64;

    int maxlen = 0;
#pragma unroll
    for (int i = 0; i < BB; i++) maxlen = max(maxlen, lengths[i]);
    const int klen = lengths[b] + MMEM + (TQ_ - maxlen - SS);
    const int kend = min(TK_, (klen + 63) & ~63);

    const int ldrow = tid >> 1;
    const int ldc0  = (tid & 1) * 4;

    auto stageK = [&](int k0c) {
        const int tk = k0c + ldrow;
        const int bytes = (tk < TK_) ? 16 : 0;
        const size_t go = ((size_t)tk * BB + b) * DD + h * DHH + ldc0 * 8;
#pragma unroll
        for (int i = 0; i < 4; i++) {
            uint32_t so = SWZ((uint32_t)(ldrow * 128 + (ldc0 + i) * 16));
            cp16(Kh + so, g_k_hi + go + i * 8, bytes);
            cp16(Kl + so, g_k_lo + go + i * 8, bytes);
        }
        CP_COMMIT();
    };
    auto stageV = [&](int k0c) {
        const int tk = k0c + ldrow;
        const int bytes = (tk < TK_) ? 16 : 0;
        const size_t go = ((size_t)tk * BB + b) * DD + h * DHH + ldc0 * 8;
#pragma unroll
        for (int i = 0; i < 4; i++) {
            uint32_t so = SWZ((uint32_t)(ldrow * 128 + (ldc0 + i) * 16));
            cp16(Vh + so, g_v_hi + go + i * 8, bytes);
            cp16(Vl + so, g_v_lo + go + i * 8, bytes);
        }
        CP_COMMIT();
    };

    // stage Q (group 1), stage K(0) (group 2); WAIT1 drains Q only
    {
        const int q = q0 + ldrow;
        const int bytes = (q < TQ_) ? 16 : 0;
        const size_t go = ((size_t)q * BB + b) * DD + h * DHH + ldc0 * 8;
#pragma unroll
        for (int i = 0; i < 4; i++) {
            uint32_t so = SWZ((uint32_t)(ldrow * 128 + (ldc0 + i) * 16));
            cp16(Qh + so, g_q_hi + go + i * 8, bytes);
            cp16(Ql + so, g_q_lo + go + i * 8, bytes);
        }
        CP_COMMIT();
    }
    stageK(0);
    CP_WAIT1();
    __syncthreads();

    const int rr  = (lane & 7) + ((lane >> 3) & 1) * 8;
    const int kk8 = (lane >> 4) * 8;

    uint32_t qh[4][4], ql[4][4];
#pragma unroll
    for (int kd = 0; kd < 4; kd++) {
        uint32_t off = SWZ((uint32_t)((16 * w + rr) * 128 + (kd * 16 + kk8) * 2));
        ldmat4(qh[kd], Qh + off);
        ldmat4(ql[kd], Ql + off);
    }

    float o[8][4];
#pragma unroll
    for (int j = 0; j < 8; j++)
#pragma unroll
        for (int d = 0; d < 4; d++) o[j][d] = 0.f;
    float mr0 = neg_inf_f(), mr1 = neg_inf_f(), lr0 = 0.f, lr1 = 0.f;

    const int lq = lane >> 2, lc = (lane & 3) * 2;
    const int qr0 = q0 + 16 * w + lq, qr1 = qr0 + 8;

    for (int k0 = 0; k0 < kend; k0 += 64) {
        CP_WAIT0();          // K(k0) ready (and prior V drained)
        __syncthreads();     // all warps past PV(k0-64): V buffer free
        stageV(k0);          // async V load overlaps S MMAs

        // ---- mask prefetch (hoisted: latency hidden behind S MMAs) ----
        // packed: mAp[j>>1] bits [15:0]=j even (x|y<<8), [31:16]=j odd
        uint32_t mAp[4], mBp[4];
#pragma unroll
        for (int j = 0; j < 8; j++) {
            const int kc = k0 + 8 * j + lc;
            uint32_t a = 0x0101u, bm = 0x0101u;
            if (kc < TK_ - 1) {
                if (qr0 < TQ_) a  = *(const unsigned short*)&g_mask[(size_t)qr0 * TK_ + kc];
                if (qr1 < TQ_) bm = *(const unsigned short*)&g_mask[(size_t)qr1 * TK_ + kc];
            }
            if (j & 1) { mAp[j >> 1] |= a << 16; mBp[j >> 1] |= bm << 16; }
            else       { mAp[j >> 1]  = a;       mBp[j >> 1]  = bm;       }
        }

        // ---- S = Q K^T ----
        float s[8][4];
#pragma unroll
        for (int j = 0; j < 8; j++)
#pragma unroll
            for (int d = 0; d < 4; d++) s[j][d] = 0.f;

#pragma unroll
        for (int kd = 0; kd < 4; kd++) {
            const uint32_t ko = (uint32_t)((kd * 16 + kk8) * 2);
#pragma unroll
            for (int p = 0; p < 4; p++) {
                uint32_t kh4[4], kl4[4];
                uint32_t off = SWZ((uint32_t)((p * 16 + rr) * 128) + ko);
                ldmat4(kh4, Kh + off);
                ldmat4(kl4, Kl + off);
                mma16816(s[2 * p],     qh[kd], kh4[0], kh4[2]);
                mma16816(s[2 * p],     qh[kd], kl4[0], kl4[2]);
                mma16816(s[2 * p],     ql[kd], kh4[0], kh4[2]);
                mma16816(s[2 * p + 1], qh[kd], kh4[1], kh4[3]);
                mma16816(s[2 * p + 1], qh[kd], kl4[1], kl4[3]);
                mma16816(s[2 * p + 1], ql[kd], kh4[1], kh4[3]);
            }
        }

        CP_WAIT0();          // V(k0) ready
        __syncthreads();     // all warps past S: K buffer free

        // ---- mask apply (values already in registers) ----
#pragma unroll
        for (int j = 0; j < 8; j++) {
            const int kc = k0 + 8 * j + lc;
            const uint32_t av = (mAp[j >> 1] >> ((j & 1) * 16));
            const uint32_t bv = (mBp[j >> 1] >> ((j & 1) * 16));
            const unsigned char mAx = av & 0xFF, mAy = (av >> 8) & 0xFF;
            const unsigned char mBx = bv & 0xFF, mBy = (bv >> 8) & 0xFF;
            if (kc >= TK_) {
                s[j][0] = s[j][2] = neg_inf_f();
            } else {
                if (mAx || kc >= klen) s[j][0] = NEGINF_;
                if (mBx || kc >= klen) s[j][2] = NEGINF_;
            }
            if (kc + 1 >= TK_) {
                s[j][1] = s[j][3] = neg_inf_f();
            } else {
                if (mAy || kc + 1 >= klen) s[j][1] = NEGINF_;
                if (mBy || kc + 1 >= klen) s[j][3] = NEGINF_;
            }
        }

        // ---- online softmax ----
        float mx0 = NEGINF_, mx1 = NEGINF_;
#pragma unroll
        for (int j = 0; j < 8; j++) {
            mx0 = fmaxf(mx0, fmaxf(s[j][0], s[j][1]));
            mx1 = fmaxf(mx1, fmaxf(s[j][2], s[j][3]));
        }
        mx0 = fmaxf(mx0, __shfl_xor_sync(0xffffffffu, mx0, 1));
        mx0 = fmaxf(mx0, __shfl_xor_sync(0xffffffffu, mx0, 2));
        mx1 = fmaxf(mx1, __shfl_xor_sync(0xffffffffu, mx1, 1));
        mx1 = fmaxf(mx1, __shfl_xor_sync(0xffffffffu, mx1, 2));
        const float mn0 = fmaxf(mr0, mx0), mn1 = fmaxf(mr1, mx1);
        const float a0 = __expf(mr0 - mn0), a1 = __expf(mr1 - mn1);
        float su0 = 0.f, su1 = 0.f;
#pragma unroll
        for (int j = 0; j < 8; j++) {
            s[j][0] = __expf(s[j][0] - mn0);
            s[j][1] = __expf(s[j][1] - mn0);
            s[j][2] = __expf(s[j][2] - mn1);
            s[j][3] = __expf(s[j][3] - mn1);
            su0 += s[j][0] + s[j][1];
            su1 += s[j][2] + s[j][3];
        }
        su0 += __shfl_xor_sync(0xffffffffu, su0, 1);
        su0 += __shfl_xor_sync(0xffffffffu, su0, 2);
        su1 += __shfl_xor_sync(0xffffffffu, su1, 1);
        su1 += __shfl_xor_sync(0xffffffffu, su1, 2);
        lr0 = lr0 * a0 + su0;  mr0 = mn0;
        lr1 = lr1 * a1 + su1;  mr1 = mn1;
#pragma unroll
        for (int j = 0; j < 8; j++) {
            o[j][0] *= a0; o[j][1] *= a0;
            o[j][2] *= a1; o[j][3] *= a1;
        }

        // ---- P -> bf16 hi/lo ----
        uint32_t ph0[8], pl0[8], ph1[8], pl1[8];
#pragma unroll
        for (int j = 0; j < 8; j++) {
            ph0[j] = pk_hi(s[j][0], s[j][1]);
            pl0[j] = pk_lo(s[j][0], s[j][1]);
            ph1[j] = pk_hi(s[j][2], s[j][3]);
            pl1[j] = pk_lo(s[j][2], s[j][3]);
        }

        if (k0 + 64 < kend) stageK(k0 + 64);   // async K load overlaps PV MMAs

        // ---- O += P V ----
#pragma unroll
        for (int kd = 0; kd < 4; kd++) {
            const uint32_t pah[4] = {ph0[2 * kd], ph1[2 * kd], ph0[2 * kd + 1], ph1[2 * kd + 1]};
            const uint32_t pal[4] = {pl0[2 * kd], pl1[2 * kd], pl0[2 * kd + 1], pl1[2 * kd + 1]};
#pragma unroll
            for (int p = 0; p < 4; p++) {
                uint32_t vh4[4], vl4[4];
                uint32_t off = SWZ((uint32_t)((kd * 16 + rr) * 128 + (p * 16 + kk8) * 2));
                ldmat4t(vh4, Vh + off);
                ldmat4t(vl4, Vl + off);
                mma16816(o[2 * p],     pah, vh4[0], vh4[1]);
                mma16816(o[2 * p],     pah, vl4[0], vl4[1]);
                mma16816(o[2 * p],     pal, vh4[0], vh4[1]);
                mma16816(o[2 * p + 1], pah, vh4[2], vh4[3]);
                mma16816(o[2 * p + 1], pah, vl4[2], vl4[3]);
                mma16816(o[2 * p + 1], pal, vh4[2], vh4[3]);
            }
        }
    }

    // ---- epilogue: o / l -> split bf16 for the O projection ----
    const float inv0 = 1.f / lr0, inv1 = 1.f / lr1;
#pragma unroll
    for (int j = 0; j < 8; j++) {
        const int dh = h * DHH + 8 * j + lc;
        if (qr0 < TQ_) {
            const float v0 = o[j][0] * inv0, v1 = o[j][1] * inv0;
            const size_t ad = ((size_t)qr0 * BB + b) * DD + dh;
            *(uint32_t*)&g_a_hi[ad] = pk_hi(v0, v1);
            *(uint32_t*)&g_a_lo[ad] = pk_lo(v0, v1);
        }
        if (qr1 < TQ_) {
            const float v0 = o[j][2] * inv1, v1 = o[j][3] * inv1;
            const size_t ad = ((size_t)qr1 * BB + b) * DD + dh;
            *(uint32_t*)&g_a_hi[ad] = pk_hi(v0, v1);
            *(uint32_t*)&g_a_lo[ad] = pk_lo(v0, v1);
        }
    }
}

// ---------------------------------------------------------------------------
extern "C" void kernel_launch(void* const* d_in, const int* in_sizes, int n_in,
                              void* d_out, int out_size)
{
    const float* utt = (const float*)d_in[0];
    const float* rc  = (const float*)d_in[1];
    const float* smr = (const float*)d_in[2];
    const float* mem = (const float*)d_in[3];
    const float* Wq  = (const float*)d_in[4];
    const float* bq  = (const float*)d_in[5];
    const float* Wkv = (const float*)d_in[6];
    const float* bkv = (const float*)d_in[7];
    const float* Wo  = (const float*)d_in[8];
    const float* bo  = (const float*)d_in[9];
    const int*   len = (const int*)d_in[10];
    const unsigned char* am = (const unsigned char*)d_in[11];
    float* out = (float*)d_out;

    const int gemm_smem = 98304;   // 2 stages x 48KB
    const int attn_smem = 49152;
    cudaFuncSetAttribute(qkv_gemm, cudaFuncAttributeMaxDynamicSharedMemorySize, gemm_smem);
    cudaFuncSetAttribute(o_gemm,   cudaFuncAttributeMaxDynamicSharedMemorySize, gemm_smem);
    cudaFuncSetAttribute(attn_kernel, cudaFuncAttributeMaxDynamicSharedMemorySize, attn_smem);

    bf16 *qinh, *qinl, *kvinh, *kvinl, *ah, *al, *wh, *wl;
    cudaGetSymbolAddress((void**)&qinh,  g_qin_hi);
    cudaGetSymbolAddress((void**)&qinl,  g_qin_lo);
    cudaGetSymbolAddress((void**)&kvinh, g_kvin_hi);
    cudaGetSymbolAddress((void**)&kvinl, g_kvin_lo);
    cudaGetSymbolAddress((void**)&ah,    g_a_hi);
    cudaGetSymbolAddress((void**)&al,    g_a_lo);
    cudaGetSymbolAddress((void**)&wh,    g_w_hi);
    cudaGetSymbolAddress((void**)&wl,    g_w_lo);

    // LAUNCH 1: mask
    mask_kernel<<<(TQ_ * TK_ + 255) / 256, 256>>>(am);
    // LAUNCH 2: all conversions
    convert_all_kernel<<<dim3((TQ_ * BB * DD / 4 + 255) / 256, 3), 256>>>(
        utt, rc, smr, mem, Wq, Wkv, Wo);
    // LAUNCH 3: Q + KV projections (merged), 128-row m-tiles: 8832 = 69*128
    qkv_gemm<<<dim3(16, 69, 2), 256, gemm_smem>>>(qinh, qinl, kvinh, kvinl, wh, wl, bq, bkv);
    // LAUNCH 4: attention (profiled slot)
    attn_kernel<<<dim3(18, 64), 128, attn_smem>>>(len);
    // LAUNCH 5: O projection
    o_gemm<<<dim3(8, 69), 256, gemm_smem>>>(ah, al, wh + (size_t)1536 * DD,
                                            wl + (size_t)1536 * DD, bo, out);
}

// round 11
// speedup vs baseline: 1.4807x; 1.0014x over previous
#include <cuda_runtime.h>
#include <cuda_bf16.h>
#include <cstdint>

#define TT 1024
#define RR 64
#define SS 16
#define MMEM 16
#define BB 8
#define DD 512
#define HH 8
#define DHH 64
#define TQ_ 1104
#define TK_ 1104
#define SCALE_ 0.125f
#define NEGINF_ (-1.0e8f)

typedef __nv_bfloat16 bf16;

// ---------------- scratch (device globals; allocation-free rule) ----------------
__device__ bf16 g_qin_hi [(size_t)TQ_ * BB * DD];
__device__ bf16 g_qin_lo [(size_t)TQ_ * BB * DD];
__device__ bf16 g_kvin_hi[(size_t)TK_ * BB * DD];
__device__ bf16 g_kvin_lo[(size_t)TK_ * BB * DD];
__device__ bf16 g_w_hi[(size_t)2048 * DD];   // Wq | Wkv | Wo rows
__device__ bf16 g_w_lo[(size_t)2048 * DD];
__device__ bf16 g_q_hi[(size_t)TQ_ * BB * DD];
__device__ bf16 g_q_lo[(size_t)TQ_ * BB * DD];
__device__ bf16 g_k_hi[(size_t)TK_ * BB * DD];
__device__ bf16 g_k_lo[(size_t)TK_ * BB * DD];
__device__ bf16 g_v_hi[(size_t)TK_ * BB * DD];
__device__ bf16 g_v_lo[(size_t)TK_ * BB * DD];
__device__ bf16 g_a_hi[(size_t)TQ_ * BB * DD];
__device__ bf16 g_a_lo[(size_t)TQ_ * BB * DD];
__device__ unsigned char g_mask[(size_t)TQ_ * TK_];

__device__ __forceinline__ float neg_inf_f() { return __int_as_float(0xff800000); }

// ---------------- low-level helpers (sm_80-era only; no 'a' features) ----------------
__device__ __forceinline__ uint32_t smem_to_u32(const void* p) {
    uint32_t a;
    asm("{ .reg .u64 t; cvta.to.shared.u64 t, %1; cvt.u32.u64 %0, t; }" : "=r"(a) : "l"(p));
    return a;
}
__device__ __forceinline__ void ldmat4(uint32_t r[4], uint32_t addr) {
    asm volatile("ldmatrix.sync.aligned.m8n8.x4.shared.b16 {%0,%1,%2,%3}, [%4];"
                 : "=r"(r[0]), "=r"(r[1]), "=r"(r[2]), "=r"(r[3]) : "r"(addr));
}
__device__ __forceinline__ void ldmat4t(uint32_t r[4], uint32_t addr) {
    asm volatile("ldmatrix.sync.aligned.m8n8.x4.trans.shared.b16 {%0,%1,%2,%3}, [%4];"
                 : "=r"(r[0]), "=r"(r[1]), "=r"(r[2]), "=r"(r[3]) : "r"(addr));
}
__device__ __forceinline__ void mma16816(float d[4], const uint32_t a[4],
                                         uint32_t b0, uint32_t b1) {
    asm volatile("mma.sync.aligned.m16n8k16.row.col.f32.bf16.bf16.f32 "
                 "{%0,%1,%2,%3}, {%4,%5,%6,%7}, {%8,%9}, {%0,%1,%2,%3};"
                 : "+f"(d[0]), "+f"(d[1]), "+f"(d[2]), "+f"(d[3])
                 : "r"(a[0]), "r"(a[1]), "r"(a[2]), "r"(a[3]), "r"(b0), "r"(b1));
}
__device__ __forceinline__ void cp16(uint32_t dst, const void* src, int bytes) {
    asm volatile("cp.async.cg.shared.global [%0], [%1], 16, %2;"
                 :: "r"(dst), "l"(src), "r"(bytes));
}
#define CP_COMMIT() asm volatile("cp.async.commit_group;" ::: "memory")
#define CP_WAIT0()  asm volatile("cp.async.wait_group 0;" ::: "memory")
#define CP_WAIT1()  asm volatile("cp.async.wait_group 1;" ::: "memory")

#define SWZ(o) ((o) ^ (((o) >> 3) & 0x70))

__device__ __forceinline__ uint32_t pk2(bf16 a, bf16 b) {
    return ((uint32_t)__bfloat16_as_ushort(b) << 16) | __bfloat16_as_ushort(a);
}
__device__ __forceinline__ uint32_t pk_hi(float a, float b) {
    return pk2(__float2bfloat16(a), __float2bfloat16(b));
}
__device__ __forceinline__ uint32_t pk_lo(float a, float b) {
    bf16 ha = __float2bfloat16(a), hb = __float2bfloat16(b);
    return pk2(__float2bfloat16(a - __bfloat162float(ha)),
               __float2bfloat16(b - __bfloat162float(hb)));
}

// ---------------------------------------------------------------------------
// LAUNCH 1: mask detect + canonicalize (unchanged).
// ---------------------------------------------------------------------------
__global__ void __launch_bounds__(256) mask_kernel(const unsigned char* __restrict__ buf)
{
    __shared__ int s_large, s_nzoff;
    if (threadIdx.x == 0) { s_large = 0; s_nzoff = 0; }
    __syncthreads();
    int l = 0, z = 0;
    {
        const int base = threadIdx.x * 16;
#pragma unroll
        for (int j = 0; j < 16; j++) {
            unsigned char v = buf[base + j];
            if (v > 1) l = 1;
            if (((base + j) & 3) && v != 0) z = 1;
        }
    }
    if (l) atomicOr(&s_large, 1);
    if (z) atomicOr(&s_nzoff, 1);
    __syncthreads();
    const int mode = s_large ? 2 : (s_nzoff ? 0 : 1);

    const int idx = blockIdx.x * blockDim.x + threadIdx.x;
    if (idx >= TQ_ * TK_) return;
    unsigned char m;
    if (mode == 0)      m = buf[idx] ? 1 : 0;
    else if (mode == 1) m = (((const int*)buf)[idx] != 0) ? 1 : 0;
    else                m = (((const float*)buf)[idx] != 0.f) ? 1 : 0;
    g_mask[idx] = m;
}

// ---------------------------------------------------------------------------
// LAUNCH 2: all fp32 -> split-bf16 conversions (unchanged).
// ---------------------------------------------------------------------------
__global__ void __launch_bounds__(256) convert_all_kernel(
    const float* __restrict__ utt, const float* __restrict__ rc,
    const float* __restrict__ smr, const float* __restrict__ mem,
    const float* __restrict__ Wq, const float* __restrict__ Wkv,
    const float* __restrict__ Wo)
{
    const int y = blockIdx.y;
    const size_t e = ((size_t)blockIdx.x * blockDim.x + threadIdx.x) * 4;
    if (y < 2) {
        if (e >= (size_t)TQ_ * BB * DD) return;
        const int r = (int)(e >> 9);
        const int k = (int)(e & 511);
        const int t = r >> 3, b = r & 7;
        const float* src;
        if (y == 0) {
            if (t < RR)           src = rc  + ((size_t)t * BB + b) * DD;
            else if (t < RR + TT) src = utt + ((size_t)(t - RR) * BB + b) * DD;
            else                  src = smr + ((size_t)(t - RR - TT) * BB + b) * DD;
        } else {
            if (t < MMEM)           src = mem + ((size_t)t * BB + b) * DD;
            else if (t < MMEM + RR) src = rc  + ((size_t)(t - MMEM) * BB + b) * DD;
            else                    src = utt + ((size_t)(t - MMEM - RR) * BB + b) * DD;
        }
        float4 v = *(const float4*)(src + k);
        bf16* dh = y ? g_kvin_hi : g_qin_hi;
        bf16* dl = y ? g_kvin_lo : g_qin_lo;
        *(uint2*)&dh[e] = make_uint2(pk_hi(v.x, v.y), pk_hi(v.z, v.w));
        *(uint2*)&dl[e] = make_uint2(pk_lo(v.x, v.y), pk_lo(v.z, v.w));
    } else {
        if (e >= (size_t)2048 * DD) return;
        const int r = (int)(e >> 9);
        const int k = (int)(e & 511);
        const float* src;
        if (r < 512)       src = Wq  + (size_t)r * DD;
        else if (r < 1536) src = Wkv + (size_t)(r - 512) * DD;
        else               src = Wo  + (size_t)(r - 1536) * DD;
        float4 v = *(const float4*)(src + k);
        *(uint2*)&g_w_hi[e] = make_uint2(pk_hi(v.x, v.y), pk_hi(v.z, v.w));
        *(uint2*)&g_w_lo[e] = make_uint2(pk_lo(v.x, v.y), pk_lo(v.z, v.w));
    }
}

// ---------------------------------------------------------------------------
// GEMM core — 128m x 64n, 256 threads / 8 warps, K=512, 3-MMA split.
// R11: term-major MMA ordering (hh x8, hl x8, lh x8) — dependency gap 8
// instead of 0; per-accumulator order unchanged -> bit-identical output.
// ---------------------------------------------------------------------------
__device__ __forceinline__ void gemm_core(
    const bf16* __restrict__ a_hi, const bf16* __restrict__ a_lo,
    const bf16* __restrict__ b_hi, const bf16* __restrict__ b_lo,
    const float* __restrict__ bias, float* __restrict__ dout,
    int mode, int m0, int n0, char* smc)
{
    const uint32_t smb = smem_to_u32(smc);
    const int tid = threadIdx.x, w = tid >> 5, lane = tid & 31;
    const int wm = w >> 1, wn = w & 1;

    const int ra  = tid >> 1;
    const int ca0 = (tid & 1) * 4;
    const int rb  = tid >> 2;
    const int cb0 = (tid & 3) * 2;

    auto stage = [&](int kc) {
        const uint32_t sb = smb + (kc & 1) * 49152;
        const bf16* As_h = a_hi + (size_t)(m0 + ra) * DD + kc * 64 + ca0 * 8;
        const bf16* As_l = a_lo + (size_t)(m0 + ra) * DD + kc * 64 + ca0 * 8;
#pragma unroll
        for (int i = 0; i < 4; i++) {
            uint32_t so = SWZ((uint32_t)(ra * 128 + (ca0 + i) * 16));
            cp16(sb + so,         As_h + i * 8, 16);
            cp16(sb + 16384 + so, As_l + i * 8, 16);
        }
        const bf16* Bs_h = b_hi + (size_t)(n0 + rb) * DD + kc * 64 + cb0 * 8;
        const bf16* Bs_l = b_lo + (size_t)(n0 + rb) * DD + kc * 64 + cb0 * 8;
#pragma unroll
        for (int i = 0; i < 2; i++) {
            uint32_t so = SWZ((uint32_t)(rb * 128 + (cb0 + i) * 16));
            cp16(sb + 32768 + so, Bs_h + i * 8, 16);
            cp16(sb + 40960 + so, Bs_l + i * 8, 16);
        }
        CP_COMMIT();
    };

    float acc[2][4][4];
#pragma unroll
    for (int a = 0; a < 2; a++)
#pragma unroll
        for (int c = 0; c < 4; c++)
#pragma unroll
            for (int d = 0; d < 4; d++) acc[a][c][d] = 0.f;

    const int rr  = (lane & 7) + ((lane >> 3) & 1) * 8;
    const int kk8 = (lane >> 4) * 8;

    stage(0);
    for (int c = 0; c < 8; c++) {
        CP_WAIT0();
        __syncthreads();
        if (c < 7) stage(c + 1);
        const uint32_t sb = smb + (c & 1) * 49152;
#pragma unroll
        for (int kd = 0; kd < 4; kd++) {
            const uint32_t ko = (uint32_t)((kd * 16 + kk8) * 2);
            uint32_t ah[2][4], al[2][4], bh[2][4], bl[2][4];
#pragma unroll
            for (int mt = 0; mt < 2; mt++) {
                uint32_t off = SWZ((uint32_t)((wm * 32 + mt * 16 + rr) * 128) + ko);
                ldmat4(ah[mt], sb + off);
                ldmat4(al[mt], sb + 16384 + off);
            }
#pragma unroll
            for (int p = 0; p < 2; p++) {
                uint32_t off = SWZ((uint32_t)((wn * 32 + p * 16 + rr) * 128) + ko);
                ldmat4(bh[p], sb + 32768 + off);
                ldmat4(bl[p], sb + 40960 + off);
            }
            // term-major: hh x8, hl x8, lh x8 (dep gap 8; per-acc order hh->hl->lh)
#pragma unroll
            for (int mt = 0; mt < 2; mt++)
#pragma unroll
                for (int nt = 0; nt < 4; nt++)
                    mma16816(acc[mt][nt], ah[mt],
                             bh[nt >> 1][nt & 1], bh[nt >> 1][2 + (nt & 1)]);
#pragma unroll
            for (int mt = 0; mt < 2; mt++)
#pragma unroll
                for (int nt = 0; nt < 4; nt++)
                    mma16816(acc[mt][nt], ah[mt],
                             bl[nt >> 1][nt & 1], bl[nt >> 1][2 + (nt & 1)]);
#pragma unroll
            for (int mt = 0; mt < 2; mt++)
#pragma unroll
                for (int nt = 0; nt < 4; nt++)
                    mma16816(acc[mt][nt], al[mt],
                             bh[nt >> 1][nt & 1], bh[nt >> 1][2 + (nt & 1)]);
        }
    }

    const int lq = lane >> 2, lc = (lane & 3) * 2;
#pragma unroll
    for (int mt = 0; mt < 2; mt++) {
#pragma unroll
        for (int nt = 0; nt < 4; nt++) {
            const int col = n0 + wn * 32 + nt * 8 + lc;
            const float b0 = bias[col], b1 = bias[col + 1];
#pragma unroll
            for (int hrow = 0; hrow < 2; hrow++) {
                const int m = m0 + wm * 32 + mt * 16 + lq + hrow * 8;
                float v0 = acc[mt][nt][hrow * 2 + 0] + b0;
                float v1 = acc[mt][nt][hrow * 2 + 1] + b1;
                if (mode == 0) {
                    v0 *= SCALE_; v1 *= SCALE_;
                    *(uint32_t*)&g_q_hi[(size_t)m * DD + col] = pk_hi(v0, v1);
                    *(uint32_t*)&g_q_lo[(size_t)m * DD + col] = pk_lo(v0, v1);
                } else if (mode == 1) {
                    if (col < DD) {
                        *(uint32_t*)&g_k_hi[(size_t)m * DD + col] = pk_hi(v0, v1);
                        *(uint32_t*)&g_k_lo[(size_t)m * DD + col] = pk_lo(v0, v1);
                    } else {
                        *(uint32_t*)&g_v_hi[(size_t)m * DD + col - DD] = pk_hi(v0, v1);
                        *(uint32_t*)&g_v_lo[(size_t)m * DD + col - DD] = pk_lo(v0, v1);
                    }
                } else {
                    const int tt = m >> 3, rbb = m & 7;
                    if (tt < TQ_ - SS) {
                        *(float2*)&dout[(size_t)m * DD + col] = make_float2(v0, v1);
                    } else if (tt < TQ_ - 1) {
                        v0 = fminf(10.f, fmaxf(-10.f, v0));
                        v1 = fminf(10.f, fmaxf(-10.f, v1));
                        *(float2*)&dout[(size_t)(TQ_ - SS) * BB * DD +
                                        ((size_t)(tt - (TQ_ - SS)) * BB + rbb) * DD + col] =
                            make_float2(v0, v1);
                    }
                }
            }
        }
    }
}

// LAUNCH 3: Q-proj (z=0) + KV-proj (z=1) merged.
__global__ void __launch_bounds__(256, 2) qkv_gemm(
    const bf16* __restrict__ qinh, const bf16* __restrict__ qinl,
    const bf16* __restrict__ kvinh, const bf16* __restrict__ kvinl,
    const bf16* __restrict__ wh, const bf16* __restrict__ wl,
    const float* __restrict__ bq, const float* __restrict__ bkv)
{
    extern __shared__ char smc[];
    const int z = blockIdx.z;
    if (z == 0 && blockIdx.x >= 8) return;
    const bf16* a_hi = z ? kvinh : qinh;
    const bf16* a_lo = z ? kvinl : qinl;
    const bf16* b_hi = wh + (z ? (size_t)512 * DD : 0);
    const bf16* b_lo = wl + (z ? (size_t)512 * DD : 0);
    const float* bias = z ? bkv : bq;
    gemm_core(a_hi, a_lo, b_hi, b_lo, bias, nullptr, z,
              blockIdx.y * 128, blockIdx.x * 64, smc);
}

// LAUNCH 5: O projection.
__global__ void __launch_bounds__(256, 2) o_gemm(
    const bf16* __restrict__ ah, const bf16* __restrict__ al,
    const bf16* __restrict__ bh, const bf16* __restrict__ bl,
    const float* __restrict__ bias, float* __restrict__ dout)
{
    extern __shared__ char smc[];
    gemm_core(ah, al, bh, bl, bias, dout, 2, blockIdx.y * 128, blockIdx.x * 64, smc);
}

// ---------------------------------------------------------------------------
// LAUNCH 4: HMMA flash attention — R10 structure, ONE change: term-major MMA
// ordering in S (all-4-p K preload, dep gap 8) and PV (2-p groups, dep gap 4).
// Per-accumulator term order unchanged -> bit-identical output.
// ---------------------------------------------------------------------------
__global__ void __launch_bounds__(128, 3) attn_kernel(const int* __restrict__ lengths)
{
    extern __shared__ char smc[];
    const uint32_t smb = smem_to_u32(smc);
    const uint32_t Qh = smb, Ql = smb + 8192, Kh = smb + 16384, Kl = smb + 24576;
    const uint32_t Vh = smb + 32768, Vl = smb + 40960;

    const int tid = threadIdx.x, w = tid >> 5, lane = tid & 31;
    const int b = blockIdx.y >> 3, h = blockIdx.y & 7;
    const int q0 = blockIdx.x * 64;

    int maxlen = 0;
#pragma unroll
    for (int i = 0; i < BB; i++) maxlen = max(maxlen, lengths[i]);
    const int klen = lengths[b] + MMEM + (TQ_ - maxlen - SS);
    const int kend = min(TK_, (klen + 63) & ~63);

    const int ldrow = tid >> 1;
    const int ldc0  = (tid & 1) * 4;

    auto stageK = [&](int k0c) {
        const int tk = k0c + ldrow;
        const int bytes = (tk < TK_) ? 16 : 0;
        const size_t go = ((size_t)tk * BB + b) * DD + h * DHH + ldc0 * 8;
#pragma unroll
        for (int i = 0; i < 4; i++) {
            uint32_t so = SWZ((uint32_t)(ldrow * 128 + (ldc0 + i) * 16));
            cp16(Kh + so, g_k_hi + go + i * 8, bytes);
            cp16(Kl + so, g_k_lo + go + i * 8, bytes);
        }
        CP_COMMIT();
    };
    auto stageV = [&](int k0c) {
        const int tk = k0c + ldrow;
        const int bytes = (tk < TK_) ? 16 : 0;
        const size_t go = ((size_t)tk * BB + b) * DD + h * DHH + ldc0 * 8;
#pragma unroll
        for (int i = 0; i < 4; i++) {
            uint32_t so = SWZ((uint32_t)(ldrow * 128 + (ldc0 + i) * 16));
            cp16(Vh + so, g_v_hi + go + i * 8, bytes);
            cp16(Vl + so, g_v_lo + go + i * 8, bytes);
        }
        CP_COMMIT();
    };

    // stage Q (group 1), stage K(0) (group 2); WAIT1 drains Q only
    {
        const int q = q0 + ldrow;
        const int bytes = (q < TQ_) ? 16 : 0;
        const size_t go = ((size_t)q * BB + b) * DD + h * DHH + ldc0 * 8;
#pragma unroll
        for (int i = 0; i < 4; i++) {
            uint32_t so = SWZ((uint32_t)(ldrow * 128 + (ldc0 + i) * 16));
            cp16(Qh + so, g_q_hi + go + i * 8, bytes);
            cp16(Ql + so, g_q_lo + go + i * 8, bytes);
        }
        CP_COMMIT();
    }
    stageK(0);
    CP_WAIT1();
    __syncthreads();

    const int rr  = (lane & 7) + ((lane >> 3) & 1) * 8;
    const int kk8 = (lane >> 4) * 8;

    uint32_t qh[4][4], ql[4][4];
#pragma unroll
    for (int kd = 0; kd < 4; kd++) {
        uint32_t off = SWZ((uint32_t)((16 * w + rr) * 128 + (kd * 16 + kk8) * 2));
        ldmat4(qh[kd], Qh + off);
        ldmat4(ql[kd], Ql + off);
    }

    float o[8][4];
#pragma unroll
    for (int j = 0; j < 8; j++)
#pragma unroll
        for (int d = 0; d < 4; d++) o[j][d] = 0.f;
    float mr0 = neg_inf_f(), mr1 = neg_inf_f(), lr0 = 0.f, lr1 = 0.f;

    const int lq = lane >> 2, lc = (lane & 3) * 2;
    const int qr0 = q0 + 16 * w + lq, qr1 = qr0 + 8;

    for (int k0 = 0; k0 < kend; k0 += 64) {
        CP_WAIT0();
        __syncthreads();
        stageV(k0);

        // ---- mask prefetch (hidden behind S MMAs) ----
        uint32_t mAp[4], mBp[4];
#pragma unroll
        for (int j = 0; j < 8; j++) {
            const int kc = k0 + 8 * j + lc;
            uint32_t a = 0x0101u, bm = 0x0101u;
            if (kc < TK_ - 1) {
                if (qr0 < TQ_) a  = *(const unsigned short*)&g_mask[(size_t)qr0 * TK_ + kc];
                if (qr1 < TQ_) bm = *(const unsigned short*)&g_mask[(size_t)qr1 * TK_ + kc];
            }
            if (j & 1) { mAp[j >> 1] |= a << 16; mBp[j >> 1] |= bm << 16; }
            else       { mAp[j >> 1]  = a;       mBp[j >> 1]  = bm;       }
        }

        // ---- S = Q K^T (term-major: dep gap 8; per-acc order hh->hl->lh) ----
        float s[8][4];
#pragma unroll
        for (int j = 0; j < 8; j++)
#pragma unroll
            for (int d = 0; d < 4; d++) s[j][d] = 0.f;

#pragma unroll
        for (int kd = 0; kd < 4; kd++) {
            const uint32_t ko = (uint32_t)((kd * 16 + kk8) * 2);
            uint32_t kh4[4][4], kl4[4][4];
#pragma unroll
            for (int p = 0; p < 4; p++) {
                uint32_t off = SWZ((uint32_t)((p * 16 + rr) * 128) + ko);
                ldmat4(kh4[p], Kh + off);
                ldmat4(kl4[p], Kl + off);
            }
#pragma unroll
            for (int p = 0; p < 4; p++) {
                mma16816(s[2 * p],     qh[kd], kh4[p][0], kh4[p][2]);
                mma16816(s[2 * p + 1], qh[kd], kh4[p][1], kh4[p][3]);
            }
#pragma unroll
            for (int p = 0; p < 4; p++) {
                mma16816(s[2 * p],     qh[kd], kl4[p][0], kl4[p][2]);
                mma16816(s[2 * p + 1], qh[kd], kl4[p][1], kl4[p][3]);
            }
#pragma unroll
            for (int p = 0; p < 4; p++) {
                mma16816(s[2 * p],     ql[kd], kh4[p][0], kh4[p][2]);
                mma16816(s[2 * p + 1], ql[kd], kh4[p][1], kh4[p][3]);
            }
        }

        CP_WAIT0();          // V(k0) ready
        __syncthreads();     // all warps past S: K buffer free

        // ---- mask apply ----
#pragma unroll
        for (int j = 0; j < 8; j++) {
            const int kc = k0 + 8 * j + lc;
            const uint32_t av = (mAp[j >> 1] >> ((j & 1) * 16));
            const uint32_t bv = (mBp[j >> 1] >> ((j & 1) * 16));
            const unsigned char mAx = av & 0xFF, mAy = (av >> 8) & 0xFF;
            const unsigned char mBx = bv & 0xFF, mBy = (bv >> 8) & 0xFF;
            if (kc >= TK_) {
                s[j][0] = s[j][2] = neg_inf_f();
            } else {
                if (mAx || kc >= klen) s[j][0] = NEGINF_;
                if (mBx || kc >= klen) s[j][2] = NEGINF_;
            }
            if (kc + 1 >= TK_) {
                s[j][1] = s[j][3] = neg_inf_f();
            } else {
                if (mAy || kc + 1 >= klen) s[j][1] = NEGINF_;
                if (mBy || kc + 1 >= klen) s[j][3] = NEGINF_;
            }
        }

        // ---- online softmax ----
        float mx0 = NEGINF_, mx1 = NEGINF_;
#pragma unroll
        for (int j = 0; j < 8; j++) {
            mx0 = fmaxf(mx0, fmaxf(s[j][0], s[j][1]));
            mx1 = fmaxf(mx1, fmaxf(s[j][2], s[j][3]));
        }
        mx0 = fmaxf(mx0, __shfl_xor_sync(0xffffffffu, mx0, 1));
        mx0 = fmaxf(mx0, __shfl_xor_sync(0xffffffffu, mx0, 2));
        mx1 = fmaxf(mx1, __shfl_xor_sync(0xffffffffu, mx1, 1));
        mx1 = fmaxf(mx1, __shfl_xor_sync(0xffffffffu, mx1, 2));
        const float mn0 = fmaxf(mr0, mx0), mn1 = fmaxf(mr1, mx1);
        const float a0 = __expf(mr0 - mn0), a1 = __expf(mr1 - mn1);
        float su0 = 0.f, su1 = 0.f;
#pragma unroll
        for (int j = 0; j < 8; j++) {
            s[j][0] = __expf(s[j][0] - mn0);
            s[j][1] = __expf(s[j][1] - mn0);
            s[j][2] = __expf(s[j][2] - mn1);
            s[j][3] = __expf(s[j][3] - mn1);
            su0 += s[j][0] + s[j][1];
            su1 += s[j][2] + s[j][3];
        }
        su0 += __shfl_xor_sync(0xffffffffu, su0, 1);
        su0 += __shfl_xor_sync(0xffffffffu, su0, 2);
        su1 += __shfl_xor_sync(0xffffffffu, su1, 1);
        su1 += __shfl_xor_sync(0xffffffffu, su1, 2);
        lr0 = lr0 * a0 + su0;  mr0 = mn0;
        lr1 = lr1 * a1 + su1;  mr1 = mn1;
#pragma unroll
        for (int j = 0; j < 8; j++) {
            o[j][0] *= a0; o[j][1] *= a0;
            o[j][2] *= a1; o[j][3] *= a1;
        }

        // ---- P -> bf16 hi/lo ----
        uint32_t ph0[8], pl0[8], ph1[8], pl1[8];
#pragma unroll
        for (int j = 0; j < 8; j++) {
            ph0[j] = pk_hi(s[j][0], s[j][1]);
            pl0[j] = pk_lo(s[j][0], s[j][1]);
            ph1[j] = pk_hi(s[j][2], s[j][3]);
            pl1[j] = pk_lo(s[j][2], s[j][3]);
        }

        if (k0 + 64 < kend) stageK(k0 + 64);

        // ---- O += P V (term-major over 2-p groups: dep gap 4) ----
#pragma unroll
        for (int kd = 0; kd < 4; kd++) {
            const uint32_t pah[4] = {ph0[2 * kd], ph1[2 * kd], ph0[2 * kd + 1], ph1[2 * kd + 1]};
            const uint32_t pal[4] = {pl0[2 * kd], pl1[2 * kd], pl0[2 * kd + 1], pl1[2 * kd + 1]};
#pragma unroll
            for (int pp = 0; pp < 4; pp += 2) {
                uint32_t vh4[2][4], vl4[2][4];
#pragma unroll
                for (int pi = 0; pi < 2; pi++) {
                    uint32_t off = SWZ((uint32_t)((kd * 16 + rr) * 128 + ((pp + pi) * 16 + kk8) * 2));
                    ldmat4t(vh4[pi], Vh + off);
                    ldmat4t(vl4[pi], Vl + off);
                }
#pragma unroll
                for (int pi = 0; pi < 2; pi++) {
                    const int p = pp + pi;
                    mma16816(o[2 * p],     pah, vh4[pi][0], vh4[pi][1]);
                    mma16816(o[2 * p + 1], pah, vh4[pi][2], vh4[pi][3]);
                }
#pragma unroll
                for (int pi = 0; pi < 2; pi++) {
                    const int p = pp + pi;
                    mma16816(o[2 * p],     pah, vl4[pi][0], vl4[pi][1]);
                    mma16816(o[2 * p + 1], pah, vl4[pi][2], vl4[pi][3]);
                }
#pragma unroll
                for (int pi = 0; pi < 2; pi++) {
                    const int p = pp + pi;
                    mma16816(o[2 * p],     pal, vh4[pi][0], vh4[pi][1]);
                    mma16816(o[2 * p + 1], pal, vh4[pi][2], vh4[pi][3]);
                }
            }
        }
    }

    // ---- epilogue ----
    const float inv0 = 1.f / lr0, inv1 = 1.f / lr1;
#pragma unroll
    for (int j = 0; j < 8; j++) {
        const int dh = h * DHH + 8 * j + lc;
        if (qr0 < TQ_) {
            const float v0 = o[j][0] * inv0, v1 = o[j][1] * inv0;
            const size_t ad = ((size_t)qr0 * BB + b) * DD + dh;
            *(uint32_t*)&g_a_hi[ad] = pk_hi(v0, v1);
            *(uint32_t*)&g_a_lo[ad] = pk_lo(v0, v1);
        }
        if (qr1 < TQ_) {
            const float v0 = o[j][2] * inv1, v1 = o[j][3] * inv1;
            const size_t ad = ((size_t)qr1 * BB + b) * DD + dh;
            *(uint32_t*)&g_a_hi[ad] = pk_hi(v0, v1);
            *(uint32_t*)&g_a_lo[ad] = pk_lo(v0, v1);
        }
    }
}

// ---------------------------------------------------------------------------
extern "C" void kernel_launch(void* const* d_in, const int* in_sizes, int n_in,
                              void* d_out, int out_size)
{
    const float* utt = (const float*)d_in[0];
    const float* rc  = (const float*)d_in[1];
    const float* smr = (const float*)d_in[2];
    const float* mem = (const float*)d_in[3];
    const float* Wq  = (const float*)d_in[4];
    const float* bq  = (const float*)d_in[5];
    const float* Wkv = (const float*)d_in[6];
    const float* bkv = (const float*)d_in[7];
    const float* Wo  = (const float*)d_in[8];
    const float* bo  = (const float*)d_in[9];
    const int*   len = (const int*)d_in[10];
    const unsigned char* am = (const unsigned char*)d_in[11];
    float* out = (float*)d_out;

    const int gemm_smem = 98304;
    const int attn_smem = 49152;
    cudaFuncSetAttribute(qkv_gemm, cudaFuncAttributeMaxDynamicSharedMemorySize, gemm_smem);
    cudaFuncSetAttribute(o_gemm,   cudaFuncAttributeMaxDynamicSharedMemorySize, gemm_smem);
    cudaFuncSetAttribute(attn_kernel, cudaFuncAttributeMaxDynamicSharedMemorySize, attn_smem);

    bf16 *qinh, *qinl, *kvinh, *kvinl, *ah, *al, *wh, *wl;
    cudaGetSymbolAddress((void**)&qinh,  g_qin_hi);
    cudaGetSymbolAddress((void**)&qinl,  g_qin_lo);
    cudaGetSymbolAddress((void**)&kvinh, g_kvin_hi);
    cudaGetSymbolAddress((void**)&kvinl, g_kvin_lo);
    cudaGetSymbolAddress((void**)&ah,    g_a_hi);
    cudaGetSymbolAddress((void**)&al,    g_a_lo);
    cudaGetSymbolAddress((void**)&wh,    g_w_hi);
    cudaGetSymbolAddress((void**)&wl,    g_w_lo);

    mask_kernel<<<(TQ_ * TK_ + 255) / 256, 256>>>(am);
    convert_all_kernel<<<dim3((TQ_ * BB * DD / 4 + 255) / 256, 3), 256>>>(
        utt, rc, smr, mem, Wq, Wkv, Wo);
    qkv_gemm<<<dim3(16, 69, 2), 256, gemm_smem>>>(qinh, qinl, kvinh, kvinl, wh, wl, bq, bkv);
    attn_kernel<<<dim3(18, 64), 128, attn_smem>>>(len);
    o_gemm<<<dim3(8, 69), 256, gemm_smem>>>(ah, al, wh + (size_t)1536 * DD,
                                            wl + (size_t)1536 * DD, bo, out);
}

// round 12
// speedup vs baseline: 1.5506x; 1.0472x over previous
#include <cuda_runtime.h>
#include <cuda_bf16.h>
#include <cstdint>

#define TT 1024
#define RR 64
#define SS 16
#define MMEM 16
#define BB 8
#define DD 512
#define HH 8
#define DHH 64
#define TQ_ 1104
#define TK_ 1104
#define SCALE_ 0.125f
#define NEGINF_ (-1.0e8f)

typedef __nv_bfloat16 bf16;

// ---------------- scratch (device globals; allocation-free rule) ----------------
__device__ bf16 g_qin_hi [(size_t)TQ_ * BB * DD];
__device__ bf16 g_qin_lo [(size_t)TQ_ * BB * DD];
__device__ bf16 g_kvin_hi[(size_t)TK_ * BB * DD];
__device__ bf16 g_kvin_lo[(size_t)TK_ * BB * DD];
__device__ bf16 g_w_hi[(size_t)2048 * DD];   // Wq | Wkv | Wo rows
__device__ bf16 g_w_lo[(size_t)2048 * DD];
__device__ bf16 g_q_hi[(size_t)TQ_ * BB * DD];
__device__ bf16 g_q_lo[(size_t)TQ_ * BB * DD];
__device__ bf16 g_k_hi[(size_t)TK_ * BB * DD];
__device__ bf16 g_k_lo[(size_t)TK_ * BB * DD];
__device__ bf16 g_v_hi[(size_t)TK_ * BB * DD];
__device__ bf16 g_v_lo[(size_t)TK_ * BB * DD];
__device__ bf16 g_a_hi[(size_t)TQ_ * BB * DD];
__device__ bf16 g_a_lo[(size_t)TQ_ * BB * DD];
__device__ unsigned char g_mask[(size_t)TQ_ * TK_];

__device__ __forceinline__ float neg_inf_f() { return __int_as_float(0xff800000); }

// ---------------- low-level helpers (sm_80-era only; no 'a' features) ----------------
__device__ __forceinline__ uint32_t smem_to_u32(const void* p) {
    uint32_t a;
    asm("{ .reg .u64 t; cvta.to.shared.u64 t, %1; cvt.u32.u64 %0, t; }" : "=r"(a) : "l"(p));
    return a;
}
__device__ __forceinline__ void ldmat4(uint32_t r[4], uint32_t addr) {
    asm volatile("ldmatrix.sync.aligned.m8n8.x4.shared.b16 {%0,%1,%2,%3}, [%4];"
                 : "=r"(r[0]), "=r"(r[1]), "=r"(r[2]), "=r"(r[3]) : "r"(addr));
}
__device__ __forceinline__ void ldmat4t(uint32_t r[4], uint32_t addr) {
    asm volatile("ldmatrix.sync.aligned.m8n8.x4.trans.shared.b16 {%0,%1,%2,%3}, [%4];"
                 : "=r"(r[0]), "=r"(r[1]), "=r"(r[2]), "=r"(r[3]) : "r"(addr));
}
__device__ __forceinline__ void mma16816(float d[4], const uint32_t a[4],
                                         uint32_t b0, uint32_t b1) {
    asm volatile("mma.sync.aligned.m16n8k16.row.col.f32.bf16.bf16.f32 "
                 "{%0,%1,%2,%3}, {%4,%5,%6,%7}, {%8,%9}, {%0,%1,%2,%3};"
                 : "+f"(d[0]), "+f"(d[1]), "+f"(d[2]), "+f"(d[3])
                 : "r"(a[0]), "r"(a[1]), "r"(a[2]), "r"(a[3]), "r"(b0), "r"(b1));
}
__device__ __forceinline__ void cp16(uint32_t dst, const void* src, int bytes) {
    asm volatile("cp.async.cg.shared.global [%0], [%1], 16, %2;"
                 :: "r"(dst), "l"(src), "r"(bytes));
}
#define CP_COMMIT() asm volatile("cp.async.commit_group;" ::: "memory")
#define CP_WAIT0()  asm volatile("cp.async.wait_group 0;" ::: "memory")
#define CP_WAIT1()  asm volatile("cp.async.wait_group 1;" ::: "memory")

#define SWZ(o) ((o) ^ (((o) >> 3) & 0x70))

__device__ __forceinline__ uint32_t pk2(bf16 a, bf16 b) {
    return ((uint32_t)__bfloat16_as_ushort(b) << 16) | __bfloat16_as_ushort(a);
}
__device__ __forceinline__ uint32_t pk_hi(float a, float b) {
    return pk2(__float2bfloat16(a), __float2bfloat16(b));
}
__device__ __forceinline__ uint32_t pk_lo(float a, float b) {
    bf16 ha = __float2bfloat16(a), hb = __float2bfloat16(b);
    return pk2(__float2bfloat16(a - __bfloat162float(ha)),
               __float2bfloat16(b - __bfloat162float(hb)));
}

// ---------------------------------------------------------------------------
// LAUNCH 1: mask detect + canonicalize (unchanged).
// ---------------------------------------------------------------------------
__global__ void __launch_bounds__(256) mask_kernel(const unsigned char* __restrict__ buf)
{
    __shared__ int s_large, s_nzoff;
    if (threadIdx.x == 0) { s_large = 0; s_nzoff = 0; }
    __syncthreads();
    int l = 0, z = 0;
    {
        const int base = threadIdx.x * 16;
#pragma unroll
        for (int j = 0; j < 16; j++) {
            unsigned char v = buf[base + j];
            if (v > 1) l = 1;
            if (((base + j) & 3) && v != 0) z = 1;
        }
    }
    if (l) atomicOr(&s_large, 1);
    if (z) atomicOr(&s_nzoff, 1);
    __syncthreads();
    const int mode = s_large ? 2 : (s_nzoff ? 0 : 1);

    const int idx = blockIdx.x * blockDim.x + threadIdx.x;
    if (idx >= TQ_ * TK_) return;
    unsigned char m;
    if (mode == 0)      m = buf[idx] ? 1 : 0;
    else if (mode == 1) m = (((const int*)buf)[idx] != 0) ? 1 : 0;
    else                m = (((const float*)buf)[idx] != 0.f) ? 1 : 0;
    g_mask[idx] = m;
}

// ---------------------------------------------------------------------------
// LAUNCH 2: all fp32 -> split-bf16 conversions (unchanged).
// ---------------------------------------------------------------------------
__global__ void __launch_bounds__(256) convert_all_kernel(
    const float* __restrict__ utt, const float* __restrict__ rc,
    const float* __restrict__ smr, const float* __restrict__ mem,
    const float* __restrict__ Wq, const float* __restrict__ Wkv,
    const float* __restrict__ Wo)
{
    const int y = blockIdx.y;
    const size_t e = ((size_t)blockIdx.x * blockDim.x + threadIdx.x) * 4;
    if (y < 2) {
        if (e >= (size_t)TQ_ * BB * DD) return;
        const int r = (int)(e >> 9);
        const int k = (int)(e & 511);
        const int t = r >> 3, b = r & 7;
        const float* src;
        if (y == 0) {
            if (t < RR)           src = rc  + ((size_t)t * BB + b) * DD;
            else if (t < RR + TT) src = utt + ((size_t)(t - RR) * BB + b) * DD;
            else                  src = smr + ((size_t)(t - RR - TT) * BB + b) * DD;
        } else {
            if (t < MMEM)           src = mem + ((size_t)t * BB + b) * DD;
            else if (t < MMEM + RR) src = rc  + ((size_t)(t - MMEM) * BB + b) * DD;
            else                    src = utt + ((size_t)(t - MMEM - RR) * BB + b) * DD;
        }
        float4 v = *(const float4*)(src + k);
        bf16* dh = y ? g_kvin_hi : g_qin_hi;
        bf16* dl = y ? g_kvin_lo : g_qin_lo;
        *(uint2*)&dh[e] = make_uint2(pk_hi(v.x, v.y), pk_hi(v.z, v.w));
        *(uint2*)&dl[e] = make_uint2(pk_lo(v.x, v.y), pk_lo(v.z, v.w));
    } else {
        if (e >= (size_t)2048 * DD) return;
        const int r = (int)(e >> 9);
        const int k = (int)(e & 511);
        const float* src;
        if (r < 512)       src = Wq  + (size_t)r * DD;
        else if (r < 1536) src = Wkv + (size_t)(r - 512) * DD;
        else               src = Wo  + (size_t)(r - 1536) * DD;
        float4 v = *(const float4*)(src + k);
        *(uint2*)&g_w_hi[e] = make_uint2(pk_hi(v.x, v.y), pk_hi(v.z, v.w));
        *(uint2*)&g_w_lo[e] = make_uint2(pk_lo(v.x, v.y), pk_lo(v.z, v.w));
    }
}

// ---------------------------------------------------------------------------
// GEMM core — 128m x 64n, 256 threads / 8 warps, K=512, 3-MMA split,
// term-major ordering (unchanged from R11; R11 proved ordering perf-neutral).
// ---------------------------------------------------------------------------
__device__ __forceinline__ void gemm_core(
    const bf16* __restrict__ a_hi, const bf16* __restrict__ a_lo,
    const bf16* __restrict__ b_hi, const bf16* __restrict__ b_lo,
    const float* __restrict__ bias, float* __restrict__ dout,
    int mode, int m0, int n0, char* smc)
{
    const uint32_t smb = smem_to_u32(smc);
    const int tid = threadIdx.x, w = tid >> 5, lane = tid & 31;
    const int wm = w >> 1, wn = w & 1;

    const int ra  = tid >> 1;
    const int ca0 = (tid & 1) * 4;
    const int rb  = tid >> 2;
    const int cb0 = (tid & 3) * 2;

    auto stage = [&](int kc) {
        const uint32_t sb = smb + (kc & 1) * 49152;
        const bf16* As_h = a_hi + (size_t)(m0 + ra) * DD + kc * 64 + ca0 * 8;
        const bf16* As_l = a_lo + (size_t)(m0 + ra) * DD + kc * 64 + ca0 * 8;
#pragma unroll
        for (int i = 0; i < 4; i++) {
            uint32_t so = SWZ((uint32_t)(ra * 128 + (ca0 + i) * 16));
            cp16(sb + so,         As_h + i * 8, 16);
            cp16(sb + 16384 + so, As_l + i * 8, 16);
        }
        const bf16* Bs_h = b_hi + (size_t)(n0 + rb) * DD + kc * 64 + cb0 * 8;
        const bf16* Bs_l = b_lo + (size_t)(n0 + rb) * DD + kc * 64 + cb0 * 8;
#pragma unroll
        for (int i = 0; i < 2; i++) {
            uint32_t so = SWZ((uint32_t)(rb * 128 + (cb0 + i) * 16));
            cp16(sb + 32768 + so, Bs_h + i * 8, 16);
            cp16(sb + 40960 + so, Bs_l + i * 8, 16);
        }
        CP_COMMIT();
    };

    float acc[2][4][4];
#pragma unroll
    for (int a = 0; a < 2; a++)
#pragma unroll
        for (int c = 0; c < 4; c++)
#pragma unroll
            for (int d = 0; d < 4; d++) acc[a][c][d] = 0.f;

    const int rr  = (lane & 7) + ((lane >> 3) & 1) * 8;
    const int kk8 = (lane >> 4) * 8;

    stage(0);
    for (int c = 0; c < 8; c++) {
        CP_WAIT0();
        __syncthreads();
        if (c < 7) stage(c + 1);
        const uint32_t sb = smb + (c & 1) * 49152;
#pragma unroll
        for (int kd = 0; kd < 4; kd++) {
            const uint32_t ko = (uint32_t)((kd * 16 + kk8) * 2);
            uint32_t ah[2][4], al[2][4], bh[2][4], bl[2][4];
#pragma unroll
            for (int mt = 0; mt < 2; mt++) {
                uint32_t off = SWZ((uint32_t)((wm * 32 + mt * 16 + rr) * 128) + ko);
                ldmat4(ah[mt], sb + off);
                ldmat4(al[mt], sb + 16384 + off);
            }
#pragma unroll
            for (int p = 0; p < 2; p++) {
                uint32_t off = SWZ((uint32_t)((wn * 32 + p * 16 + rr) * 128) + ko);
                ldmat4(bh[p], sb + 32768 + off);
                ldmat4(bl[p], sb + 40960 + off);
            }
#pragma unroll
            for (int mt = 0; mt < 2; mt++)
#pragma unroll
                for (int nt = 0; nt < 4; nt++)
                    mma16816(acc[mt][nt], ah[mt],
                             bh[nt >> 1][nt & 1], bh[nt >> 1][2 + (nt & 1)]);
#pragma unroll
            for (int mt = 0; mt < 2; mt++)
#pragma unroll
                for (int nt = 0; nt < 4; nt++)
                    mma16816(acc[mt][nt], ah[mt],
                             bl[nt >> 1][nt & 1], bl[nt >> 1][2 + (nt & 1)]);
#pragma unroll
            for (int mt = 0; mt < 2; mt++)
#pragma unroll
                for (int nt = 0; nt < 4; nt++)
                    mma16816(acc[mt][nt], al[mt],
                             bh[nt >> 1][nt & 1], bh[nt >> 1][2 + (nt & 1)]);
        }
    }

    const int lq = lane >> 2, lc = (lane & 3) * 2;
#pragma unroll
    for (int mt = 0; mt < 2; mt++) {
#pragma unroll
        for (int nt = 0; nt < 4; nt++) {
            const int col = n0 + wn * 32 + nt * 8 + lc;
            const float b0 = bias[col], b1 = bias[col + 1];
#pragma unroll
            for (int hrow = 0; hrow < 2; hrow++) {
                const int m = m0 + wm * 32 + mt * 16 + lq + hrow * 8;
                float v0 = acc[mt][nt][hrow * 2 + 0] + b0;
                float v1 = acc[mt][nt][hrow * 2 + 1] + b1;
                if (mode == 0) {
                    v0 *= SCALE_; v1 *= SCALE_;
                    *(uint32_t*)&g_q_hi[(size_t)m * DD + col] = pk_hi(v0, v1);
                    *(uint32_t*)&g_q_lo[(size_t)m * DD + col] = pk_lo(v0, v1);
                } else if (mode == 1) {
                    if (col < DD) {
                        *(uint32_t*)&g_k_hi[(size_t)m * DD + col] = pk_hi(v0, v1);
                        *(uint32_t*)&g_k_lo[(size_t)m * DD + col] = pk_lo(v0, v1);
                    } else {
                        *(uint32_t*)&g_v_hi[(size_t)m * DD + col - DD] = pk_hi(v0, v1);
                        *(uint32_t*)&g_v_lo[(size_t)m * DD + col - DD] = pk_lo(v0, v1);
                    }
                } else {
                    const int tt = m >> 3, rbb = m & 7;
                    if (tt < TQ_ - SS) {
                        *(float2*)&dout[(size_t)m * DD + col] = make_float2(v0, v1);
                    } else if (tt < TQ_ - 1) {
                        v0 = fminf(10.f, fmaxf(-10.f, v0));
                        v1 = fminf(10.f, fmaxf(-10.f, v1));
                        *(float2*)&dout[(size_t)(TQ_ - SS) * BB * DD +
                                        ((size_t)(tt - (TQ_ - SS)) * BB + rbb) * DD + col] =
                            make_float2(v0, v1);
                    }
                }
            }
        }
    }
}

// LAUNCH 3: Q-proj (z=0) + KV-proj (z=1) merged.
__global__ void __launch_bounds__(256, 2) qkv_gemm(
    const bf16* __restrict__ qinh, const bf16* __restrict__ qinl,
    const bf16* __restrict__ kvinh, const bf16* __restrict__ kvinl,
    const bf16* __restrict__ wh, const bf16* __restrict__ wl,
    const float* __restrict__ bq, const float* __restrict__ bkv)
{
    extern __shared__ char smc[];
    const int z = blockIdx.z;
    if (z == 0 && blockIdx.x >= 8) return;
    const bf16* a_hi = z ? kvinh : qinh;
    const bf16* a_lo = z ? kvinl : qinl;
    const bf16* b_hi = wh + (z ? (size_t)512 * DD : 0);
    const bf16* b_lo = wl + (z ? (size_t)512 * DD : 0);
    const float* bias = z ? bkv : bq;
    gemm_core(a_hi, a_lo, b_hi, b_lo, bias, nullptr, z,
              blockIdx.y * 128, blockIdx.x * 64, smc);
}

// LAUNCH 5: O projection.
__global__ void __launch_bounds__(256, 2) o_gemm(
    const bf16* __restrict__ ah, const bf16* __restrict__ al,
    const bf16* __restrict__ bh, const bf16* __restrict__ bl,
    const float* __restrict__ bias, float* __restrict__ dout)
{
    extern __shared__ char smc[];
    gemm_core(ah, al, bh, bl, bias, dout, 2, blockIdx.y * 128, blockIdx.x * 64, smc);
}

// ---------------------------------------------------------------------------
// LAUNCH 4: HMMA flash attention — R10 structure with three register cuts:
//  (1) S-loop K fragments loaded per-p (8 regs, not 32 — reverts R11 preload)
//  (2) Q fragments re-ldmatrix'd from persistent smem per kd (frees 32 regs)
//  (3) P packed lazily per-kd inside PV (frees 32-reg pack arrays)
// -> fits __launch_bounds__(128, 4): 4 CTAs/SM, 16 warps/SM.
// Per-accumulator arithmetic order unchanged -> bit-identical output.
// ---------------------------------------------------------------------------
__global__ void __launch_bounds__(128, 4) attn_kernel(const int* __restrict__ lengths)
{
    extern __shared__ char smc[];
    const uint32_t smb = smem_to_u32(smc);
    const uint32_t Qh = smb, Ql = smb + 8192, Kh = smb + 16384, Kl = smb + 24576;
    const uint32_t Vh = smb + 32768, Vl = smb + 40960;

    const int tid = threadIdx.x, w = tid >> 5, lane = tid & 31;
    const int b = blockIdx.y >> 3, h = blockIdx.y & 7;
    const int q0 = blockIdx.x * 64;

    int maxlen = 0;
#pragma unroll
    for (int i = 0; i < BB; i++) maxlen = max(maxlen, lengths[i]);
    const int klen = lengths[b] + MMEM + (TQ_ - maxlen - SS);
    const int kend = min(TK_, (klen + 63) & ~63);

    const int ldrow = tid >> 1;
    const int ldc0  = (tid & 1) * 4;

    auto stageK = [&](int k0c) {
        const int tk = k0c + ldrow;
        const int bytes = (tk < TK_) ? 16 : 0;
        const size_t go = ((size_t)tk * BB + b) * DD + h * DHH + ldc0 * 8;
#pragma unroll
        for (int i = 0; i < 4; i++) {
            uint32_t so = SWZ((uint32_t)(ldrow * 128 + (ldc0 + i) * 16));
            cp16(Kh + so, g_k_hi + go + i * 8, bytes);
            cp16(Kl + so, g_k_lo + go + i * 8, bytes);
        }
        CP_COMMIT();
    };
    auto stageV = [&](int k0c) {
        const int tk = k0c + ldrow;
        const int bytes = (tk < TK_) ? 16 : 0;
        const size_t go = ((size_t)tk * BB + b) * DD + h * DHH + ldc0 * 8;
#pragma unroll
        for (int i = 0; i < 4; i++) {
            uint32_t so = SWZ((uint32_t)(ldrow * 128 + (ldc0 + i) * 16));
            cp16(Vh + so, g_v_hi + go + i * 8, bytes);
            cp16(Vl + so, g_v_lo + go + i * 8, bytes);
        }
        CP_COMMIT();
    };

    // stage Q (group 1), stage K(0) (group 2); WAIT1 drains Q only
    {
        const int q = q0 + ldrow;
        const int bytes = (q < TQ_) ? 16 : 0;
        const size_t go = ((size_t)q * BB + b) * DD + h * DHH + ldc0 * 8;
#pragma unroll
        for (int i = 0; i < 4; i++) {
            uint32_t so = SWZ((uint32_t)(ldrow * 128 + (ldc0 + i) * 16));
            cp16(Qh + so, g_q_hi + go + i * 8, bytes);
            cp16(Ql + so, g_q_lo + go + i * 8, bytes);
        }
        CP_COMMIT();
    }
    stageK(0);
    CP_WAIT1();
    __syncthreads();

    const int rr  = (lane & 7) + ((lane >> 3) & 1) * 8;
    const int kk8 = (lane >> 4) * 8;

    float o[8][4];
#pragma unroll
    for (int j = 0; j < 8; j++)
#pragma unroll
        for (int d = 0; d < 4; d++) o[j][d] = 0.f;
    float mr0 = neg_inf_f(), mr1 = neg_inf_f(), lr0 = 0.f, lr1 = 0.f;

    const int lq = lane >> 2, lc = (lane & 3) * 2;
    const int qr0 = q0 + 16 * w + lq, qr1 = qr0 + 8;

    for (int k0 = 0; k0 < kend; k0 += 64) {
        CP_WAIT0();
        __syncthreads();
        stageV(k0);

        // ---- mask prefetch (hidden behind S MMAs) ----
        uint32_t mAp[4], mBp[4];
#pragma unroll
        for (int j = 0; j < 8; j++) {
            const int kc = k0 + 8 * j + lc;
            uint32_t a = 0x0101u, bm = 0x0101u;
            if (kc < TK_ - 1) {
                if (qr0 < TQ_) a  = *(const unsigned short*)&g_mask[(size_t)qr0 * TK_ + kc];
                if (qr1 < TQ_) bm = *(const unsigned short*)&g_mask[(size_t)qr1 * TK_ + kc];
            }
            if (j & 1) { mAp[j >> 1] |= a << 16; mBp[j >> 1] |= bm << 16; }
            else       { mAp[j >> 1]  = a;       mBp[j >> 1]  = bm;       }
        }

        // ---- S = Q K^T (Q frags re-loaded from persistent smem per kd) ----
        float s[8][4];
#pragma unroll
        for (int j = 0; j < 8; j++)
#pragma unroll
            for (int d = 0; d < 4; d++) s[j][d] = 0.f;

#pragma unroll
        for (int kd = 0; kd < 4; kd++) {
            const uint32_t ko = (uint32_t)((kd * 16 + kk8) * 2);
            uint32_t qhf[4], qlf[4];
            {
                uint32_t qoff = SWZ((uint32_t)((16 * w + rr) * 128) + ko);
                ldmat4(qhf, Qh + qoff);
                ldmat4(qlf, Ql + qoff);
            }
#pragma unroll
            for (int p = 0; p < 4; p++) {
                uint32_t kh4[4], kl4[4];
                uint32_t off = SWZ((uint32_t)((p * 16 + rr) * 128) + ko);
                ldmat4(kh4, Kh + off);
                ldmat4(kl4, Kl + off);
                mma16816(s[2 * p],     qhf, kh4[0], kh4[2]);
                mma16816(s[2 * p],     qhf, kl4[0], kl4[2]);
                mma16816(s[2 * p],     qlf, kh4[0], kh4[2]);
                mma16816(s[2 * p + 1], qhf, kh4[1], kh4[3]);
                mma16816(s[2 * p + 1], qhf, kl4[1], kl4[3]);
                mma16816(s[2 * p + 1], qlf, kh4[1], kh4[3]);
            }
        }

        CP_WAIT0();          // V(k0) ready
        __syncthreads();     // all warps past S: K buffer free

        // ---- mask apply ----
#pragma unroll
        for (int j = 0; j < 8; j++) {
            const int kc = k0 + 8 * j + lc;
            const uint32_t av = (mAp[j >> 1] >> ((j & 1) * 16));
            const uint32_t bv = (mBp[j >> 1] >> ((j & 1) * 16));
            const unsigned char mAx = av & 0xFF, mAy = (av >> 8) & 0xFF;
            const unsigned char mBx = bv & 0xFF, mBy = (bv >> 8) & 0xFF;
            if (kc >= TK_) {
                s[j][0] = s[j][2] = neg_inf_f();
            } else {
                if (mAx || kc >= klen) s[j][0] = NEGINF_;
                if (mBx || kc >= klen) s[j][2] = NEGINF_;
            }
            if (kc + 1 >= TK_) {
                s[j][1] = s[j][3] = neg_inf_f();
            } else {
                if (mAy || kc + 1 >= klen) s[j][1] = NEGINF_;
                if (mBy || kc + 1 >= klen) s[j][3] = NEGINF_;
            }
        }

        // ---- online softmax ----
        float mx0 = NEGINF_, mx1 = NEGINF_;
#pragma unroll
        for (int j = 0; j < 8; j++) {
            mx0 = fmaxf(mx0, fmaxf(s[j][0], s[j][1]));
            mx1 = fmaxf(mx1, fmaxf(s[j][2], s[j][3]));
        }
        mx0 = fmaxf(mx0, __shfl_xor_sync(0xffffffffu, mx0, 1));
        mx0 = fmaxf(mx0, __shfl_xor_sync(0xffffffffu, mx0, 2));
        mx1 = fmaxf(mx1, __shfl_xor_sync(0xffffffffu, mx1, 1));
        mx1 = fmaxf(mx1, __shfl_xor_sync(0xffffffffu, mx1, 2));
        const float mn0 = fmaxf(mr0, mx0), mn1 = fmaxf(mr1, mx1);
        const float a0 = __expf(mr0 - mn0), a1 = __expf(mr1 - mn1);
        float su0 = 0.f, su1 = 0.f;
#pragma unroll
        for (int j = 0; j < 8; j++) {
            s[j][0] = __expf(s[j][0] - mn0);
            s[j][1] = __expf(s[j][1] - mn0);
            s[j][2] = __expf(s[j][2] - mn1);
            s[j][3] = __expf(s[j][3] - mn1);
            su0 += s[j][0] + s[j][1];
            su1 += s[j][2] + s[j][3];
        }
        su0 += __shfl_xor_sync(0xffffffffu, su0, 1);
        su0 += __shfl_xor_sync(0xffffffffu, su0, 2);
        su1 += __shfl_xor_sync(0xffffffffu, su1, 1);
        su1 += __shfl_xor_sync(0xffffffffu, su1, 2);
        lr0 = lr0 * a0 + su0;  mr0 = mn0;
        lr1 = lr1 * a1 + su1;  mr1 = mn1;
#pragma unroll
        for (int j = 0; j < 8; j++) {
            o[j][0] *= a0; o[j][1] *= a0;
            o[j][2] *= a1; o[j][3] *= a1;
        }

        if (k0 + 64 < kend) stageK(k0 + 64);   // async K load overlaps PV MMAs

        // ---- O += P V (P packed lazily per kd from s; same values/order) ----
#pragma unroll
        for (int kd = 0; kd < 4; kd++) {
            const uint32_t pah[4] = { pk_hi(s[2 * kd][0],     s[2 * kd][1]),
                                      pk_hi(s[2 * kd][2],     s[2 * kd][3]),
                                      pk_hi(s[2 * kd + 1][0], s[2 * kd + 1][1]),
                                      pk_hi(s[2 * kd + 1][2], s[2 * kd + 1][3]) };
            const uint32_t pal[4] = { pk_lo(s[2 * kd][0],     s[2 * kd][1]),
                                      pk_lo(s[2 * kd][2],     s[2 * kd][3]),
                                      pk_lo(s[2 * kd + 1][0], s[2 * kd + 1][1]),
                                      pk_lo(s[2 * kd + 1][2], s[2 * kd + 1][3]) };
#pragma unroll
            for (int p = 0; p < 4; p++) {
                uint32_t vh4[4], vl4[4];
                uint32_t off = SWZ((uint32_t)((kd * 16 + rr) * 128 + (p * 16 + kk8) * 2));
                ldmat4t(vh4, Vh + off);
                ldmat4t(vl4, Vl + off);
                mma16816(o[2 * p],     pah, vh4[0], vh4[1]);
                mma16816(o[2 * p],     pah, vl4[0], vl4[1]);
                mma16816(o[2 * p],     pal, vh4[0], vh4[1]);
                mma16816(o[2 * p + 1], pah, vh4[2], vh4[3]);
                mma16816(o[2 * p + 1], pah, vl4[2], vl4[3]);
                mma16816(o[2 * p + 1], pal, vh4[2], vh4[3]);
            }
        }
    }

    // ---- epilogue ----
    const float inv0 = 1.f / lr0, inv1 = 1.f / lr1;
#pragma unroll
    for (int j = 0; j < 8; j++) {
        const int dh = h * DHH + 8 * j + lc;
        if (qr0 < TQ_) {
            const float v0 = o[j][0] * inv0, v1 = o[j][1] * inv0;
            const size_t ad = ((size_t)qr0 * BB + b) * DD + dh;
            *(uint32_t*)&g_a_hi[ad] = pk_hi(v0, v1);
            *(uint32_t*)&g_a_lo[ad] = pk_lo(v0, v1);
        }
        if (qr1 < TQ_) {
            const float v0 = o[j][2] * inv1, v1 = o[j][3] * inv1;
            const size_t ad = ((size_t)qr1 * BB + b) * DD + dh;
            *(uint32_t*)&g_a_hi[ad] = pk_hi(v0, v1);
            *(uint32_t*)&g_a_lo[ad] = pk_lo(v0, v1);
        }
    }
}

// ---------------------------------------------------------------------------
extern "C" void kernel_launch(void* const* d_in, const int* in_sizes, int n_in,
                              void* d_out, int out_size)
{
    const float* utt = (const float*)d_in[0];
    const float* rc  = (const float*)d_in[1];
    const float* smr = (const float*)d_in[2];
    const float* mem = (const float*)d_in[3];
    const float* Wq  = (const float*)d_in[4];
    const float* bq  = (const float*)d_in[5];
    const float* Wkv = (const float*)d_in[6];
    const float* bkv = (const float*)d_in[7];
    const float* Wo  = (const float*)d_in[8];
    const float* bo  = (const float*)d_in[9];
    const int*   len = (const int*)d_in[10];
    const unsigned char* am = (const unsigned char*)d_in[11];
    float* out = (float*)d_out;

    const int gemm_smem = 98304;
    const int attn_smem = 49152;
    cudaFuncSetAttribute(qkv_gemm, cudaFuncAttributeMaxDynamicSharedMemorySize, gemm_smem);
    cudaFuncSetAttribute(o_gemm,   cudaFuncAttributeMaxDynamicSharedMemorySize, gemm_smem);
    cudaFuncSetAttribute(attn_kernel, cudaFuncAttributeMaxDynamicSharedMemorySize, attn_smem);

    bf16 *qinh, *qinl, *kvinh, *kvinl, *ah, *al, *wh, *wl;
    cudaGetSymbolAddress((void**)&qinh,  g_qin_hi);
    cudaGetSymbolAddress((void**)&qinl,  g_qin_lo);
    cudaGetSymbolAddress((void**)&kvinh, g_kvin_hi);
    cudaGetSymbolAddress((void**)&kvinl, g_kvin_lo);
    cudaGetSymbolAddress((void**)&ah,    g_a_hi);
    cudaGetSymbolAddress((void**)&al,    g_a_lo);
    cudaGetSymbolAddress((void**)&wh,    g_w_hi);
    cudaGetSymbolAddress((void**)&wl,    g_w_lo);

    mask_kernel<<<(TQ_ * TK_ + 255) / 256, 256>>>(am);
    convert_all_kernel<<<dim3((TQ_ * BB * DD / 4 + 255) / 256, 3), 256>>>(
        utt, rc, smr, mem, Wq, Wkv, Wo);
    qkv_gemm<<<dim3(16, 69, 2), 256, gemm_smem>>>(qinh, qinl, kvinh, kvinl, wh, wl, bq, bkv);
    attn_kernel<<<dim3(18, 64), 128, attn_smem>>>(len);
    o_gemm<<<dim3(8, 69), 256, gemm_smem>>>(ah, al, wh + (size_t)1536 * DD,
                                            wl + (size_t)1536 * DD, bo, out);
}

// round 13
// speedup vs baseline: 1.5579x; 1.0047x over previous
#include <cuda_runtime.h>
#include <cuda_bf16.h>
#include <cstdint>

#define TT 1024
#define RR 64
#define SS 16
#define MMEM 16
#define BB 8
#define DD 512
#define HH 8
#define DHH 64
#define TQ_ 1104
#define TK_ 1104
// SCALE * log2(e): scores produced directly in base-2 domain
#define SCALE2_ 0.18033688011112042591f
// -1e8 * log2(e): finite mask value in base-2 domain (matches reference exp(-1e8) semantics)
#define NEGINF2_ (-1.4426950408889634e8f)

typedef __nv_bfloat16 bf16;

// ---------------- scratch (device globals; allocation-free rule) ----------------
__device__ bf16 g_qin_hi [(size_t)TQ_ * BB * DD];
__device__ bf16 g_qin_lo [(size_t)TQ_ * BB * DD];
__device__ bf16 g_kvin_hi[(size_t)TK_ * BB * DD];
__device__ bf16 g_kvin_lo[(size_t)TK_ * BB * DD];
__device__ bf16 g_w_hi[(size_t)2048 * DD];   // Wq | Wkv | Wo rows
__device__ bf16 g_w_lo[(size_t)2048 * DD];
__device__ bf16 g_q_hi[(size_t)TQ_ * BB * DD];
__device__ bf16 g_q_lo[(size_t)TQ_ * BB * DD];
__device__ bf16 g_k_hi[(size_t)TK_ * BB * DD];
__device__ bf16 g_k_lo[(size_t)TK_ * BB * DD];
__device__ bf16 g_v_hi[(size_t)TK_ * BB * DD];
__device__ bf16 g_v_lo[(size_t)TK_ * BB * DD];
__device__ bf16 g_a_hi[(size_t)TQ_ * BB * DD];
__device__ bf16 g_a_lo[(size_t)TQ_ * BB * DD];
__device__ unsigned char g_mask[(size_t)TQ_ * TK_];

__device__ __forceinline__ float neg_inf_f() { return __int_as_float(0xff800000); }
__device__ __forceinline__ float ex2f(float x) {
    float r; asm("ex2.approx.f32 %0, %1;" : "=f"(r) : "f"(x)); return r;
}

// ---------------- low-level helpers (sm_80-era only; no 'a' features) ----------------
__device__ __forceinline__ uint32_t smem_to_u32(const void* p) {
    uint32_t a;
    asm("{ .reg .u64 t; cvta.to.shared.u64 t, %1; cvt.u32.u64 %0, t; }" : "=r"(a) : "l"(p));
    return a;
}
__device__ __forceinline__ void ldmat4(uint32_t r[4], uint32_t addr) {
    asm volatile("ldmatrix.sync.aligned.m8n8.x4.shared.b16 {%0,%1,%2,%3}, [%4];"
                 : "=r"(r[0]), "=r"(r[1]), "=r"(r[2]), "=r"(r[3]) : "r"(addr));
}
__device__ __forceinline__ void ldmat4t(uint32_t r[4], uint32_t addr) {
    asm volatile("ldmatrix.sync.aligned.m8n8.x4.trans.shared.b16 {%0,%1,%2,%3}, [%4];"
                 : "=r"(r[0]), "=r"(r[1]), "=r"(r[2]), "=r"(r[3]) : "r"(addr));
}
__device__ __forceinline__ void mma16816(float d[4], const uint32_t a[4],
                                         uint32_t b0, uint32_t b1) {
    asm volatile("mma.sync.aligned.m16n8k16.row.col.f32.bf16.bf16.f32 "
                 "{%0,%1,%2,%3}, {%4,%5,%6,%7}, {%8,%9}, {%0,%1,%2,%3};"
                 : "+f"(d[0]), "+f"(d[1]), "+f"(d[2]), "+f"(d[3])
                 : "r"(a[0]), "r"(a[1]), "r"(a[2]), "r"(a[3]), "r"(b0), "r"(b1));
}
__device__ __forceinline__ void cp16(uint32_t dst, const void* src, int bytes) {
    asm volatile("cp.async.cg.shared.global [%0], [%1], 16, %2;"
                 :: "r"(dst), "l"(src), "r"(bytes));
}
#define CP_COMMIT() asm volatile("cp.async.commit_group;" ::: "memory")
#define CP_WAIT0()  asm volatile("cp.async.wait_group 0;" ::: "memory")
#define CP_WAIT1()  asm volatile("cp.async.wait_group 1;" ::: "memory")

#define SWZ(o) ((o) ^ (((o) >> 3) & 0x70))

// packed bf16x2 conversions: cvt.rn.bf16x2.f32 rounds RN -> bit-identical to
// paired __float2bfloat16; lo terms are exact fp32 residuals then RN.
__device__ __forceinline__ uint32_t pk_hi(float a, float b) {
    uint32_t r;
    asm("cvt.rn.bf16x2.f32 %0, %1, %2;" : "=r"(r) : "f"(b), "f"(a));
    return r;
}
__device__ __forceinline__ uint32_t pk_lo(float a, float b) {
    const uint32_t h = pk_hi(a, b);
    const float la = a - __uint_as_float(h << 16);
    const float lb = b - __uint_as_float(h & 0xffff0000u);
    return pk_hi(la, lb);
}

// ---------------------------------------------------------------------------
// LAUNCH 1: mask detect + canonicalize (unchanged).
// ---------------------------------------------------------------------------
__global__ void __launch_bounds__(256) mask_kernel(const unsigned char* __restrict__ buf)
{
    __shared__ int s_large, s_nzoff;
    if (threadIdx.x == 0) { s_large = 0; s_nzoff = 0; }
    __syncthreads();
    int l = 0, z = 0;
    {
        const int base = threadIdx.x * 16;
#pragma unroll
        for (int j = 0; j < 16; j++) {
            unsigned char v = buf[base + j];
            if (v > 1) l = 1;
            if (((base + j) & 3) && v != 0) z = 1;
        }
    }
    if (l) atomicOr(&s_large, 1);
    if (z) atomicOr(&s_nzoff, 1);
    __syncthreads();
    const int mode = s_large ? 2 : (s_nzoff ? 0 : 1);

    const int idx = blockIdx.x * blockDim.x + threadIdx.x;
    if (idx >= TQ_ * TK_) return;
    unsigned char m;
    if (mode == 0)      m = buf[idx] ? 1 : 0;
    else if (mode == 1) m = (((const int*)buf)[idx] != 0) ? 1 : 0;
    else                m = (((const float*)buf)[idx] != 0.f) ? 1 : 0;
    g_mask[idx] = m;
}

// ---------------------------------------------------------------------------
// LAUNCH 2: all fp32 -> split-bf16 conversions (packed cvt).
// ---------------------------------------------------------------------------
__global__ void __launch_bounds__(256) convert_all_kernel(
    const float* __restrict__ utt, const float* __restrict__ rc,
    const float* __restrict__ smr, const float* __restrict__ mem,
    const float* __restrict__ Wq, const float* __restrict__ Wkv,
    const float* __restrict__ Wo)
{
    const int y = blockIdx.y;
    const size_t e = ((size_t)blockIdx.x * blockDim.x + threadIdx.x) * 4;
    if (y < 2) {
        if (e >= (size_t)TQ_ * BB * DD) return;
        const int r = (int)(e >> 9);
        const int k = (int)(e & 511);
        const int t = r >> 3, b = r & 7;
        const float* src;
        if (y == 0) {
            if (t < RR)           src = rc  + ((size_t)t * BB + b) * DD;
            else if (t < RR + TT) src = utt + ((size_t)(t - RR) * BB + b) * DD;
            else                  src = smr + ((size_t)(t - RR - TT) * BB + b) * DD;
        } else {
            if (t < MMEM)           src = mem + ((size_t)t * BB + b) * DD;
            else if (t < MMEM + RR) src = rc  + ((size_t)(t - MMEM) * BB + b) * DD;
            else                    src = utt + ((size_t)(t - MMEM - RR) * BB + b) * DD;
        }
        float4 v = *(const float4*)(src + k);
        bf16* dh = y ? g_kvin_hi : g_qin_hi;
        bf16* dl = y ? g_kvin_lo : g_qin_lo;
        *(uint2*)&dh[e] = make_uint2(pk_hi(v.x, v.y), pk_hi(v.z, v.w));
        *(uint2*)&dl[e] = make_uint2(pk_lo(v.x, v.y), pk_lo(v.z, v.w));
    } else {
        if (e >= (size_t)2048 * DD) return;
        const int r = (int)(e >> 9);
        const int k = (int)(e & 511);
        const float* src;
        if (r < 512)       src = Wq  + (size_t)r * DD;
        else if (r < 1536) src = Wkv + (size_t)(r - 512) * DD;
        else               src = Wo  + (size_t)(r - 1536) * DD;
        float4 v = *(const float4*)(src + k);
        *(uint2*)&g_w_hi[e] = make_uint2(pk_hi(v.x, v.y), pk_hi(v.z, v.w));
        *(uint2*)&g_w_lo[e] = make_uint2(pk_lo(v.x, v.y), pk_lo(v.z, v.w));
    }
}

// ---------------------------------------------------------------------------
// GEMM core — 128m x 64n, 256 threads / 8 warps, K=512, 3-MMA split,
// term-major ordering. Mode 0 now scales by SCALE2_ (SCALE * log2e) so the
// attention consumes base-2-domain scores.
// ---------------------------------------------------------------------------
__device__ __forceinline__ void gemm_core(
    const bf16* __restrict__ a_hi, const bf16* __restrict__ a_lo,
    const bf16* __restrict__ b_hi, const bf16* __restrict__ b_lo,
    const float* __restrict__ bias, float* __restrict__ dout,
    int mode, int m0, int n0, char* smc)
{
    const uint32_t smb = smem_to_u32(smc);
    const int tid = threadIdx.x, w = tid >> 5, lane = tid & 31;
    const int wm = w >> 1, wn = w & 1;

    const int ra  = tid >> 1;
    const int ca0 = (tid & 1) * 4;
    const int rb  = tid >> 2;
    const int cb0 = (tid & 3) * 2;

    auto stage = [&](int kc) {
        const uint32_t sb = smb + (kc & 1) * 49152;
        const bf16* As_h = a_hi + (size_t)(m0 + ra) * DD + kc * 64 + ca0 * 8;
        const bf16* As_l = a_lo + (size_t)(m0 + ra) * DD + kc * 64 + ca0 * 8;
#pragma unroll
        for (int i = 0; i < 4; i++) {
            uint32_t so = SWZ((uint32_t)(ra * 128 + (ca0 + i) * 16));
            cp16(sb + so,         As_h + i * 8, 16);
            cp16(sb + 16384 + so, As_l + i * 8, 16);
        }
        const bf16* Bs_h = b_hi + (size_t)(n0 + rb) * DD + kc * 64 + cb0 * 8;
        const bf16* Bs_l = b_lo + (size_t)(n0 + rb) * DD + kc * 64 + cb0 * 8;
#pragma unroll
        for (int i = 0; i < 2; i++) {
            uint32_t so = SWZ((uint32_t)(rb * 128 + (cb0 + i) * 16));
            cp16(sb + 32768 + so, Bs_h + i * 8, 16);
            cp16(sb + 40960 + so, Bs_l + i * 8, 16);
        }
        CP_COMMIT();
    };

    float acc[2][4][4];
#pragma unroll
    for (int a = 0; a < 2; a++)
#pragma unroll
        for (int c = 0; c < 4; c++)
#pragma unroll
            for (int d = 0; d < 4; d++) acc[a][c][d] = 0.f;

    const int rr  = (lane & 7) + ((lane >> 3) & 1) * 8;
    const int kk8 = (lane >> 4) * 8;

    stage(0);
    for (int c = 0; c < 8; c++) {
        CP_WAIT0();
        __syncthreads();
        if (c < 7) stage(c + 1);
        const uint32_t sb = smb + (c & 1) * 49152;
#pragma unroll
        for (int kd = 0; kd < 4; kd++) {
            const uint32_t ko = (uint32_t)((kd * 16 + kk8) * 2);
            uint32_t ah[2][4], al[2][4], bh[2][4], bl[2][4];
#pragma unroll
            for (int mt = 0; mt < 2; mt++) {
                uint32_t off = SWZ((uint32_t)((wm * 32 + mt * 16 + rr) * 128) + ko);
                ldmat4(ah[mt], sb + off);
                ldmat4(al[mt], sb + 16384 + off);
            }
#pragma unroll
            for (int p = 0; p < 2; p++) {
                uint32_t off = SWZ((uint32_t)((wn * 32 + p * 16 + rr) * 128) + ko);
                ldmat4(bh[p], sb + 32768 + off);
                ldmat4(bl[p], sb + 40960 + off);
            }
#pragma unroll
            for (int mt = 0; mt < 2; mt++)
#pragma unroll
                for (int nt = 0; nt < 4; nt++)
                    mma16816(acc[mt][nt], ah[mt],
                             bh[nt >> 1][nt & 1], bh[nt >> 1][2 + (nt & 1)]);
#pragma unroll
            for (int mt = 0; mt < 2; mt++)
#pragma unroll
                for (int nt = 0; nt < 4; nt++)
                    mma16816(acc[mt][nt], ah[mt],
                             bl[nt >> 1][nt & 1], bl[nt >> 1][2 + (nt & 1)]);
#pragma unroll
            for (int mt = 0; mt < 2; mt++)
#pragma unroll
                for (int nt = 0; nt < 4; nt++)
                    mma16816(acc[mt][nt], al[mt],
                             bh[nt >> 1][nt & 1], bh[nt >> 1][2 + (nt & 1)]);
        }
    }

    const int lq = lane >> 2, lc = (lane & 3) * 2;
#pragma unroll
    for (int mt = 0; mt < 2; mt++) {
#pragma unroll
        for (int nt = 0; nt < 4; nt++) {
            const int col = n0 + wn * 32 + nt * 8 + lc;
            const float b0 = bias[col], b1 = bias[col + 1];
#pragma unroll
            for (int hrow = 0; hrow < 2; hrow++) {
                const int m = m0 + wm * 32 + mt * 16 + lq + hrow * 8;
                float v0 = acc[mt][nt][hrow * 2 + 0] + b0;
                float v1 = acc[mt][nt][hrow * 2 + 1] + b1;
                if (mode == 0) {
                    v0 *= SCALE2_; v1 *= SCALE2_;
                    *(uint32_t*)&g_q_hi[(size_t)m * DD + col] = pk_hi(v0, v1);
                    *(uint32_t*)&g_q_lo[(size_t)m * DD + col] = pk_lo(v0, v1);
                } else if (mode == 1) {
                    if (col < DD) {
                        *(uint32_t*)&g_k_hi[(size_t)m * DD + col] = pk_hi(v0, v1);
                        *(uint32_t*)&g_k_lo[(size_t)m * DD + col] = pk_lo(v0, v1);
                    } else {
                        *(uint32_t*)&g_v_hi[(size_t)m * DD + col - DD] = pk_hi(v0, v1);
                        *(uint32_t*)&g_v_lo[(size_t)m * DD + col - DD] = pk_lo(v0, v1);
                    }
                } else {
                    const int tt = m >> 3, rbb = m & 7;
                    if (tt < TQ_ - SS) {
                        *(float2*)&dout[(size_t)m * DD + col] = make_float2(v0, v1);
                    } else if (tt < TQ_ - 1) {
                        v0 = fminf(10.f, fmaxf(-10.f, v0));
                        v1 = fminf(10.f, fmaxf(-10.f, v1));
                        *(float2*)&dout[(size_t)(TQ_ - SS) * BB * DD +
                                        ((size_t)(tt - (TQ_ - SS)) * BB + rbb) * DD + col] =
                            make_float2(v0, v1);
                    }
                }
            }
        }
    }
}

// LAUNCH 3: Q-proj (z=0) + KV-proj (z=1) merged.
__global__ void __launch_bounds__(256, 2) qkv_gemm(
    const bf16* __restrict__ qinh, const bf16* __restrict__ qinl,
    const bf16* __restrict__ kvinh, const bf16* __restrict__ kvinl,
    const bf16* __restrict__ wh, const bf16* __restrict__ wl,
    const float* __restrict__ bq, const float* __restrict__ bkv)
{
    extern __shared__ char smc[];
    const int z = blockIdx.z;
    if (z == 0 && blockIdx.x >= 8) return;
    const bf16* a_hi = z ? kvinh : qinh;
    const bf16* a_lo = z ? kvinl : qinl;
    const bf16* b_hi = wh + (z ? (size_t)512 * DD : 0);
    const bf16* b_lo = wl + (z ? (size_t)512 * DD : 0);
    const float* bias = z ? bkv : bq;
    gemm_core(a_hi, a_lo, b_hi, b_lo, bias, nullptr, z,
              blockIdx.y * 128, blockIdx.x * 64, smc);
}

// LAUNCH 5: O projection.
__global__ void __launch_bounds__(256, 2) o_gemm(
    const bf16* __restrict__ ah, const bf16* __restrict__ al,
    const bf16* __restrict__ bh, const bf16* __restrict__ bl,
    const float* __restrict__ bias, float* __restrict__ dout)
{
    extern __shared__ char smc[];
    gemm_core(ah, al, bh, bl, bias, dout, 2, blockIdx.y * 128, blockIdx.x * 64, smc);
}

// ---------------------------------------------------------------------------
// LAUNCH 4: HMMA flash attention — R12 structure, softmax-phase cuts:
//  (1) base-2 domain: scores arrive pre-scaled by log2e -> ex2.approx direct
//  (2) per-lane l accumulation (alpha is quad-uniform); quad-sum in epilogue
//      -> removes 4 shuffles per tile
//  (3) packed cvt.rn.bf16x2 in P-pack and epilogue
// ---------------------------------------------------------------------------
__global__ void __launch_bounds__(128, 4) attn_kernel(const int* __restrict__ lengths)
{
    extern __shared__ char smc[];
    const uint32_t smb = smem_to_u32(smc);
    const uint32_t Qh = smb, Ql = smb + 8192, Kh = smb + 16384, Kl = smb + 24576;
    const uint32_t Vh = smb + 32768, Vl = smb + 40960;

    const int tid = threadIdx.x, w = tid >> 5, lane = tid & 31;
    const int b = blockIdx.y >> 3, h = blockIdx.y & 7;
    const int q0 = blockIdx.x * 64;

    int maxlen = 0;
#pragma unroll
    for (int i = 0; i < BB; i++) maxlen = max(maxlen, lengths[i]);
    const int klen = lengths[b] + MMEM + (TQ_ - maxlen - SS);
    const int kend = min(TK_, (klen + 63) & ~63);

    const int ldrow = tid >> 1;
    const int ldc0  = (tid & 1) * 4;

    auto stageK = [&](int k0c) {
        const int tk = k0c + ldrow;
        const int bytes = (tk < TK_) ? 16 : 0;
        const size_t go = ((size_t)tk * BB + b) * DD + h * DHH + ldc0 * 8;
#pragma unroll
        for (int i = 0; i < 4; i++) {
            uint32_t so = SWZ((uint32_t)(ldrow * 128 + (ldc0 + i) * 16));
            cp16(Kh + so, g_k_hi + go + i * 8, bytes);
            cp16(Kl + so, g_k_lo + go + i * 8, bytes);
        }
        CP_COMMIT();
    };
    auto stageV = [&](int k0c) {
        const int tk = k0c + ldrow;
        const int bytes = (tk < TK_) ? 16 : 0;
        const size_t go = ((size_t)tk * BB + b) * DD + h * DHH + ldc0 * 8;
#pragma unroll
        for (int i = 0; i < 4; i++) {
            uint32_t so = SWZ((uint32_t)(ldrow * 128 + (ldc0 + i) * 16));
            cp16(Vh + so, g_v_hi + go + i * 8, bytes);
            cp16(Vl + so, g_v_lo + go + i * 8, bytes);
        }
        CP_COMMIT();
    };

    // stage Q (group 1), stage K(0) (group 2); WAIT1 drains Q only
    {
        const int q = q0 + ldrow;
        const int bytes = (q < TQ_) ? 16 : 0;
        const size_t go = ((size_t)q * BB + b) * DD + h * DHH + ldc0 * 8;
#pragma unroll
        for (int i = 0; i < 4; i++) {
            uint32_t so = SWZ((uint32_t)(ldrow * 128 + (ldc0 + i) * 16));
            cp16(Qh + so, g_q_hi + go + i * 8, bytes);
            cp16(Ql + so, g_q_lo + go + i * 8, bytes);
        }
        CP_COMMIT();
    }
    stageK(0);
    CP_WAIT1();
    __syncthreads();

    const int rr  = (lane & 7) + ((lane >> 3) & 1) * 8;
    const int kk8 = (lane >> 4) * 8;

    float o[8][4];
#pragma unroll
    for (int j = 0; j < 8; j++)
#pragma unroll
        for (int d = 0; d < 4; d++) o[j][d] = 0.f;
    float mr0 = neg_inf_f(), mr1 = neg_inf_f(), lr0 = 0.f, lr1 = 0.f;  // lr per-lane

    const int lq = lane >> 2, lc = (lane & 3) * 2;
    const int qr0 = q0 + 16 * w + lq, qr1 = qr0 + 8;

    for (int k0 = 0; k0 < kend; k0 += 64) {
        CP_WAIT0();
        __syncthreads();
        stageV(k0);

        // ---- mask prefetch (hidden behind S MMAs) ----
        uint32_t mAp[4], mBp[4];
#pragma unroll
        for (int j = 0; j < 8; j++) {
            const int kc = k0 + 8 * j + lc;
            uint32_t a = 0x0101u, bm = 0x0101u;
            if (kc < TK_ - 1) {
                if (qr0 < TQ_) a  = *(const unsigned short*)&g_mask[(size_t)qr0 * TK_ + kc];
                if (qr1 < TQ_) bm = *(const unsigned short*)&g_mask[(size_t)qr1 * TK_ + kc];
            }
            if (j & 1) { mAp[j >> 1] |= a << 16; mBp[j >> 1] |= bm << 16; }
            else       { mAp[j >> 1]  = a;       mBp[j >> 1]  = bm;       }
        }

        // ---- S = Q K^T (scores already in base-2 domain) ----
        float s[8][4];
#pragma unroll
        for (int j = 0; j < 8; j++)
#pragma unroll
            for (int d = 0; d < 4; d++) s[j][d] = 0.f;

#pragma unroll
        for (int kd = 0; kd < 4; kd++) {
            const uint32_t ko = (uint32_t)((kd * 16 + kk8) * 2);
            uint32_t qhf[4], qlf[4];
            {
                uint32_t qoff = SWZ((uint32_t)((16 * w + rr) * 128) + ko);
                ldmat4(qhf, Qh + qoff);
                ldmat4(qlf, Ql + qoff);
            }
#pragma unroll
            for (int p = 0; p < 4; p++) {
                uint32_t kh4[4], kl4[4];
                uint32_t off = SWZ((uint32_t)((p * 16 + rr) * 128) + ko);
                ldmat4(kh4, Kh + off);
                ldmat4(kl4, Kl + off);
                mma16816(s[2 * p],     qhf, kh4[0], kh4[2]);
                mma16816(s[2 * p],     qhf, kl4[0], kl4[2]);
                mma16816(s[2 * p],     qlf, kh4[0], kh4[2]);
                mma16816(s[2 * p + 1], qhf, kh4[1], kh4[3]);
                mma16816(s[2 * p + 1], qhf, kl4[1], kl4[3]);
                mma16816(s[2 * p + 1], qlf, kh4[1], kh4[3]);
            }
        }

        CP_WAIT0();          // V(k0) ready
        __syncthreads();     // all warps past S: K buffer free

        // ---- mask apply ----
#pragma unroll
        for (int j = 0; j < 8; j++) {
            const int kc = k0 + 8 * j + lc;
            const uint32_t av = (mAp[j >> 1] >> ((j & 1) * 16));
            const uint32_t bv = (mBp[j >> 1] >> ((j & 1) * 16));
            const unsigned char mAx = av & 0xFF, mAy = (av >> 8) & 0xFF;
            const unsigned char mBx = bv & 0xFF, mBy = (bv >> 8) & 0xFF;
            if (kc >= TK_) {
                s[j][0] = s[j][2] = neg_inf_f();
            } else {
                if (mAx || kc >= klen) s[j][0] = NEGINF2_;
                if (mBx || kc >= klen) s[j][2] = NEGINF2_;
            }
            if (kc + 1 >= TK_) {
                s[j][1] = s[j][3] = neg_inf_f();
            } else {
                if (mAy || kc + 1 >= klen) s[j][1] = NEGINF2_;
                if (mBy || kc + 1 >= klen) s[j][3] = NEGINF2_;
            }
        }

        // ---- online softmax (base-2; max quad-reduced, l per-lane) ----
        float mx0 = NEGINF2_, mx1 = NEGINF2_;
#pragma unroll
        for (int j = 0; j < 8; j++) {
            mx0 = fmaxf(mx0, fmaxf(s[j][0], s[j][1]));
            mx1 = fmaxf(mx1, fmaxf(s[j][2], s[j][3]));
        }
        mx0 = fmaxf(mx0, __shfl_xor_sync(0xffffffffu, mx0, 1));
        mx0 = fmaxf(mx0, __shfl_xor_sync(0xffffffffu, mx0, 2));
        mx1 = fmaxf(mx1, __shfl_xor_sync(0xffffffffu, mx1, 1));
        mx1 = fmaxf(mx1, __shfl_xor_sync(0xffffffffu, mx1, 2));
        const float mn0 = fmaxf(mr0, mx0), mn1 = fmaxf(mr1, mx1);
        const float a0 = ex2f(mr0 - mn0), a1 = ex2f(mr1 - mn1);
        float su0 = 0.f, su1 = 0.f;
#pragma unroll
        for (int j = 0; j < 8; j++) {
            s[j][0] = ex2f(s[j][0] - mn0);
            s[j][1] = ex2f(s[j][1] - mn0);
            s[j][2] = ex2f(s[j][2] - mn1);
            s[j][3] = ex2f(s[j][3] - mn1);
            su0 += s[j][0] + s[j][1];
            su1 += s[j][2] + s[j][3];
        }
        lr0 = lr0 * a0 + su0;  mr0 = mn0;   // per-lane; quad-summed in epilogue
        lr1 = lr1 * a1 + su1;  mr1 = mn1;
#pragma unroll
        for (int j = 0; j < 8; j++) {
            o[j][0] *= a0; o[j][1] *= a0;
            o[j][2] *= a1; o[j][3] *= a1;
        }

        if (k0 + 64 < kend) stageK(k0 + 64);   // async K load overlaps PV MMAs

        // ---- O += P V (P packed lazily per kd; packed cvt) ----
#pragma unroll
        for (int kd = 0; kd < 4; kd++) {
            const uint32_t pah[4] = { pk_hi(s[2 * kd][0],     s[2 * kd][1]),
                                      pk_hi(s[2 * kd][2],     s[2 * kd][3]),
                                      pk_hi(s[2 * kd + 1][0], s[2 * kd + 1][1]),
                                      pk_hi(s[2 * kd + 1][2], s[2 * kd + 1][3]) };
            const uint32_t pal[4] = { pk_lo(s[2 * kd][0],     s[2 * kd][1]),
                                      pk_lo(s[2 * kd][2],     s[2 * kd][3]),
                                      pk_lo(s[2 * kd + 1][0], s[2 * kd + 1][1]),
                                      pk_lo(s[2 * kd + 1][2], s[2 * kd + 1][3]) };
#pragma unroll
            for (int p = 0; p < 4; p++) {
                uint32_t vh4[4], vl4[4];
                uint32_t off = SWZ((uint32_t)((kd * 16 + rr) * 128 + (p * 16 + kk8) * 2));
                ldmat4t(vh4, Vh + off);
                ldmat4t(vl4, Vl + off);
                mma16816(o[2 * p],     pah, vh4[0], vh4[1]);
                mma16816(o[2 * p],     pah, vl4[0], vl4[1]);
                mma16816(o[2 * p],     pal, vh4[0], vh4[1]);
                mma16816(o[2 * p + 1], pah, vh4[2], vh4[3]);
                mma16816(o[2 * p + 1], pah, vl4[2], vl4[3]);
                mma16816(o[2 * p + 1], pal, vh4[2], vh4[3]);
            }
        }
    }

    // ---- epilogue: quad-sum the per-lane l, then normalize ----
    lr0 += __shfl_xor_sync(0xffffffffu, lr0, 1);
    lr0 += __shfl_xor_sync(0xffffffffu, lr0, 2);
    lr1 += __shfl_xor_sync(0xffffffffu, lr1, 1);
    lr1 += __shfl_xor_sync(0xffffffffu, lr1, 2);
    const float inv0 = 1.f / lr0, inv1 = 1.f / lr1;
#pragma unroll
    for (int j = 0; j < 8; j++) {
        const int dh = h * DHH + 8 * j + lc;
        if (qr0 < TQ_) {
            const float v0 = o[j][0] * inv0, v1 = o[j][1] * inv0;
            const size_t ad = ((size_t)qr0 * BB + b) * DD + dh;
            *(uint32_t*)&g_a_hi[ad] = pk_hi(v0, v1);
            *(uint32_t*)&g_a_lo[ad] = pk_lo(v0, v1);
        }
        if (qr1 < TQ_) {
            const float v0 = o[j][2] * inv1, v1 = o[j][3] * inv1;
            const size_t ad = ((size_t)qr1 * BB + b) * DD + dh;
            *(uint32_t*)&g_a_hi[ad] = pk_hi(v0, v1);
            *(uint32_t*)&g_a_lo[ad] = pk_lo(v0, v1);
        }
    }
}

// ---------------------------------------------------------------------------
extern "C" void kernel_launch(void* const* d_in, const int* in_sizes, int n_in,
                              void* d_out, int out_size)
{
    const float* utt = (const float*)d_in[0];
    const float* rc  = (const float*)d_in[1];
    const float* smr = (const float*)d_in[2];
    const float* mem = (const float*)d_in[3];
    const float* Wq  = (const float*)d_in[4];
    const float* bq  = (const float*)d_in[5];
    const float* Wkv = (const float*)d_in[6];
    const float* bkv = (const float*)d_in[7];
    const float* Wo  = (const float*)d_in[8];
    const float* bo  = (const float*)d_in[9];
    const int*   len = (const int*)d_in[10];
    const unsigned char* am = (const unsigned char*)d_in[11];
    float* out = (float*)d_out;

    const int gemm_smem = 98304;
    const int attn_smem = 49152;
    cudaFuncSetAttribute(qkv_gemm, cudaFuncAttributeMaxDynamicSharedMemorySize, gemm_smem);
    cudaFuncSetAttribute(o_gemm,   cudaFuncAttributeMaxDynamicSharedMemorySize, gemm_smem);
    cudaFuncSetAttribute(attn_kernel, cudaFuncAttributeMaxDynamicSharedMemorySize, attn_smem);

    bf16 *qinh, *qinl, *kvinh, *kvinl, *ah, *al, *wh, *wl;
    cudaGetSymbolAddress((void**)&qinh,  g_qin_hi);
    cudaGetSymbolAddress((void**)&qinl,  g_qin_lo);
    cudaGetSymbolAddress((void**)&kvinh, g_kvin_hi);
    cudaGetSymbolAddress((void**)&kvinl, g_kvin_lo);
    cudaGetSymbolAddress((void**)&ah,    g_a_hi);
    cudaGetSymbolAddress((void**)&al,    g_a_lo);
    cudaGetSymbolAddress((void**)&wh,    g_w_hi);
    cudaGetSymbolAddress((void**)&wl,    g_w_lo);

    mask_kernel<<<(TQ_ * TK_ + 255) / 256, 256>>>(am);
    convert_all_kernel<<<dim3((TQ_ * BB * DD / 4 + 255) / 256, 3), 256>>>(
        utt, rc, smr, mem, Wq, Wkv, Wo);
    qkv_gemm<<<dim3(16, 69, 2), 256, gemm_smem>>>(qinh, qinl, kvinh, kvinl, wh, wl, bq, bkv);
    attn_kernel<<<dim3(18, 64), 128, attn_smem>>>(len);
    o_gemm<<<dim3(8, 69), 256, gemm_smem>>>(ah, al, wh + (size_t)1536 * DD,
                                            wl + (size_t)1536 * DD, bo, out);
}

// round 14
// speedup vs baseline: 1.6302x; 1.0464x over previous
#include <cuda_runtime.h>
#include <cuda_bf16.h>
#include <cstdint>

#define TT 1024
#define RR 64
#define SS 16
#define MMEM 16
#define BB 8
#define DD 512
#define HH 8
#define DHH 64
#define TQ_ 1104
#define TK_ 1104
// SCALE * log2(e): scores produced directly in base-2 domain
#define SCALE2_ 0.18033688011112042591f
// -1e8 * log2(e): finite mask value in base-2 domain
#define NEGINF2_ (-1.4426950408889634e8f)

typedef __nv_bfloat16 bf16;

// ---------------- scratch (device globals; allocation-free rule) ----------------
__device__ bf16 g_qin_hi [(size_t)TQ_ * BB * DD];
__device__ bf16 g_qin_lo [(size_t)TQ_ * BB * DD];
__device__ bf16 g_kvin_hi[(size_t)TK_ * BB * DD];
__device__ bf16 g_kvin_lo[(size_t)TK_ * BB * DD];
__device__ bf16 g_w_hi[(size_t)2048 * DD];   // Wq | Wkv | Wo rows
__device__ bf16 g_w_lo[(size_t)2048 * DD];
__device__ bf16 g_q_hi[(size_t)TQ_ * BB * DD];
__device__ bf16 g_q_lo[(size_t)TQ_ * BB * DD];
__device__ bf16 g_k_hi[(size_t)TK_ * BB * DD];
__device__ bf16 g_k_lo[(size_t)TK_ * BB * DD];
__device__ bf16 g_v_hi[(size_t)TK_ * BB * DD];
__device__ bf16 g_v_lo[(size_t)TK_ * BB * DD];
__device__ bf16 g_a_hi[(size_t)TQ_ * BB * DD];
__device__ bf16 g_a_lo[(size_t)TQ_ * BB * DD];
__device__ unsigned char g_mask[(size_t)TQ_ * TK_];

__device__ __forceinline__ float neg_inf_f() { return __int_as_float(0xff800000); }
__device__ __forceinline__ float ex2f(float x) {
    float r; asm("ex2.approx.f32 %0, %1;" : "=f"(r) : "f"(x)); return r;
}

// ---------------- low-level helpers (sm_80-era only; no 'a' features) ----------------
__device__ __forceinline__ uint32_t smem_to_u32(const void* p) {
    uint32_t a;
    asm("{ .reg .u64 t; cvta.to.shared.u64 t, %1; cvt.u32.u64 %0, t; }" : "=r"(a) : "l"(p));
    return a;
}
__device__ __forceinline__ void ldmat4(uint32_t r[4], uint32_t addr) {
    asm volatile("ldmatrix.sync.aligned.m8n8.x4.shared.b16 {%0,%1,%2,%3}, [%4];"
                 : "=r"(r[0]), "=r"(r[1]), "=r"(r[2]), "=r"(r[3]) : "r"(addr));
}
__device__ __forceinline__ void ldmat4t(uint32_t r[4], uint32_t addr) {
    asm volatile("ldmatrix.sync.aligned.m8n8.x4.trans.shared.b16 {%0,%1,%2,%3}, [%4];"
                 : "=r"(r[0]), "=r"(r[1]), "=r"(r[2]), "=r"(r[3]) : "r"(addr));
}
__device__ __forceinline__ void mma16816(float d[4], const uint32_t a[4],
                                         uint32_t b0, uint32_t b1) {
    asm volatile("mma.sync.aligned.m16n8k16.row.col.f32.bf16.bf16.f32 "
                 "{%0,%1,%2,%3}, {%4,%5,%6,%7}, {%8,%9}, {%0,%1,%2,%3};"
                 : "+f"(d[0]), "+f"(d[1]), "+f"(d[2]), "+f"(d[3])
                 : "r"(a[0]), "r"(a[1]), "r"(a[2]), "r"(a[3]), "r"(b0), "r"(b1));
}
__device__ __forceinline__ void cp16(uint32_t dst, const void* src, int bytes) {
    asm volatile("cp.async.cg.shared.global [%0], [%1], 16, %2;"
                 :: "r"(dst), "l"(src), "r"(bytes));
}
#define CP_COMMIT() asm volatile("cp.async.commit_group;" ::: "memory")
#define CP_WAIT0()  asm volatile("cp.async.wait_group 0;" ::: "memory")
#define CP_WAIT1()  asm volatile("cp.async.wait_group 1;" ::: "memory")

#define SWZ(o) ((o) ^ (((o) >> 3) & 0x70))

__device__ __forceinline__ uint32_t pk_hi(float a, float b) {
    uint32_t r;
    asm("cvt.rn.bf16x2.f32 %0, %1, %2;" : "=r"(r) : "f"(b), "f"(a));
    return r;
}
__device__ __forceinline__ uint32_t pk_lo(float a, float b) {
    const uint32_t h = pk_hi(a, b);
    const float la = a - __uint_as_float(h << 16);
    const float lb = b - __uint_as_float(h & 0xffff0000u);
    return pk_hi(la, lb);
}

// ---------------------------------------------------------------------------
// LAUNCH 1: mask detect + canonicalize (unchanged).
// ---------------------------------------------------------------------------
__global__ void __launch_bounds__(256) mask_kernel(const unsigned char* __restrict__ buf)
{
    __shared__ int s_large, s_nzoff;
    if (threadIdx.x == 0) { s_large = 0; s_nzoff = 0; }
    __syncthreads();
    int l = 0, z = 0;
    {
        const int base = threadIdx.x * 16;
#pragma unroll
        for (int j = 0; j < 16; j++) {
            unsigned char v = buf[base + j];
            if (v > 1) l = 1;
            if (((base + j) & 3) && v != 0) z = 1;
        }
    }
    if (l) atomicOr(&s_large, 1);
    if (z) atomicOr(&s_nzoff, 1);
    __syncthreads();
    const int mode = s_large ? 2 : (s_nzoff ? 0 : 1);

    const int idx = blockIdx.x * blockDim.x + threadIdx.x;
    if (idx >= TQ_ * TK_) return;
    unsigned char m;
    if (mode == 0)      m = buf[idx] ? 1 : 0;
    else if (mode == 1) m = (((const int*)buf)[idx] != 0) ? 1 : 0;
    else                m = (((const float*)buf)[idx] != 0.f) ? 1 : 0;
    g_mask[idx] = m;
}

// ---------------------------------------------------------------------------
// LAUNCH 2: all fp32 -> split-bf16 conversions (unchanged).
// ---------------------------------------------------------------------------
__global__ void __launch_bounds__(256) convert_all_kernel(
    const float* __restrict__ utt, const float* __restrict__ rc,
    const float* __restrict__ smr, const float* __restrict__ mem,
    const float* __restrict__ Wq, const float* __restrict__ Wkv,
    const float* __restrict__ Wo)
{
    const int y = blockIdx.y;
    const size_t e = ((size_t)blockIdx.x * blockDim.x + threadIdx.x) * 4;
    if (y < 2) {
        if (e >= (size_t)TQ_ * BB * DD) return;
        const int r = (int)(e >> 9);
        const int k = (int)(e & 511);
        const int t = r >> 3, b = r & 7;
        const float* src;
        if (y == 0) {
            if (t < RR)           src = rc  + ((size_t)t * BB + b) * DD;
            else if (t < RR + TT) src = utt + ((size_t)(t - RR) * BB + b) * DD;
            else                  src = smr + ((size_t)(t - RR - TT) * BB + b) * DD;
        } else {
            if (t < MMEM)           src = mem + ((size_t)t * BB + b) * DD;
            else if (t < MMEM + RR) src = rc  + ((size_t)(t - MMEM) * BB + b) * DD;
            else                    src = utt + ((size_t)(t - MMEM - RR) * BB + b) * DD;
        }
        float4 v = *(const float4*)(src + k);
        bf16* dh = y ? g_kvin_hi : g_qin_hi;
        bf16* dl = y ? g_kvin_lo : g_qin_lo;
        *(uint2*)&dh[e] = make_uint2(pk_hi(v.x, v.y), pk_hi(v.z, v.w));
        *(uint2*)&dl[e] = make_uint2(pk_lo(v.x, v.y), pk_lo(v.z, v.w));
    } else {
        if (e >= (size_t)2048 * DD) return;
        const int r = (int)(e >> 9);
        const int k = (int)(e & 511);
        const float* src;
        if (r < 512)       src = Wq  + (size_t)r * DD;
        else if (r < 1536) src = Wkv + (size_t)(r - 512) * DD;
        else               src = Wo  + (size_t)(r - 1536) * DD;
        float4 v = *(const float4*)(src + k);
        *(uint2*)&g_w_hi[e] = make_uint2(pk_hi(v.x, v.y), pk_hi(v.z, v.w));
        *(uint2*)&g_w_lo[e] = make_uint2(pk_lo(v.x, v.y), pk_lo(v.z, v.w));
    }
}

// ---------------------------------------------------------------------------
// GEMM core — 128m x 64n, 256 threads / 8 warps, K=512, 3-MMA split (unchanged).
// ---------------------------------------------------------------------------
__device__ __forceinline__ void gemm_core(
    const bf16* __restrict__ a_hi, const bf16* __restrict__ a_lo,
    const bf16* __restrict__ b_hi, const bf16* __restrict__ b_lo,
    const float* __restrict__ bias, float* __restrict__ dout,
    int mode, int m0, int n0, char* smc)
{
    const uint32_t smb = smem_to_u32(smc);
    const int tid = threadIdx.x, w = tid >> 5, lane = tid & 31;
    const int wm = w >> 1, wn = w & 1;

    const int ra  = tid >> 1;
    const int ca0 = (tid & 1) * 4;
    const int rb  = tid >> 2;
    const int cb0 = (tid & 3) * 2;

    auto stage = [&](int kc) {
        const uint32_t sb = smb + (kc & 1) * 49152;
        const bf16* As_h = a_hi + (size_t)(m0 + ra) * DD + kc * 64 + ca0 * 8;
        const bf16* As_l = a_lo + (size_t)(m0 + ra) * DD + kc * 64 + ca0 * 8;
#pragma unroll
        for (int i = 0; i < 4; i++) {
            uint32_t so = SWZ((uint32_t)(ra * 128 + (ca0 + i) * 16));
            cp16(sb + so,         As_h + i * 8, 16);
            cp16(sb + 16384 + so, As_l + i * 8, 16);
        }
        const bf16* Bs_h = b_hi + (size_t)(n0 + rb) * DD + kc * 64 + cb0 * 8;
        const bf16* Bs_l = b_lo + (size_t)(n0 + rb) * DD + kc * 64 + cb0 * 8;
#pragma unroll
        for (int i = 0; i < 2; i++) {
            uint32_t so = SWZ((uint32_t)(rb * 128 + (cb0 + i) * 16));
            cp16(sb + 32768 + so, Bs_h + i * 8, 16);
            cp16(sb + 40960 + so, Bs_l + i * 8, 16);
        }
        CP_COMMIT();
    };

    float acc[2][4][4];
#pragma unroll
    for (int a = 0; a < 2; a++)
#pragma unroll
        for (int c = 0; c < 4; c++)
#pragma unroll
            for (int d = 0; d < 4; d++) acc[a][c][d] = 0.f;

    const int rr  = (lane & 7) + ((lane >> 3) & 1) * 8;
    const int kk8 = (lane >> 4) * 8;

    stage(0);
    for (int c = 0; c < 8; c++) {
        CP_WAIT0();
        __syncthreads();
        if (c < 7) stage(c + 1);
        const uint32_t sb = smb + (c & 1) * 49152;
#pragma unroll
        for (int kd = 0; kd < 4; kd++) {
            const uint32_t ko = (uint32_t)((kd * 16 + kk8) * 2);
            uint32_t ah[2][4], al[2][4], bh[2][4], bl[2][4];
#pragma unroll
            for (int mt = 0; mt < 2; mt++) {
                uint32_t off = SWZ((uint32_t)((wm * 32 + mt * 16 + rr) * 128) + ko);
                ldmat4(ah[mt], sb + off);
                ldmat4(al[mt], sb + 16384 + off);
            }
#pragma unroll
            for (int p = 0; p < 2; p++) {
                uint32_t off = SWZ((uint32_t)((wn * 32 + p * 16 + rr) * 128) + ko);
                ldmat4(bh[p], sb + 32768 + off);
                ldmat4(bl[p], sb + 40960 + off);
            }
#pragma unroll
            for (int mt = 0; mt < 2; mt++)
#pragma unroll
                for (int nt = 0; nt < 4; nt++)
                    mma16816(acc[mt][nt], ah[mt],
                             bh[nt >> 1][nt & 1], bh[nt >> 1][2 + (nt & 1)]);
#pragma unroll
            for (int mt = 0; mt < 2; mt++)
#pragma unroll
                for (int nt = 0; nt < 4; nt++)
                    mma16816(acc[mt][nt], ah[mt],
                             bl[nt >> 1][nt & 1], bl[nt >> 1][2 + (nt & 1)]);
#pragma unroll
            for (int mt = 0; mt < 2; mt++)
#pragma unroll
                for (int nt = 0; nt < 4; nt++)
                    mma16816(acc[mt][nt], al[mt],
                             bh[nt >> 1][nt & 1], bh[nt >> 1][2 + (nt & 1)]);
        }
    }

    const int lq = lane >> 2, lc = (lane & 3) * 2;
#pragma unroll
    for (int mt = 0; mt < 2; mt++) {
#pragma unroll
        for (int nt = 0; nt < 4; nt++) {
            const int col = n0 + wn * 32 + nt * 8 + lc;
            const float b0 = bias[col], b1 = bias[col + 1];
#pragma unroll
            for (int hrow = 0; hrow < 2; hrow++) {
                const int m = m0 + wm * 32 + mt * 16 + lq + hrow * 8;
                float v0 = acc[mt][nt][hrow * 2 + 0] + b0;
                float v1 = acc[mt][nt][hrow * 2 + 1] + b1;
                if (mode == 0) {
                    v0 *= SCALE2_; v1 *= SCALE2_;
                    *(uint32_t*)&g_q_hi[(size_t)m * DD + col] = pk_hi(v0, v1);
                    *(uint32_t*)&g_q_lo[(size_t)m * DD + col] = pk_lo(v0, v1);
                } else if (mode == 1) {
                    if (col < DD) {
                        *(uint32_t*)&g_k_hi[(size_t)m * DD + col] = pk_hi(v0, v1);
                        *(uint32_t*)&g_k_lo[(size_t)m * DD + col] = pk_lo(v0, v1);
                    } else {
                        *(uint32_t*)&g_v_hi[(size_t)m * DD + col - DD] = pk_hi(v0, v1);
                        *(uint32_t*)&g_v_lo[(size_t)m * DD + col - DD] = pk_lo(v0, v1);
                    }
                } else {
                    const int tt = m >> 3, rbb = m & 7;
                    if (tt < TQ_ - SS) {
                        *(float2*)&dout[(size_t)m * DD + col] = make_float2(v0, v1);
                    } else if (tt < TQ_ - 1) {
                        v0 = fminf(10.f, fmaxf(-10.f, v0));
                        v1 = fminf(10.f, fmaxf(-10.f, v1));
                        *(float2*)&dout[(size_t)(TQ_ - SS) * BB * DD +
                                        ((size_t)(tt - (TQ_ - SS)) * BB + rbb) * DD + col] =
                            make_float2(v0, v1);
                    }
                }
            }
        }
    }
}

// LAUNCH 3: Q-proj (z=0) + KV-proj (z=1) merged.
__global__ void __launch_bounds__(256, 2) qkv_gemm(
    const bf16* __restrict__ qinh, const bf16* __restrict__ qinl,
    const bf16* __restrict__ kvinh, const bf16* __restrict__ kvinl,
    const bf16* __restrict__ wh, const bf16* __restrict__ wl,
    const float* __restrict__ bq, const float* __restrict__ bkv)
{
    extern __shared__ char smc[];
    const int z = blockIdx.z;
    if (z == 0 && blockIdx.x >= 8) return;
    const bf16* a_hi = z ? kvinh : qinh;
    const bf16* a_lo = z ? kvinl : qinl;
    const bf16* b_hi = wh + (z ? (size_t)512 * DD : 0);
    const bf16* b_lo = wl + (z ? (size_t)512 * DD : 0);
    const float* bias = z ? bkv : bq;
    gemm_core(a_hi, a_lo, b_hi, b_lo, bias, nullptr, z,
              blockIdx.y * 128, blockIdx.x * 64, smc);
}

// LAUNCH 5: O projection.
__global__ void __launch_bounds__(256, 2) o_gemm(
    const bf16* __restrict__ ah, const bf16* __restrict__ al,
    const bf16* __restrict__ bh, const bf16* __restrict__ bl,
    const float* __restrict__ bias, float* __restrict__ dout)
{
    extern __shared__ char smc[];
    gemm_core(ah, al, bh, bl, bias, dout, 2, blockIdx.y * 128, blockIdx.x * 64, smc);
}

// ---------------------------------------------------------------------------
// LAUNCH 4: HMMA flash attention — R13 math, ONE change: 128-q CTAs with
// 256 threads / 8 warps (R5 layout, proven bit-identical by R5==R6 forensics).
// K/V staging amortized over 8 warps (per-warp LSU work halves); each (b,h)
// K/V stream read 9x instead of 18x from L2. Per-warp register footprint
// unchanged -> __launch_bounds__(256,2) keeps 16 warps/SM.
// smem: Qh 16K | Ql 16K | Kh 8K | Kl 8K | Vh 8K | Vl 8K = 64KB.
// ---------------------------------------------------------------------------
__global__ void __launch_bounds__(256, 2) attn_kernel(const int* __restrict__ lengths)
{
    extern __shared__ char smc[];
    const uint32_t smb = smem_to_u32(smc);
    const uint32_t Qh = smb, Ql = smb + 16384;
    const uint32_t Kh = smb + 32768, Kl = smb + 40960;
    const uint32_t Vh = smb + 49152, Vl = smb + 57344;

    const int tid = threadIdx.x, w = tid >> 5, lane = tid & 31;
    const int b = blockIdx.y >> 3, h = blockIdx.y & 7;
    const int q0 = blockIdx.x * 128;

    int maxlen = 0;
#pragma unroll
    for (int i = 0; i < BB; i++) maxlen = max(maxlen, lengths[i]);
    const int klen = lengths[b] + MMEM + (TQ_ - maxlen - SS);
    const int kend = min(TK_, (klen + 63) & ~63);

    // K/V staging: 64 rows x 128B, 256 threads -> 2x16B per thread
    const int rkv  = tid >> 2;
    const int ckv0 = (tid & 3) * 2;

    auto stageK = [&](int k0c) {
        const int tk = k0c + rkv;
        const int bytes = (tk < TK_) ? 16 : 0;
        const size_t go = ((size_t)tk * BB + b) * DD + h * DHH + ckv0 * 8;
#pragma unroll
        for (int i = 0; i < 2; i++) {
            uint32_t so = SWZ((uint32_t)(rkv * 128 + (ckv0 + i) * 16));
            cp16(Kh + so, g_k_hi + go + i * 8, bytes);
            cp16(Kl + so, g_k_lo + go + i * 8, bytes);
        }
        CP_COMMIT();
    };
    auto stageV = [&](int k0c) {
        const int tk = k0c + rkv;
        const int bytes = (tk < TK_) ? 16 : 0;
        const size_t go = ((size_t)tk * BB + b) * DD + h * DHH + ckv0 * 8;
#pragma unroll
        for (int i = 0; i < 2; i++) {
            uint32_t so = SWZ((uint32_t)(rkv * 128 + (ckv0 + i) * 16));
            cp16(Vh + so, g_v_hi + go + i * 8, bytes);
            cp16(Vl + so, g_v_lo + go + i * 8, bytes);
        }
        CP_COMMIT();
    };

    // stage Q (128 rows x 128B; 2 threads/row -> 4x16B each) then K(0)
    {
        const int rq  = tid >> 1;
        const int cq0 = (tid & 1) * 4;
        const int q = q0 + rq;
        const int bytes = (q < TQ_) ? 16 : 0;
        const size_t go = ((size_t)q * BB + b) * DD + h * DHH + cq0 * 8;
#pragma unroll
        for (int i = 0; i < 4; i++) {
            uint32_t so = SWZ((uint32_t)(rq * 128 + (cq0 + i) * 16));
            cp16(Qh + so, g_q_hi + go + i * 8, bytes);
            cp16(Ql + so, g_q_lo + go + i * 8, bytes);
        }
        CP_COMMIT();
    }
    stageK(0);
    CP_WAIT1();
    __syncthreads();

    const int rr  = (lane & 7) + ((lane >> 3) & 1) * 8;
    const int kk8 = (lane >> 4) * 8;

    float o[8][4];
#pragma unroll
    for (int j = 0; j < 8; j++)
#pragma unroll
        for (int d = 0; d < 4; d++) o[j][d] = 0.f;
    float mr0 = neg_inf_f(), mr1 = neg_inf_f(), lr0 = 0.f, lr1 = 0.f;

    const int lq = lane >> 2, lc = (lane & 3) * 2;
    const int qr0 = q0 + 16 * w + lq, qr1 = qr0 + 8;

    for (int k0 = 0; k0 < kend; k0 += 64) {
        CP_WAIT0();
        __syncthreads();
        stageV(k0);

        // ---- mask prefetch (hidden behind S MMAs) ----
        uint32_t mAp[4], mBp[4];
#pragma unroll
        for (int j = 0; j < 8; j++) {
            const int kc = k0 + 8 * j + lc;
            uint32_t a = 0x0101u, bm = 0x0101u;
            if (kc < TK_ - 1) {
                if (qr0 < TQ_) a  = *(const unsigned short*)&g_mask[(size_t)qr0 * TK_ + kc];
                if (qr1 < TQ_) bm = *(const unsigned short*)&g_mask[(size_t)qr1 * TK_ + kc];
            }
            if (j & 1) { mAp[j >> 1] |= a << 16; mBp[j >> 1] |= bm << 16; }
            else       { mAp[j >> 1]  = a;       mBp[j >> 1]  = bm;       }
        }

        // ---- S = Q K^T (Q frags re-loaded per kd from persistent smem) ----
        float s[8][4];
#pragma unroll
        for (int j = 0; j < 8; j++)
#pragma unroll
            for (int d = 0; d < 4; d++) s[j][d] = 0.f;

#pragma unroll
        for (int kd = 0; kd < 4; kd++) {
            const uint32_t ko = (uint32_t)((kd * 16 + kk8) * 2);
            uint32_t qhf[4], qlf[4];
            {
                uint32_t qoff = SWZ((uint32_t)((16 * w + rr) * 128) + ko);
                ldmat4(qhf, Qh + qoff);
                ldmat4(qlf, Ql + qoff);
            }
#pragma unroll
            for (int p = 0; p < 4; p++) {
                uint32_t kh4[4], kl4[4];
                uint32_t off = SWZ((uint32_t)((p * 16 + rr) * 128) + ko);
                ldmat4(kh4, Kh + off);
                ldmat4(kl4, Kl + off);
                mma16816(s[2 * p],     qhf, kh4[0], kh4[2]);
                mma16816(s[2 * p],     qhf, kl4[0], kl4[2]);
                mma16816(s[2 * p],     qlf, kh4[0], kh4[2]);
                mma16816(s[2 * p + 1], qhf, kh4[1], kh4[3]);
                mma16816(s[2 * p + 1], qhf, kl4[1], kl4[3]);
                mma16816(s[2 * p + 1], qlf, kh4[1], kh4[3]);
            }
        }

        CP_WAIT0();          // V(k0) ready
        __syncthreads();     // all warps past S: K buffer free

        // ---- mask apply ----
#pragma unroll
        for (int j = 0; j < 8; j++) {
            const int kc = k0 + 8 * j + lc;
            const uint32_t av = (mAp[j >> 1] >> ((j & 1) * 16));
            const uint32_t bv = (mBp[j >> 1] >> ((j & 1) * 16));
            const unsigned char mAx = av & 0xFF, mAy = (av >> 8) & 0xFF;
            const unsigned char mBx = bv & 0xFF, mBy = (bv >> 8) & 0xFF;
            if (kc >= TK_) {
                s[j][0] = s[j][2] = neg_inf_f();
            } else {
                if (mAx || kc >= klen) s[j][0] = NEGINF2_;
                if (mBx || kc >= klen) s[j][2] = NEGINF2_;
            }
            if (kc + 1 >= TK_) {
                s[j][1] = s[j][3] = neg_inf_f();
            } else {
                if (mAy || kc + 1 >= klen) s[j][1] = NEGINF2_;
                if (mBy || kc + 1 >= klen) s[j][3] = NEGINF2_;
            }
        }

        // ---- online softmax (base-2; max quad-reduced, l per-lane) ----
        float mx0 = NEGINF2_, mx1 = NEGINF2_;
#pragma unroll
        for (int j = 0; j < 8; j++) {
            mx0 = fmaxf(mx0, fmaxf(s[j][0], s[j][1]));
            mx1 = fmaxf(mx1, fmaxf(s[j][2], s[j][3]));
        }
        mx0 = fmaxf(mx0, __shfl_xor_sync(0xffffffffu, mx0, 1));
        mx0 = fmaxf(mx0, __shfl_xor_sync(0xffffffffu, mx0, 2));
        mx1 = fmaxf(mx1, __shfl_xor_sync(0xffffffffu, mx1, 1));
        mx1 = fmaxf(mx1, __shfl_xor_sync(0xffffffffu, mx1, 2));
        const float mn0 = fmaxf(mr0, mx0), mn1 = fmaxf(mr1, mx1);
        const float a0 = ex2f(mr0 - mn0), a1 = ex2f(mr1 - mn1);
        float su0 = 0.f, su1 = 0.f;
#pragma unroll
        for (int j = 0; j < 8; j++) {
            s[j][0] = ex2f(s[j][0] - mn0);
            s[j][1] = ex2f(s[j][1] - mn0);
            s[j][2] = ex2f(s[j][2] - mn1);
            s[j][3] = ex2f(s[j][3] - mn1);
            su0 += s[j][0] + s[j][1];
            su1 += s[j][2] + s[j][3];
        }
        lr0 = lr0 * a0 + su0;  mr0 = mn0;
        lr1 = lr1 * a1 + su1;  mr1 = mn1;
#pragma unroll
        for (int j = 0; j < 8; j++) {
            o[j][0] *= a0; o[j][1] *= a0;
            o[j][2] *= a1; o[j][3] *= a1;
        }

        if (k0 + 64 < kend) stageK(k0 + 64);   // async K load overlaps PV MMAs

        // ---- O += P V (P packed lazily per kd) ----
#pragma unroll
        for (int kd = 0; kd < 4; kd++) {
            const uint32_t pah[4] = { pk_hi(s[2 * kd][0],     s[2 * kd][1]),
                                      pk_hi(s[2 * kd][2],     s[2 * kd][3]),
                                      pk_hi(s[2 * kd + 1][0], s[2 * kd + 1][1]),
                                      pk_hi(s[2 * kd + 1][2], s[2 * kd + 1][3]) };
            const uint32_t pal[4] = { pk_lo(s[2 * kd][0],     s[2 * kd][1]),
                                      pk_lo(s[2 * kd][2],     s[2 * kd][3]),
                                      pk_lo(s[2 * kd + 1][0], s[2 * kd + 1][1]),
                                      pk_lo(s[2 * kd + 1][2], s[2 * kd + 1][3]) };
#pragma unroll
            for (int p = 0; p < 4; p++) {
                uint32_t vh4[4], vl4[4];
                uint32_t off = SWZ((uint32_t)((kd * 16 + rr) * 128 + (p * 16 + kk8) * 2));
                ldmat4t(vh4, Vh + off);
                ldmat4t(vl4, Vl + off);
                mma16816(o[2 * p],     pah, vh4[0], vh4[1]);
                mma16816(o[2 * p],     pah, vl4[0], vl4[1]);
                mma16816(o[2 * p],     pal, vh4[0], vh4[1]);
                mma16816(o[2 * p + 1], pah, vh4[2], vh4[3]);
                mma16816(o[2 * p + 1], pah, vl4[2], vl4[3]);
                mma16816(o[2 * p + 1], pal, vh4[2], vh4[3]);
            }
        }
    }

    // ---- epilogue: quad-sum per-lane l, normalize, split-bf16 store ----
    lr0 += __shfl_xor_sync(0xffffffffu, lr0, 1);
    lr0 += __shfl_xor_sync(0xffffffffu, lr0, 2);
    lr1 += __shfl_xor_sync(0xffffffffu, lr1, 1);
    lr1 += __shfl_xor_sync(0xffffffffu, lr1, 2);
    const float inv0 = 1.f / lr0, inv1 = 1.f / lr1;
#pragma unroll
    for (int j = 0; j < 8; j++) {
        const int dh = h * DHH + 8 * j + lc;
        if (qr0 < TQ_) {
            const float v0 = o[j][0] * inv0, v1 = o[j][1] * inv0;
            const size_t ad = ((size_t)qr0 * BB + b) * DD + dh;
            *(uint32_t*)&g_a_hi[ad] = pk_hi(v0, v1);
            *(uint32_t*)&g_a_lo[ad] = pk_lo(v0, v1);
        }
        if (qr1 < TQ_) {
            const float v0 = o[j][2] * inv1, v1 = o[j][3] * inv1;
            const size_t ad = ((size_t)qr1 * BB + b) * DD + dh;
            *(uint32_t*)&g_a_hi[ad] = pk_hi(v0, v1);
            *(uint32_t*)&g_a_lo[ad] = pk_lo(v0, v1);
        }
    }
}

// ---------------------------------------------------------------------------
extern "C" void kernel_launch(void* const* d_in, const int* in_sizes, int n_in,
                              void* d_out, int out_size)
{
    const float* utt = (const float*)d_in[0];
    const float* rc  = (const float*)d_in[1];
    const float* smr = (const float*)d_in[2];
    const float* mem = (const float*)d_in[3];
    const float* Wq  = (const float*)d_in[4];
    const float* bq  = (const float*)d_in[5];
    const float* Wkv = (const float*)d_in[6];
    const float* bkv = (const float*)d_in[7];
    const float* Wo  = (const float*)d_in[8];
    const float* bo  = (const float*)d_in[9];
    const int*   len = (const int*)d_in[10];
    const unsigned char* am = (const unsigned char*)d_in[11];
    float* out = (float*)d_out;

    const int gemm_smem = 98304;
    const int attn_smem = 65536;   // Q 32K + K 16K + V 16K
    cudaFuncSetAttribute(qkv_gemm, cudaFuncAttributeMaxDynamicSharedMemorySize, gemm_smem);
    cudaFuncSetAttribute(o_gemm,   cudaFuncAttributeMaxDynamicSharedMemorySize, gemm_smem);
    cudaFuncSetAttribute(attn_kernel, cudaFuncAttributeMaxDynamicSharedMemorySize, attn_smem);

    bf16 *qinh, *qinl, *kvinh, *kvinl, *ah, *al, *wh, *wl;
    cudaGetSymbolAddress((void**)&qinh,  g_qin_hi);
    cudaGetSymbolAddress((void**)&qinl,  g_qin_lo);
    cudaGetSymbolAddress((void**)&kvinh, g_kvin_hi);
    cudaGetSymbolAddress((void**)&kvinl, g_kvin_lo);
    cudaGetSymbolAddress((void**)&ah,    g_a_hi);
    cudaGetSymbolAddress((void**)&al,    g_a_lo);
    cudaGetSymbolAddress((void**)&wh,    g_w_hi);
    cudaGetSymbolAddress((void**)&wl,    g_w_lo);

    mask_kernel<<<(TQ_ * TK_ + 255) / 256, 256>>>(am);
    convert_all_kernel<<<dim3((TQ_ * BB * DD / 4 + 255) / 256, 3), 256>>>(
        utt, rc, smr, mem, Wq, Wkv, Wo);
    qkv_gemm<<<dim3(16, 69, 2), 256, gemm_smem>>>(qinh, qinl, kvinh, kvinl, wh, wl, bq, bkv);
    // 9 q-tiles of 128 (ceil(1104/128) = 9)
    attn_kernel<<<dim3(9, 64), 256, attn_smem>>>(len);
    o_gemm<<<dim3(8, 69), 256, gemm_smem>>>(ah, al, wh + (size_t)1536 * DD,
                                            wl + (size_t)1536 * DD, bo, out);
}

// round 15
// speedup vs baseline: 1.8168x; 1.1145x over previous
#include <cuda_runtime.h>
#include <cuda_bf16.h>
#include <cuda_fp16.h>
#include <cstdint>

#define TT 1024
#define RR 64
#define SS 16
#define MMEM 16
#define BB 8
#define DD 512
#define HH 8
#define DHH 64
#define TQ_ 1104
#define TK_ 1104
// SCALE * log2(e): scores produced directly in base-2 domain
#define SCALE2_ 0.18033688011112042591f
// -1e8 * log2(e): finite mask value in base-2 domain
#define NEGINF2_ (-1.4426950408889634e8f)

typedef __nv_bfloat16 bf16;

// ---------------- scratch (device globals; allocation-free rule) ----------------
__device__ bf16 g_qin_hi [(size_t)TQ_ * BB * DD];
__device__ bf16 g_qin_lo [(size_t)TQ_ * BB * DD];
__device__ bf16 g_kvin_hi[(size_t)TK_ * BB * DD];
__device__ bf16 g_kvin_lo[(size_t)TK_ * BB * DD];
__device__ bf16 g_w_hi[(size_t)2048 * DD];   // Wq | Wkv | Wo rows
__device__ bf16 g_w_lo[(size_t)2048 * DD];
// attention operands: fp16 asymmetric-split scheme
__device__ __half g_q16h[(size_t)TQ_ * BB * DD];
__device__ __half g_q16l[(size_t)TQ_ * BB * DD];
__device__ __half g_k16 [(size_t)TK_ * BB * DD];
__device__ __half g_v16h[(size_t)TK_ * BB * DD];
__device__ __half g_v16l[(size_t)TK_ * BB * DD];
__device__ bf16 g_a_hi[(size_t)TQ_ * BB * DD];
__device__ bf16 g_a_lo[(size_t)TQ_ * BB * DD];
__device__ unsigned char g_mask[(size_t)TQ_ * TK_];

__device__ __forceinline__ float neg_inf_f() { return __int_as_float(0xff800000); }
__device__ __forceinline__ float ex2f(float x) {
    float r; asm("ex2.approx.f32 %0, %1;" : "=f"(r) : "f"(x)); return r;
}

// ---------------- low-level helpers (sm_80-era only; no 'a' features) ----------------
__device__ __forceinline__ uint32_t smem_to_u32(const void* p) {
    uint32_t a;
    asm("{ .reg .u64 t; cvta.to.shared.u64 t, %1; cvt.u32.u64 %0, t; }" : "=r"(a) : "l"(p));
    return a;
}
__device__ __forceinline__ void ldmat4(uint32_t r[4], uint32_t addr) {
    asm volatile("ldmatrix.sync.aligned.m8n8.x4.shared.b16 {%0,%1,%2,%3}, [%4];"
                 : "=r"(r[0]), "=r"(r[1]), "=r"(r[2]), "=r"(r[3]) : "r"(addr));
}
__device__ __forceinline__ void ldmat4t(uint32_t r[4], uint32_t addr) {
    asm volatile("ldmatrix.sync.aligned.m8n8.x4.trans.shared.b16 {%0,%1,%2,%3}, [%4];"
                 : "=r"(r[0]), "=r"(r[1]), "=r"(r[2]), "=r"(r[3]) : "r"(addr));
}
__device__ __forceinline__ void mma16816(float d[4], const uint32_t a[4],
                                         uint32_t b0, uint32_t b1) {
    asm volatile("mma.sync.aligned.m16n8k16.row.col.f32.bf16.bf16.f32 "
                 "{%0,%1,%2,%3}, {%4,%5,%6,%7}, {%8,%9}, {%0,%1,%2,%3};"
                 : "+f"(d[0]), "+f"(d[1]), "+f"(d[2]), "+f"(d[3])
                 : "r"(a[0]), "r"(a[1]), "r"(a[2]), "r"(a[3]), "r"(b0), "r"(b1));
}
__device__ __forceinline__ void mma16816h(float d[4], const uint32_t a[4],
                                          uint32_t b0, uint32_t b1) {
    asm volatile("mma.sync.aligned.m16n8k16.row.col.f32.f16.f16.f32 "
                 "{%0,%1,%2,%3}, {%4,%5,%6,%7}, {%8,%9}, {%0,%1,%2,%3};"
                 : "+f"(d[0]), "+f"(d[1]), "+f"(d[2]), "+f"(d[3])
                 : "r"(a[0]), "r"(a[1]), "r"(a[2]), "r"(a[3]), "r"(b0), "r"(b1));
}
__device__ __forceinline__ void cp16(uint32_t dst, const void* src, int bytes) {
    asm volatile("cp.async.cg.shared.global [%0], [%1], 16, %2;"
                 :: "r"(dst), "l"(src), "r"(bytes));
}
#define CP_COMMIT() asm volatile("cp.async.commit_group;" ::: "memory")
#define CP_WAIT0()  asm volatile("cp.async.wait_group 0;" ::: "memory")
#define CP_WAIT1()  asm volatile("cp.async.wait_group 1;" ::: "memory")

#define SWZ(o) ((o) ^ (((o) >> 3) & 0x70))

// bf16 packs (GEMM path)
__device__ __forceinline__ uint32_t pk_hi(float a, float b) {
    uint32_t r;
    asm("cvt.rn.bf16x2.f32 %0, %1, %2;" : "=r"(r) : "f"(b), "f"(a));
    return r;
}
__device__ __forceinline__ uint32_t pk_lo(float a, float b) {
    const uint32_t h = pk_hi(a, b);
    const float la = a - __uint_as_float(h << 16);
    const float lb = b - __uint_as_float(h & 0xffff0000u);
    return pk_hi(la, lb);
}
// fp16 packs (attention path)
__device__ __forceinline__ uint32_t ph16(float a, float b) {
    __half2 t = __floats2half2_rn(a, b);
    return *(uint32_t*)&t;
}
__device__ __forceinline__ uint32_t pl16(float a, float b) {
    __half2 t = __floats2half2_rn(a, b);
    const float la = a - __half2float(__low2half(t));
    const float lb = b - __half2float(__high2half(t));
    return ph16(la, lb);
}

// ---------------------------------------------------------------------------
// LAUNCH 1: mask detect + canonicalize (unchanged).
// ---------------------------------------------------------------------------
__global__ void __launch_bounds__(256) mask_kernel(const unsigned char* __restrict__ buf)
{
    __shared__ int s_large, s_nzoff;
    if (threadIdx.x == 0) { s_large = 0; s_nzoff = 0; }
    __syncthreads();
    int l = 0, z = 0;
    {
        const int base = threadIdx.x * 16;
#pragma unroll
        for (int j = 0; j < 16; j++) {
            unsigned char v = buf[base + j];
            if (v > 1) l = 1;
            if (((base + j) & 3) && v != 0) z = 1;
        }
    }
    if (l) atomicOr(&s_large, 1);
    if (z) atomicOr(&s_nzoff, 1);
    __syncthreads();
    const int mode = s_large ? 2 : (s_nzoff ? 0 : 1);

    const int idx = blockIdx.x * blockDim.x + threadIdx.x;
    if (idx >= TQ_ * TK_) return;
    unsigned char m;
    if (mode == 0)      m = buf[idx] ? 1 : 0;
    else if (mode == 1) m = (((const int*)buf)[idx] != 0) ? 1 : 0;
    else                m = (((const float*)buf)[idx] != 0.f) ? 1 : 0;
    g_mask[idx] = m;
}

// ---------------------------------------------------------------------------
// LAUNCH 2: all fp32 -> split-bf16 conversions (unchanged).
// ---------------------------------------------------------------------------
__global__ void __launch_bounds__(256) convert_all_kernel(
    const float* __restrict__ utt, const float* __restrict__ rc,
    const float* __restrict__ smr, const float* __restrict__ mem,
    const float* __restrict__ Wq, const float* __restrict__ Wkv,
    const float* __restrict__ Wo)
{
    const int y = blockIdx.y;
    const size_t e = ((size_t)blockIdx.x * blockDim.x + threadIdx.x) * 4;
    if (y < 2) {
        if (e >= (size_t)TQ_ * BB * DD) return;
        const int r = (int)(e >> 9);
        const int k = (int)(e & 511);
        const int t = r >> 3, b = r & 7;
        const float* src;
        if (y == 0) {
            if (t < RR)           src = rc  + ((size_t)t * BB + b) * DD;
            else if (t < RR + TT) src = utt + ((size_t)(t - RR) * BB + b) * DD;
            else                  src = smr + ((size_t)(t - RR - TT) * BB + b) * DD;
        } else {
            if (t < MMEM)           src = mem + ((size_t)t * BB + b) * DD;
            else if (t < MMEM + RR) src = rc  + ((size_t)(t - MMEM) * BB + b) * DD;
            else                    src = utt + ((size_t)(t - MMEM - RR) * BB + b) * DD;
        }
        float4 v = *(const float4*)(src + k);
        bf16* dh = y ? g_kvin_hi : g_qin_hi;
        bf16* dl = y ? g_kvin_lo : g_qin_lo;
        *(uint2*)&dh[e] = make_uint2(pk_hi(v.x, v.y), pk_hi(v.z, v.w));
        *(uint2*)&dl[e] = make_uint2(pk_lo(v.x, v.y), pk_lo(v.z, v.w));
    } else {
        if (e >= (size_t)2048 * DD) return;
        const int r = (int)(e >> 9);
        const int k = (int)(e & 511);
        const float* src;
        if (r < 512)       src = Wq  + (size_t)r * DD;
        else if (r < 1536) src = Wkv + (size_t)(r - 512) * DD;
        else               src = Wo  + (size_t)(r - 1536) * DD;
        float4 v = *(const float4*)(src + k);
        *(uint2*)&g_w_hi[e] = make_uint2(pk_hi(v.x, v.y), pk_hi(v.z, v.w));
        *(uint2*)&g_w_lo[e] = make_uint2(pk_lo(v.x, v.y), pk_lo(v.z, v.w));
    }
}

// ---------------------------------------------------------------------------
// GEMM core — 128m x 64n, 256 threads / 8 warps, K=512, bf16 3-MMA split
// (unchanged math). Mode 0/1 epilogues now emit the fp16 attention operands:
//   mode 0 -> Q split fp16 (x SCALE2_)
//   mode 1 -> K single fp16 | V split fp16
// ---------------------------------------------------------------------------
__device__ __forceinline__ void gemm_core(
    const bf16* __restrict__ a_hi, const bf16* __restrict__ a_lo,
    const bf16* __restrict__ b_hi, const bf16* __restrict__ b_lo,
    const float* __restrict__ bias, float* __restrict__ dout,
    int mode, int m0, int n0, char* smc)
{
    const uint32_t smb = smem_to_u32(smc);
    const int tid = threadIdx.x, w = tid >> 5, lane = tid & 31;
    const int wm = w >> 1, wn = w & 1;

    const int ra  = tid >> 1;
    const int ca0 = (tid & 1) * 4;
    const int rb  = tid >> 2;
    const int cb0 = (tid & 3) * 2;

    auto stage = [&](int kc) {
        const uint32_t sb = smb + (kc & 1) * 49152;
        const bf16* As_h = a_hi + (size_t)(m0 + ra) * DD + kc * 64 + ca0 * 8;
        const bf16* As_l = a_lo + (size_t)(m0 + ra) * DD + kc * 64 + ca0 * 8;
#pragma unroll
        for (int i = 0; i < 4; i++) {
            uint32_t so = SWZ((uint32_t)(ra * 128 + (ca0 + i) * 16));
            cp16(sb + so,         As_h + i * 8, 16);
            cp16(sb + 16384 + so, As_l + i * 8, 16);
        }
        const bf16* Bs_h = b_hi + (size_t)(n0 + rb) * DD + kc * 64 + cb0 * 8;
        const bf16* Bs_l = b_lo + (size_t)(n0 + rb) * DD + kc * 64 + cb0 * 8;
#pragma unroll
        for (int i = 0; i < 2; i++) {
            uint32_t so = SWZ((uint32_t)(rb * 128 + (cb0 + i) * 16));
            cp16(sb + 32768 + so, Bs_h + i * 8, 16);
            cp16(sb + 40960 + so, Bs_l + i * 8, 16);
        }
        CP_COMMIT();
    };

    float acc[2][4][4];
#pragma unroll
    for (int a = 0; a < 2; a++)
#pragma unroll
        for (int c = 0; c < 4; c++)
#pragma unroll
            for (int d = 0; d < 4; d++) acc[a][c][d] = 0.f;

    const int rr  = (lane & 7) + ((lane >> 3) & 1) * 8;
    const int kk8 = (lane >> 4) * 8;

    stage(0);
    for (int c = 0; c < 8; c++) {
        CP_WAIT0();
        __syncthreads();
        if (c < 7) stage(c + 1);
        const uint32_t sb = smb + (c & 1) * 49152;
#pragma unroll
        for (int kd = 0; kd < 4; kd++) {
            const uint32_t ko = (uint32_t)((kd * 16 + kk8) * 2);
            uint32_t ah[2][4], al[2][4], bh[2][4], bl[2][4];
#pragma unroll
            for (int mt = 0; mt < 2; mt++) {
                uint32_t off = SWZ((uint32_t)((wm * 32 + mt * 16 + rr) * 128) + ko);
                ldmat4(ah[mt], sb + off);
                ldmat4(al[mt], sb + 16384 + off);
            }
#pragma unroll
            for (int p = 0; p < 2; p++) {
                uint32_t off = SWZ((uint32_t)((wn * 32 + p * 16 + rr) * 128) + ko);
                ldmat4(bh[p], sb + 32768 + off);
                ldmat4(bl[p], sb + 40960 + off);
            }
#pragma unroll
            for (int mt = 0; mt < 2; mt++)
#pragma unroll
                for (int nt = 0; nt < 4; nt++)
                    mma16816(acc[mt][nt], ah[mt],
                             bh[nt >> 1][nt & 1], bh[nt >> 1][2 + (nt & 1)]);
#pragma unroll
            for (int mt = 0; mt < 2; mt++)
#pragma unroll
                for (int nt = 0; nt < 4; nt++)
                    mma16816(acc[mt][nt], ah[mt],
                             bl[nt >> 1][nt & 1], bl[nt >> 1][2 + (nt & 1)]);
#pragma unroll
            for (int mt = 0; mt < 2; mt++)
#pragma unroll
                for (int nt = 0; nt < 4; nt++)
                    mma16816(acc[mt][nt], al[mt],
                             bh[nt >> 1][nt & 1], bh[nt >> 1][2 + (nt & 1)]);
        }
    }

    const int lq = lane >> 2, lc = (lane & 3) * 2;
#pragma unroll
    for (int mt = 0; mt < 2; mt++) {
#pragma unroll
        for (int nt = 0; nt < 4; nt++) {
            const int col = n0 + wn * 32 + nt * 8 + lc;
            const float b0 = bias[col], b1 = bias[col + 1];
#pragma unroll
            for (int hrow = 0; hrow < 2; hrow++) {
                const int m = m0 + wm * 32 + mt * 16 + lq + hrow * 8;
                float v0 = acc[mt][nt][hrow * 2 + 0] + b0;
                float v1 = acc[mt][nt][hrow * 2 + 1] + b1;
                if (mode == 0) {
                    v0 *= SCALE2_; v1 *= SCALE2_;
                    *(uint32_t*)&g_q16h[(size_t)m * DD + col] = ph16(v0, v1);
                    *(uint32_t*)&g_q16l[(size_t)m * DD + col] = pl16(v0, v1);
                } else if (mode == 1) {
                    if (col < DD) {
                        *(uint32_t*)&g_k16[(size_t)m * DD + col] = ph16(v0, v1);
                    } else {
                        *(uint32_t*)&g_v16h[(size_t)m * DD + col - DD] = ph16(v0, v1);
                        *(uint32_t*)&g_v16l[(size_t)m * DD + col - DD] = pl16(v0, v1);
                    }
                } else {
                    const int tt = m >> 3, rbb = m & 7;
                    if (tt < TQ_ - SS) {
                        *(float2*)&dout[(size_t)m * DD + col] = make_float2(v0, v1);
                    } else if (tt < TQ_ - 1) {
                        v0 = fminf(10.f, fmaxf(-10.f, v0));
                        v1 = fminf(10.f, fmaxf(-10.f, v1));
                        *(float2*)&dout[(size_t)(TQ_ - SS) * BB * DD +
                                        ((size_t)(tt - (TQ_ - SS)) * BB + rbb) * DD + col] =
                            make_float2(v0, v1);
                    }
                }
            }
        }
    }
}

// LAUNCH 3: Q-proj (z=0) + KV-proj (z=1) merged.
__global__ void __launch_bounds__(256, 2) qkv_gemm(
    const bf16* __restrict__ qinh, const bf16* __restrict__ qinl,
    const bf16* __restrict__ kvinh, const bf16* __restrict__ kvinl,
    const bf16* __restrict__ wh, const bf16* __restrict__ wl,
    const float* __restrict__ bq, const float* __restrict__ bkv)
{
    extern __shared__ char smc[];
    const int z = blockIdx.z;
    if (z == 0 && blockIdx.x >= 8) return;
    const bf16* a_hi = z ? kvinh : qinh;
    const bf16* a_lo = z ? kvinl : qinl;
    const bf16* b_hi = wh + (z ? (size_t)512 * DD : 0);
    const bf16* b_lo = wl + (z ? (size_t)512 * DD : 0);
    const float* bias = z ? bkv : bq;
    gemm_core(a_hi, a_lo, b_hi, b_lo, bias, nullptr, z,
              blockIdx.y * 128, blockIdx.x * 64, smc);
}

// LAUNCH 5: O projection.
__global__ void __launch_bounds__(256, 2) o_gemm(
    const bf16* __restrict__ ah, const bf16* __restrict__ al,
    const bf16* __restrict__ bh, const bf16* __restrict__ bl,
    const float* __restrict__ bias, float* __restrict__ dout)
{
    extern __shared__ char smc[];
    gemm_core(ah, al, bh, bl, bias, dout, 2, blockIdx.y * 128, blockIdx.x * 64, smc);
}

// ---------------------------------------------------------------------------
// LAUNCH 4: HMMA flash attention — R14 structure, fp16 asymmetric 2-term:
//   S  = (qh + ql) . k      (Q split fp16, K single fp16)  : 4 MMA/(kd,p)
//   PV = p . (vh + vl)      (P single fp16, V split fp16)  : 4 MMA/(kd,p)
// MMA/tile 192->128, ldsm 72->56, K smem/staging halved.
// smem: Qh 16K | Ql 16K | K 8K | Vh 8K | Vl 8K = 56KB.
// ---------------------------------------------------------------------------
__global__ void __launch_bounds__(256, 2) attn_kernel(const int* __restrict__ lengths)
{
    extern __shared__ char smc[];
    const uint32_t smb = smem_to_u32(smc);
    const uint32_t Qh = smb, Ql = smb + 16384;
    const uint32_t Ks = smb + 32768;
    const uint32_t Vh = smb + 40960, Vl = smb + 49152;

    const int tid = threadIdx.x, w = tid >> 5, lane = tid & 31;
    const int b = blockIdx.y >> 3, h = blockIdx.y & 7;
    const int q0 = blockIdx.x * 128;

    int maxlen = 0;
#pragma unroll
    for (int i = 0; i < BB; i++) maxlen = max(maxlen, lengths[i]);
    const int klen = lengths[b] + MMEM + (TQ_ - maxlen - SS);
    const int kend = min(TK_, (klen + 63) & ~63);

    const int rkv  = tid >> 2;
    const int ckv0 = (tid & 3) * 2;

    auto stageK = [&](int k0c) {
        const int tk = k0c + rkv;
        const int bytes = (tk < TK_) ? 16 : 0;
        const size_t go = ((size_t)tk * BB + b) * DD + h * DHH + ckv0 * 8;
#pragma unroll
        for (int i = 0; i < 2; i++) {
            uint32_t so = SWZ((uint32_t)(rkv * 128 + (ckv0 + i) * 16));
            cp16(Ks + so, g_k16 + go + i * 8, bytes);
        }
        CP_COMMIT();
    };
    auto stageV = [&](int k0c) {
        const int tk = k0c + rkv;
        const int bytes = (tk < TK_) ? 16 : 0;
        const size_t go = ((size_t)tk * BB + b) * DD + h * DHH + ckv0 * 8;
#pragma unroll
        for (int i = 0; i < 2; i++) {
            uint32_t so = SWZ((uint32_t)(rkv * 128 + (ckv0 + i) * 16));
            cp16(Vh + so, g_v16h + go + i * 8, bytes);
            cp16(Vl + so, g_v16l + go + i * 8, bytes);
        }
        CP_COMMIT();
    };

    // stage Q (128 rows x 128B; 2 threads/row -> 4x16B each) then K(0)
    {
        const int rq  = tid >> 1;
        const int cq0 = (tid & 1) * 4;
        const int q = q0 + rq;
        const int bytes = (q < TQ_) ? 16 : 0;
        const size_t go = ((size_t)q * BB + b) * DD + h * DHH + cq0 * 8;
#pragma unroll
        for (int i = 0; i < 4; i++) {
            uint32_t so = SWZ((uint32_t)(rq * 128 + (cq0 + i) * 16));
            cp16(Qh + so, g_q16h + go + i * 8, bytes);
            cp16(Ql + so, g_q16l + go + i * 8, bytes);
        }
        CP_COMMIT();
    }
    stageK(0);
    CP_WAIT1();
    __syncthreads();

    const int rr  = (lane & 7) + ((lane >> 3) & 1) * 8;
    const int kk8 = (lane >> 4) * 8;

    float o[8][4];
#pragma unroll
    for (int j = 0; j < 8; j++)
#pragma unroll
        for (int d = 0; d < 4; d++) o[j][d] = 0.f;
    float mr0 = neg_inf_f(), mr1 = neg_inf_f(), lr0 = 0.f, lr1 = 0.f;

    const int lq = lane >> 2, lc = (lane & 3) * 2;
    const int qr0 = q0 + 16 * w + lq, qr1 = qr0 + 8;

    for (int k0 = 0; k0 < kend; k0 += 64) {
        CP_WAIT0();
        __syncthreads();
        stageV(k0);

        // ---- mask prefetch (hidden behind S MMAs) ----
        uint32_t mAp[4], mBp[4];
#pragma unroll
        for (int j = 0; j < 8; j++) {
            const int kc = k0 + 8 * j + lc;
            uint32_t a = 0x0101u, bm = 0x0101u;
            if (kc < TK_ - 1) {
                if (qr0 < TQ_) a  = *(const unsigned short*)&g_mask[(size_t)qr0 * TK_ + kc];
                if (qr1 < TQ_) bm = *(const unsigned short*)&g_mask[(size_t)qr1 * TK_ + kc];
            }
            if (j & 1) { mAp[j >> 1] |= a << 16; mBp[j >> 1] |= bm << 16; }
            else       { mAp[j >> 1]  = a;       mBp[j >> 1]  = bm;       }
        }

        // ---- S = (qh + ql) . k  (fp16; K single) ----
        float s[8][4];
#pragma unroll
        for (int j = 0; j < 8; j++)
#pragma unroll
            for (int d = 0; d < 4; d++) s[j][d] = 0.f;

#pragma unroll
        for (int kd = 0; kd < 4; kd++) {
            const uint32_t ko = (uint32_t)((kd * 16 + kk8) * 2);
            uint32_t qhf[4], qlf[4];
            {
                uint32_t qoff = SWZ((uint32_t)((16 * w + rr) * 128) + ko);
                ldmat4(qhf, Qh + qoff);
                ldmat4(qlf, Ql + qoff);
            }
#pragma unroll
            for (int p = 0; p < 4; p++) {
                uint32_t k4[4];
                uint32_t off = SWZ((uint32_t)((p * 16 + rr) * 128) + ko);
                ldmat4(k4, Ks + off);
                mma16816h(s[2 * p],     qhf, k4[0], k4[2]);
                mma16816h(s[2 * p],     qlf, k4[0], k4[2]);
                mma16816h(s[2 * p + 1], qhf, k4[1], k4[3]);
                mma16816h(s[2 * p + 1], qlf, k4[1], k4[3]);
            }
        }

        CP_WAIT0();          // V(k0) ready
        __syncthreads();     // all warps past S: K buffer free

        // ---- mask apply ----
#pragma unroll
        for (int j = 0; j < 8; j++) {
            const int kc = k0 + 8 * j + lc;
            const uint32_t av = (mAp[j >> 1] >> ((j & 1) * 16));
            const uint32_t bv = (mBp[j >> 1] >> ((j & 1) * 16));
            const unsigned char mAx = av & 0xFF, mAy = (av >> 8) & 0xFF;
            const unsigned char mBx = bv & 0xFF, mBy = (bv >> 8) & 0xFF;
            if (kc >= TK_) {
                s[j][0] = s[j][2] = neg_inf_f();
            } else {
                if (mAx || kc >= klen) s[j][0] = NEGINF2_;
                if (mBx || kc >= klen) s[j][2] = NEGINF2_;
            }
            if (kc + 1 >= TK_) {
                s[j][1] = s[j][3] = neg_inf_f();
            } else {
                if (mAy || kc + 1 >= klen) s[j][1] = NEGINF2_;
                if (mBy || kc + 1 >= klen) s[j][3] = NEGINF2_;
            }
        }

        // ---- online softmax (base-2; max quad-reduced, l per-lane) ----
        float mx0 = NEGINF2_, mx1 = NEGINF2_;
#pragma unroll
        for (int j = 0; j < 8; j++) {
            mx0 = fmaxf(mx0, fmaxf(s[j][0], s[j][1]));
            mx1 = fmaxf(mx1, fmaxf(s[j][2], s[j][3]));
        }
        mx0 = fmaxf(mx0, __shfl_xor_sync(0xffffffffu, mx0, 1));
        mx0 = fmaxf(mx0, __shfl_xor_sync(0xffffffffu, mx0, 2));
        mx1 = fmaxf(mx1, __shfl_xor_sync(0xffffffffu, mx1, 1));
        mx1 = fmaxf(mx1, __shfl_xor_sync(0xffffffffu, mx1, 2));
        const float mn0 = fmaxf(mr0, mx0), mn1 = fmaxf(mr1, mx1);
        const float a0 = ex2f(mr0 - mn0), a1 = ex2f(mr1 - mn1);
        float su0 = 0.f, su1 = 0.f;
#pragma unroll
        for (int j = 0; j < 8; j++) {
            s[j][0] = ex2f(s[j][0] - mn0);
            s[j][1] = ex2f(s[j][1] - mn0);
            s[j][2] = ex2f(s[j][2] - mn1);
            s[j][3] = ex2f(s[j][3] - mn1);
            su0 += s[j][0] + s[j][1];
            su1 += s[j][2] + s[j][3];
        }
        lr0 = lr0 * a0 + su0;  mr0 = mn0;
        lr1 = lr1 * a1 + su1;  mr1 = mn1;
#pragma unroll
        for (int j = 0; j < 8; j++) {
            o[j][0] *= a0; o[j][1] *= a0;
            o[j][2] *= a1; o[j][3] *= a1;
        }

        if (k0 + 64 < kend) stageK(k0 + 64);   // async K load overlaps PV MMAs

        // ---- O += p . (vh + vl)  (P single fp16, V split fp16) ----
#pragma unroll
        for (int kd = 0; kd < 4; kd++) {
            const uint32_t pa[4] = { ph16(s[2 * kd][0],     s[2 * kd][1]),
                                     ph16(s[2 * kd][2],     s[2 * kd][3]),
                                     ph16(s[2 * kd + 1][0], s[2 * kd + 1][1]),
                                     ph16(s[2 * kd + 1][2], s[2 * kd + 1][3]) };
#pragma unroll
            for (int p = 0; p < 4; p++) {
                uint32_t vh4[4], vl4[4];
                uint32_t off = SWZ((uint32_t)((kd * 16 + rr) * 128 + (p * 16 + kk8) * 2));
                ldmat4t(vh4, Vh + off);
                ldmat4t(vl4, Vl + off);
                mma16816h(o[2 * p],     pa, vh4[0], vh4[1]);
                mma16816h(o[2 * p],     pa, vl4[0], vl4[1]);
                mma16816h(o[2 * p + 1], pa, vh4[2], vh4[3]);
                mma16816h(o[2 * p + 1], pa, vl4[2], vl4[3]);
            }
        }
    }

    // ---- epilogue: quad-sum per-lane l, normalize, split-bf16 store ----
    lr0 += __shfl_xor_sync(0xffffffffu, lr0, 1);
    lr0 += __shfl_xor_sync(0xffffffffu, lr0, 2);
    lr1 += __shfl_xor_sync(0xffffffffu, lr1, 1);
    lr1 += __shfl_xor_sync(0xffffffffu, lr1, 2);
    const float inv0 = 1.f / lr0, inv1 = 1.f / lr1;
#pragma unroll
    for (int j = 0; j < 8; j++) {
        const int dh = h * DHH + 8 * j + lc;
        if (qr0 < TQ_) {
            const float v0 = o[j][0] * inv0, v1 = o[j][1] * inv0;
            const size_t ad = ((size_t)qr0 * BB + b) * DD + dh;
            *(uint32_t*)&g_a_hi[ad] = pk_hi(v0, v1);
            *(uint32_t*)&g_a_lo[ad] = pk_lo(v0, v1);
        }
        if (qr1 < TQ_) {
            const float v0 = o[j][2] * inv1, v1 = o[j][3] * inv1;
            const size_t ad = ((size_t)qr1 * BB + b) * DD + dh;
            *(uint32_t*)&g_a_hi[ad] = pk_hi(v0, v1);
            *(uint32_t*)&g_a_lo[ad] = pk_lo(v0, v1);
        }
    }
}

// ---------------------------------------------------------------------------
extern "C" void kernel_launch(void* const* d_in, const int* in_sizes, int n_in,
                              void* d_out, int out_size)
{
    const float* utt = (const float*)d_in[0];
    const float* rc  = (const float*)d_in[1];
    const float* smr = (const float*)d_in[2];
    const float* mem = (const float*)d_in[3];
    const float* Wq  = (const float*)d_in[4];
    const float* bq  = (const float*)d_in[5];
    const float* Wkv = (const float*)d_in[6];
    const float* bkv = (const float*)d_in[7];
    const float* Wo  = (const float*)d_in[8];
    const float* bo  = (const float*)d_in[9];
    const int*   len = (const int*)d_in[10];
    const unsigned char* am = (const unsigned char*)d_in[11];
    float* out = (float*)d_out;

    const int gemm_smem = 98304;
    const int attn_smem = 57344;   // Q 32K + K 8K + V 16K
    cudaFuncSetAttribute(qkv_gemm, cudaFuncAttributeMaxDynamicSharedMemorySize, gemm_smem);
    cudaFuncSetAttribute(o_gemm,   cudaFuncAttributeMaxDynamicSharedMemorySize, gemm_smem);
    cudaFuncSetAttribute(attn_kernel, cudaFuncAttributeMaxDynamicSharedMemorySize, attn_smem);

    bf16 *qinh, *qinl, *kvinh, *kvinl, *ah, *al, *wh, *wl;
    cudaGetSymbolAddress((void**)&qinh,  g_qin_hi);
    cudaGetSymbolAddress((void**)&qinl,  g_qin_lo);
    cudaGetSymbolAddress((void**)&kvinh, g_kvin_hi);
    cudaGetSymbolAddress((void**)&kvinl, g_kvin_lo);
    cudaGetSymbolAddress((void**)&ah,    g_a_hi);
    cudaGetSymbolAddress((void**)&al,    g_a_lo);
    cudaGetSymbolAddress((void**)&wh,    g_w_hi);
    cudaGetSymbolAddress((void**)&wl,    g_w_lo);

    mask_kernel<<<(TQ_ * TK_ + 255) / 256, 256>>>(am);
    convert_all_kernel<<<dim3((TQ_ * BB * DD / 4 + 255) / 256, 3), 256>>>(
        utt, rc, smr, mem, Wq, Wkv, Wo);
    qkv_gemm<<<dim3(16, 69, 2), 256, gemm_smem>>>(qinh, qinl, kvinh, kvinl, wh, wl, bq, bkv);
    attn_kernel<<<dim3(9, 64), 256, attn_smem>>>(len);
    o_gemm<<<dim3(8, 69), 256, gemm_smem>>>(ah, al, wh + (size_t)1536 * DD,
                                            wl + (size_t)1536 * DD, bo, out);
}

// round 16
// speedup vs baseline: 2.0219x; 1.1129x over previous
#include <cuda_runtime.h>
#include <cuda_bf16.h>
#include <cuda_fp16.h>
#include <cstdint>

#define TT 1024
#define RR 64
#define SS 16
#define MMEM 16
#define BB 8
#define DD 512
#define HH 8
#define DHH 64
#define TQ_ 1104
#define TK_ 1104
// SCALE * log2(e): scores produced directly in base-2 domain
#define SCALE2_ 0.18033688011112042591f
// -1e8 * log2(e): finite mask value in base-2 domain
#define NEGINF2_ (-1.4426950408889634e8f)

typedef __nv_bfloat16 bf16;

// ---------------- scratch (device globals; allocation-free rule) ----------------
__device__ bf16 g_qin_hi [(size_t)TQ_ * BB * DD];
__device__ bf16 g_qin_lo [(size_t)TQ_ * BB * DD];
__device__ bf16 g_kvin_hi[(size_t)TK_ * BB * DD];
__device__ bf16 g_kvin_lo[(size_t)TK_ * BB * DD];
__device__ bf16 g_w_hi[(size_t)2048 * DD];   // Wq | Wkv | Wo rows
__device__ bf16 g_w_lo[(size_t)2048 * DD];
// attention operands: all single fp16 (calibrated error budget, R15/R16)
__device__ __half g_q16[(size_t)TQ_ * BB * DD];
__device__ __half g_k16[(size_t)TK_ * BB * DD];
__device__ __half g_v16[(size_t)TK_ * BB * DD];
__device__ bf16 g_a_hi[(size_t)TQ_ * BB * DD];
__device__ bf16 g_a_lo[(size_t)TQ_ * BB * DD];
__device__ unsigned char g_mask[(size_t)TQ_ * TK_];

__device__ __forceinline__ float neg_inf_f() { return __int_as_float(0xff800000); }
__device__ __forceinline__ float ex2f(float x) {
    float r; asm("ex2.approx.f32 %0, %1;" : "=f"(r) : "f"(x)); return r;
}

// ---------------- low-level helpers (sm_80-era only; no 'a' features) ----------------
__device__ __forceinline__ uint32_t smem_to_u32(const void* p) {
    uint32_t a;
    asm("{ .reg .u64 t; cvta.to.shared.u64 t, %1; cvt.u32.u64 %0, t; }" : "=r"(a) : "l"(p));
    return a;
}
__device__ __forceinline__ void ldmat4(uint32_t r[4], uint32_t addr) {
    asm volatile("ldmatrix.sync.aligned.m8n8.x4.shared.b16 {%0,%1,%2,%3}, [%4];"
                 : "=r"(r[0]), "=r"(r[1]), "=r"(r[2]), "=r"(r[3]) : "r"(addr));
}
__device__ __forceinline__ void ldmat4t(uint32_t r[4], uint32_t addr) {
    asm volatile("ldmatrix.sync.aligned.m8n8.x4.trans.shared.b16 {%0,%1,%2,%3}, [%4];"
                 : "=r"(r[0]), "=r"(r[1]), "=r"(r[2]), "=r"(r[3]) : "r"(addr));
}
__device__ __forceinline__ void mma16816(float d[4], const uint32_t a[4],
                                         uint32_t b0, uint32_t b1) {
    asm volatile("mma.sync.aligned.m16n8k16.row.col.f32.bf16.bf16.f32 "
                 "{%0,%1,%2,%3}, {%4,%5,%6,%7}, {%8,%9}, {%0,%1,%2,%3};"
                 : "+f"(d[0]), "+f"(d[1]), "+f"(d[2]), "+f"(d[3])
                 : "r"(a[0]), "r"(a[1]), "r"(a[2]), "r"(a[3]), "r"(b0), "r"(b1));
}
__device__ __forceinline__ void mma16816h(float d[4], const uint32_t a[4],
                                          uint32_t b0, uint32_t b1) {
    asm volatile("mma.sync.aligned.m16n8k16.row.col.f32.f16.f16.f32 "
                 "{%0,%1,%2,%3}, {%4,%5,%6,%7}, {%8,%9}, {%0,%1,%2,%3};"
                 : "+f"(d[0]), "+f"(d[1]), "+f"(d[2]), "+f"(d[3])
                 : "r"(a[0]), "r"(a[1]), "r"(a[2]), "r"(a[3]), "r"(b0), "r"(b1));
}
__device__ __forceinline__ void cp16(uint32_t dst, const void* src, int bytes) {
    asm volatile("cp.async.cg.shared.global [%0], [%1], 16, %2;"
                 :: "r"(dst), "l"(src), "r"(bytes));
}
#define CP_COMMIT() asm volatile("cp.async.commit_group;" ::: "memory")
#define CP_WAIT0()  asm volatile("cp.async.wait_group 0;" ::: "memory")
#define CP_WAIT1()  asm volatile("cp.async.wait_group 1;" ::: "memory")

#define SWZ(o) ((o) ^ (((o) >> 3) & 0x70))

// bf16 packs (GEMM path)
__device__ __forceinline__ uint32_t pk_hi(float a, float b) {
    uint32_t r;
    asm("cvt.rn.bf16x2.f32 %0, %1, %2;" : "=r"(r) : "f"(b), "f"(a));
    return r;
}
__device__ __forceinline__ uint32_t pk_lo(float a, float b) {
    const uint32_t h = pk_hi(a, b);
    const float la = a - __uint_as_float(h << 16);
    const float lb = b - __uint_as_float(h & 0xffff0000u);
    return pk_hi(la, lb);
}
// fp16 pack (attention path)
__device__ __forceinline__ uint32_t ph16(float a, float b) {
    __half2 t = __floats2half2_rn(a, b);
    return *(uint32_t*)&t;
}

// ---------------------------------------------------------------------------
// LAUNCH 1: mask detect + canonicalize (unchanged).
// ---------------------------------------------------------------------------
__global__ void __launch_bounds__(256) mask_kernel(const unsigned char* __restrict__ buf)
{
    __shared__ int s_large, s_nzoff;
    if (threadIdx.x == 0) { s_large = 0; s_nzoff = 0; }
    __syncthreads();
    int l = 0, z = 0;
    {
        const int base = threadIdx.x * 16;
#pragma unroll
        for (int j = 0; j < 16; j++) {
            unsigned char v = buf[base + j];
            if (v > 1) l = 1;
            if (((base + j) & 3) && v != 0) z = 1;
        }
    }
    if (l) atomicOr(&s_large, 1);
    if (z) atomicOr(&s_nzoff, 1);
    __syncthreads();
    const int mode = s_large ? 2 : (s_nzoff ? 0 : 1);

    const int idx = blockIdx.x * blockDim.x + threadIdx.x;
    if (idx >= TQ_ * TK_) return;
    unsigned char m;
    if (mode == 0)      m = buf[idx] ? 1 : 0;
    else if (mode == 1) m = (((const int*)buf)[idx] != 0) ? 1 : 0;
    else                m = (((const float*)buf)[idx] != 0.f) ? 1 : 0;
    g_mask[idx] = m;
}

// ---------------------------------------------------------------------------
// LAUNCH 2: all fp32 -> split-bf16 conversions (unchanged).
// ---------------------------------------------------------------------------
__global__ void __launch_bounds__(256) convert_all_kernel(
    const float* __restrict__ utt, const float* __restrict__ rc,
    const float* __restrict__ smr, const float* __restrict__ mem,
    const float* __restrict__ Wq, const float* __restrict__ Wkv,
    const float* __restrict__ Wo)
{
    const int y = blockIdx.y;
    const size_t e = ((size_t)blockIdx.x * blockDim.x + threadIdx.x) * 4;
    if (y < 2) {
        if (e >= (size_t)TQ_ * BB * DD) return;
        const int r = (int)(e >> 9);
        const int k = (int)(e & 511);
        const int t = r >> 3, b = r & 7;
        const float* src;
        if (y == 0) {
            if (t < RR)           src = rc  + ((size_t)t * BB + b) * DD;
            else if (t < RR + TT) src = utt + ((size_t)(t - RR) * BB + b) * DD;
            else                  src = smr + ((size_t)(t - RR - TT) * BB + b) * DD;
        } else {
            if (t < MMEM)           src = mem + ((size_t)t * BB + b) * DD;
            else if (t < MMEM + RR) src = rc  + ((size_t)(t - MMEM) * BB + b) * DD;
            else                    src = utt + ((size_t)(t - MMEM - RR) * BB + b) * DD;
        }
        float4 v = *(const float4*)(src + k);
        bf16* dh = y ? g_kvin_hi : g_qin_hi;
        bf16* dl = y ? g_kvin_lo : g_qin_lo;
        *(uint2*)&dh[e] = make_uint2(pk_hi(v.x, v.y), pk_hi(v.z, v.w));
        *(uint2*)&dl[e] = make_uint2(pk_lo(v.x, v.y), pk_lo(v.z, v.w));
    } else {
        if (e >= (size_t)2048 * DD) return;
        const int r = (int)(e >> 9);
        const int k = (int)(e & 511);
        const float* src;
        if (r < 512)       src = Wq  + (size_t)r * DD;
        else if (r < 1536) src = Wkv + (size_t)(r - 512) * DD;
        else               src = Wo  + (size_t)(r - 1536) * DD;
        float4 v = *(const float4*)(src + k);
        *(uint2*)&g_w_hi[e] = make_uint2(pk_hi(v.x, v.y), pk_hi(v.z, v.w));
        *(uint2*)&g_w_lo[e] = make_uint2(pk_lo(v.x, v.y), pk_lo(v.z, v.w));
    }
}

// ---------------------------------------------------------------------------
// GEMM core — 128m x 64n, 256 threads / 8 warps, K=512, bf16 3-MMA split
// (unchanged math). Epilogues emit single-fp16 attention operands:
//   mode 0 -> Q fp16 (x SCALE2_)    mode 1 -> K fp16 | V fp16
// ---------------------------------------------------------------------------
__device__ __forceinline__ void gemm_core(
    const bf16* __restrict__ a_hi, const bf16* __restrict__ a_lo,
    const bf16* __restrict__ b_hi, const bf16* __restrict__ b_lo,
    const float* __restrict__ bias, float* __restrict__ dout,
    int mode, int m0, int n0, char* smc)
{
    const uint32_t smb = smem_to_u32(smc);
    const int tid = threadIdx.x, w = tid >> 5, lane = tid & 31;
    const int wm = w >> 1, wn = w & 1;

    const int ra  = tid >> 1;
    const int ca0 = (tid & 1) * 4;
    const int rb  = tid >> 2;
    const int cb0 = (tid & 3) * 2;

    auto stage = [&](int kc) {
        const uint32_t sb = smb + (kc & 1) * 49152;
        const bf16* As_h = a_hi + (size_t)(m0 + ra) * DD + kc * 64 + ca0 * 8;
        const bf16* As_l = a_lo + (size_t)(m0 + ra) * DD + kc * 64 + ca0 * 8;
#pragma unroll
        for (int i = 0; i < 4; i++) {
            uint32_t so = SWZ((uint32_t)(ra * 128 + (ca0 + i) * 16));
            cp16(sb + so,         As_h + i * 8, 16);
            cp16(sb + 16384 + so, As_l + i * 8, 16);
        }
        const bf16* Bs_h = b_hi + (size_t)(n0 + rb) * DD + kc * 64 + cb0 * 8;
        const bf16* Bs_l = b_lo + (size_t)(n0 + rb) * DD + kc * 64 + cb0 * 8;
#pragma unroll
        for (int i = 0; i < 2; i++) {
            uint32_t so = SWZ((uint32_t)(rb * 128 + (cb0 + i) * 16));
            cp16(sb + 32768 + so, Bs_h + i * 8, 16);
            cp16(sb + 40960 + so, Bs_l + i * 8, 16);
        }
        CP_COMMIT();
    };

    float acc[2][4][4];
#pragma unroll
    for (int a = 0; a < 2; a++)
#pragma unroll
        for (int c = 0; c < 4; c++)
#pragma unroll
            for (int d = 0; d < 4; d++) acc[a][c][d] = 0.f;

    const int rr  = (lane & 7) + ((lane >> 3) & 1) * 8;
    const int kk8 = (lane >> 4) * 8;

    stage(0);
    for (int c = 0; c < 8; c++) {
        CP_WAIT0();
        __syncthreads();
        if (c < 7) stage(c + 1);
        const uint32_t sb = smb + (c & 1) * 49152;
#pragma unroll
        for (int kd = 0; kd < 4; kd++) {
            const uint32_t ko = (uint32_t)((kd * 16 + kk8) * 2);
            uint32_t ah[2][4], al[2][4], bh[2][4], bl[2][4];
#pragma unroll
            for (int mt = 0; mt < 2; mt++) {
                uint32_t off = SWZ((uint32_t)((wm * 32 + mt * 16 + rr) * 128) + ko);
                ldmat4(ah[mt], sb + off);
                ldmat4(al[mt], sb + 16384 + off);
            }
#pragma unroll
            for (int p = 0; p < 2; p++) {
                uint32_t off = SWZ((uint32_t)((wn * 32 + p * 16 + rr) * 128) + ko);
                ldmat4(bh[p], sb + 32768 + off);
                ldmat4(bl[p], sb + 40960 + off);
            }
#pragma unroll
            for (int mt = 0; mt < 2; mt++)
#pragma unroll
                for (int nt = 0; nt < 4; nt++)
                    mma16816(acc[mt][nt], ah[mt],
                             bh[nt >> 1][nt & 1], bh[nt >> 1][2 + (nt & 1)]);
#pragma unroll
            for (int mt = 0; mt < 2; mt++)
#pragma unroll
                for (int nt = 0; nt < 4; nt++)
                    mma16816(acc[mt][nt], ah[mt],
                             bl[nt >> 1][nt & 1], bl[nt >> 1][2 + (nt & 1)]);
#pragma unroll
            for (int mt = 0; mt < 2; mt++)
#pragma unroll
                for (int nt = 0; nt < 4; nt++)
                    mma16816(acc[mt][nt], al[mt],
                             bh[nt >> 1][nt & 1], bh[nt >> 1][2 + (nt & 1)]);
        }
    }

    const int lq = lane >> 2, lc = (lane & 3) * 2;
#pragma unroll
    for (int mt = 0; mt < 2; mt++) {
#pragma unroll
        for (int nt = 0; nt < 4; nt++) {
            const int col = n0 + wn * 32 + nt * 8 + lc;
            const float b0 = bias[col], b1 = bias[col + 1];
#pragma unroll
            for (int hrow = 0; hrow < 2; hrow++) {
                const int m = m0 + wm * 32 + mt * 16 + lq + hrow * 8;
                float v0 = acc[mt][nt][hrow * 2 + 0] + b0;
                float v1 = acc[mt][nt][hrow * 2 + 1] + b1;
                if (mode == 0) {
                    v0 *= SCALE2_; v1 *= SCALE2_;
                    *(uint32_t*)&g_q16[(size_t)m * DD + col] = ph16(v0, v1);
                } else if (mode == 1) {
                    if (col < DD) {
                        *(uint32_t*)&g_k16[(size_t)m * DD + col] = ph16(v0, v1);
                    } else {
                        *(uint32_t*)&g_v16[(size_t)m * DD + col - DD] = ph16(v0, v1);
                    }
                } else {
                    const int tt = m >> 3, rbb = m & 7;
                    if (tt < TQ_ - SS) {
                        *(float2*)&dout[(size_t)m * DD + col] = make_float2(v0, v1);
                    } else if (tt < TQ_ - 1) {
                        v0 = fminf(10.f, fmaxf(-10.f, v0));
                        v1 = fminf(10.f, fmaxf(-10.f, v1));
                        *(float2*)&dout[(size_t)(TQ_ - SS) * BB * DD +
                                        ((size_t)(tt - (TQ_ - SS)) * BB + rbb) * DD + col] =
                            make_float2(v0, v1);
                    }
                }
            }
        }
    }
}

// LAUNCH 3: Q-proj (z=0) + KV-proj (z=1) merged.
__global__ void __launch_bounds__(256, 2) qkv_gemm(
    const bf16* __restrict__ qinh, const bf16* __restrict__ qinl,
    const bf16* __restrict__ kvinh, const bf16* __restrict__ kvinl,
    const bf16* __restrict__ wh, const bf16* __restrict__ wl,
    const float* __restrict__ bq, const float* __restrict__ bkv)
{
    extern __shared__ char smc[];
    const int z = blockIdx.z;
    if (z == 0 && blockIdx.x >= 8) return;
    const bf16* a_hi = z ? kvinh : qinh;
    const bf16* a_lo = z ? kvinl : qinl;
    const bf16* b_hi = wh + (z ? (size_t)512 * DD : 0);
    const bf16* b_lo = wl + (z ? (size_t)512 * DD : 0);
    const float* bias = z ? bkv : bq;
    gemm_core(a_hi, a_lo, b_hi, b_lo, bias, nullptr, z,
              blockIdx.y * 128, blockIdx.x * 64, smc);
}

// LAUNCH 5: O projection.
__global__ void __launch_bounds__(256, 2) o_gemm(
    const bf16* __restrict__ ah, const bf16* __restrict__ al,
    const bf16* __restrict__ bh, const bf16* __restrict__ bl,
    const float* __restrict__ bias, float* __restrict__ dout)
{
    extern __shared__ char smc[];
    gemm_core(ah, al, bh, bl, bias, dout, 2, blockIdx.y * 128, blockIdx.x * 64, smc);
}

// ---------------------------------------------------------------------------
// LAUNCH 4: HMMA flash attention — R15 structure, all operands single fp16:
//   S  = q . k   : 2 MMA/(kd,p)       PV = p . v : 2 MMA/(kd,p)
// MMA/tile 128->64, ldsm 56->36, staging cp.async -33%.
// smem: Q 16K | K 8K | V 8K = 32KB.
// Calibrated error model: +Q-single ~7e-5, +V-single ~1.4e-4 over measured
// 2.1e-4 -> predicted ~2.6-3.0e-4 (threshold 1e-3).
// ---------------------------------------------------------------------------
__global__ void __launch_bounds__(256, 2) attn_kernel(const int* __restrict__ lengths)
{
    extern __shared__ char smc[];
    const uint32_t smb = smem_to_u32(smc);
    const uint32_t Qs = smb;
    const uint32_t Ks = smb + 16384;
    const uint32_t Vs = smb + 24576;

    const int tid = threadIdx.x, w = tid >> 5, lane = tid & 31;
    const int b = blockIdx.y >> 3, h = blockIdx.y & 7;
    const int q0 = blockIdx.x * 128;

    int maxlen = 0;
#pragma unroll
    for (int i = 0; i < BB; i++) maxlen = max(maxlen, lengths[i]);
    const int klen = lengths[b] + MMEM + (TQ_ - maxlen - SS);
    const int kend = min(TK_, (klen + 63) & ~63);

    const int rkv  = tid >> 2;
    const int ckv0 = (tid & 3) * 2;

    auto stageK = [&](int k0c) {
        const int tk = k0c + rkv;
        const int bytes = (tk < TK_) ? 16 : 0;
        const size_t go = ((size_t)tk * BB + b) * DD + h * DHH + ckv0 * 8;
#pragma unroll
        for (int i = 0; i < 2; i++) {
            uint32_t so = SWZ((uint32_t)(rkv * 128 + (ckv0 + i) * 16));
            cp16(Ks + so, g_k16 + go + i * 8, bytes);
        }
        CP_COMMIT();
    };
    auto stageV = [&](int k0c) {
        const int tk = k0c + rkv;
        const int bytes = (tk < TK_) ? 16 : 0;
        const size_t go = ((size_t)tk * BB + b) * DD + h * DHH + ckv0 * 8;
#pragma unroll
        for (int i = 0; i < 2; i++) {
            uint32_t so = SWZ((uint32_t)(rkv * 128 + (ckv0 + i) * 16));
            cp16(Vs + so, g_v16 + go + i * 8, bytes);
        }
        CP_COMMIT();
    };

    // stage Q (128 rows x 128B; 2 threads/row -> 4x16B each) then K(0)
    {
        const int rq  = tid >> 1;
        const int cq0 = (tid & 1) * 4;
        const int q = q0 + rq;
        const int bytes = (q < TQ_) ? 16 : 0;
        const size_t go = ((size_t)q * BB + b) * DD + h * DHH + cq0 * 8;
#pragma unroll
        for (int i = 0; i < 4; i++) {
            uint32_t so = SWZ((uint32_t)(rq * 128 + (cq0 + i) * 16));
            cp16(Qs + so, g_q16 + go + i * 8, bytes);
        }
        CP_COMMIT();
    }
    stageK(0);
    CP_WAIT1();
    __syncthreads();

    const int rr  = (lane & 7) + ((lane >> 3) & 1) * 8;
    const int kk8 = (lane >> 4) * 8;

    float o[8][4];
#pragma unroll
    for (int j = 0; j < 8; j++)
#pragma unroll
        for (int d = 0; d < 4; d++) o[j][d] = 0.f;
    float mr0 = neg_inf_f(), mr1 = neg_inf_f(), lr0 = 0.f, lr1 = 0.f;

    const int lq = lane >> 2, lc = (lane & 3) * 2;
    const int qr0 = q0 + 16 * w + lq, qr1 = qr0 + 8;

    for (int k0 = 0; k0 < kend; k0 += 64) {
        CP_WAIT0();
        __syncthreads();
        stageV(k0);

        // ---- mask prefetch (hidden behind S MMAs) ----
        uint32_t mAp[4], mBp[4];
#pragma unroll
        for (int j = 0; j < 8; j++) {
            const int kc = k0 + 8 * j + lc;
            uint32_t a = 0x0101u, bm = 0x0101u;
            if (kc < TK_ - 1) {
                if (qr0 < TQ_) a  = *(const unsigned short*)&g_mask[(size_t)qr0 * TK_ + kc];
                if (qr1 < TQ_) bm = *(const unsigned short*)&g_mask[(size_t)qr1 * TK_ + kc];
            }
            if (j & 1) { mAp[j >> 1] |= a << 16; mBp[j >> 1] |= bm << 16; }
            else       { mAp[j >> 1]  = a;       mBp[j >> 1]  = bm;       }
        }

        // ---- S = q . k  (single fp16) ----
        float s[8][4];
#pragma unroll
        for (int j = 0; j < 8; j++)
#pragma unroll
            for (int d = 0; d < 4; d++) s[j][d] = 0.f;

#pragma unroll
        for (int kd = 0; kd < 4; kd++) {
            const uint32_t ko = (uint32_t)((kd * 16 + kk8) * 2);
            uint32_t qf[4];
            ldmat4(qf, Qs + SWZ((uint32_t)((16 * w + rr) * 128) + ko));
#pragma unroll
            for (int p = 0; p < 4; p++) {
                uint32_t k4[4];
                ldmat4(k4, Ks + SWZ((uint32_t)((p * 16 + rr) * 128) + ko));
                mma16816h(s[2 * p],     qf, k4[0], k4[2]);
                mma16816h(s[2 * p + 1], qf, k4[1], k4[3]);
            }
        }

        CP_WAIT0();          // V(k0) ready
        __syncthreads();     // all warps past S: K buffer free

        // ---- mask apply ----
#pragma unroll
        for (int j = 0; j < 8; j++) {
            const int kc = k0 + 8 * j + lc;
            const uint32_t av = (mAp[j >> 1] >> ((j & 1) * 16));
            const uint32_t bv = (mBp[j >> 1] >> ((j & 1) * 16));
            const unsigned char mAx = av & 0xFF, mAy = (av >> 8) & 0xFF;
            const unsigned char mBx = bv & 0xFF, mBy = (bv >> 8) & 0xFF;
            if (kc >= TK_) {
                s[j][0] = s[j][2] = neg_inf_f();
            } else {
                if (mAx || kc >= klen) s[j][0] = NEGINF2_;
                if (mBx || kc >= klen) s[j][2] = NEGINF2_;
            }
            if (kc + 1 >= TK_) {
                s[j][1] = s[j][3] = neg_inf_f();
            } else {
                if (mAy || kc + 1 >= klen) s[j][1] = NEGINF2_;
                if (mBy || kc + 1 >= klen) s[j][3] = NEGINF2_;
            }
        }

        // ---- online softmax (base-2; max quad-reduced, l per-lane) ----
        float mx0 = NEGINF2_, mx1 = NEGINF2_;
#pragma unroll
        for (int j = 0; j < 8; j++) {
            mx0 = fmaxf(mx0, fmaxf(s[j][0], s[j][1]));
            mx1 = fmaxf(mx1, fmaxf(s[j][2], s[j][3]));
        }
        mx0 = fmaxf(mx0, __shfl_xor_sync(0xffffffffu, mx0, 1));
        mx0 = fmaxf(mx0, __shfl_xor_sync(0xffffffffu, mx0, 2));
        mx1 = fmaxf(mx1, __shfl_xor_sync(0xffffffffu, mx1, 1));
        mx1 = fmaxf(mx1, __shfl_xor_sync(0xffffffffu, mx1, 2));
        const float mn0 = fmaxf(mr0, mx0), mn1 = fmaxf(mr1, mx1);
        const float a0 = ex2f(mr0 - mn0), a1 = ex2f(mr1 - mn1);
        float su0 = 0.f, su1 = 0.f;
#pragma unroll
        for (int j = 0; j < 8; j++) {
            s[j][0] = ex2f(s[j][0] - mn0);
            s[j][1] = ex2f(s[j][1] - mn0);
            s[j][2] = ex2f(s[j][2] - mn1);
            s[j][3] = ex2f(s[j][3] - mn1);
            su0 += s[j][0] + s[j][1];
            su1 += s[j][2] + s[j][3];
        }
        lr0 = lr0 * a0 + su0;  mr0 = mn0;
        lr1 = lr1 * a1 + su1;  mr1 = mn1;
#pragma unroll
        for (int j = 0; j < 8; j++) {
            o[j][0] *= a0; o[j][1] *= a0;
            o[j][2] *= a1; o[j][3] *= a1;
        }

        if (k0 + 64 < kend) stageK(k0 + 64);   // async K load overlaps PV MMAs

        // ---- O += p . v  (single fp16) ----
#pragma unroll
        for (int kd = 0; kd < 4; kd++) {
            const uint32_t pa[4] = { ph16(s[2 * kd][0],     s[2 * kd][1]),
                                     ph16(s[2 * kd][2],     s[2 * kd][3]),
                                     ph16(s[2 * kd + 1][0], s[2 * kd + 1][1]),
                                     ph16(s[2 * kd + 1][2], s[2 * kd + 1][3]) };
#pragma unroll
            for (int p = 0; p < 4; p++) {
                uint32_t v4[4];
                ldmat4t(v4, Vs + SWZ((uint32_t)((kd * 16 + rr) * 128 + (p * 16 + kk8) * 2)));
                mma16816h(o[2 * p],     pa, v4[0], v4[1]);
                mma16816h(o[2 * p + 1], pa, v4[2], v4[3]);
            }
        }
    }

    // ---- epilogue: quad-sum per-lane l, normalize, split-bf16 store ----
    lr0 += __shfl_xor_sync(0xffffffffu, lr0, 1);
    lr0 += __shfl_xor_sync(0xffffffffu, lr0, 2);
    lr1 += __shfl_xor_sync(0xffffffffu, lr1, 1);
    lr1 += __shfl_xor_sync(0xffffffffu, lr1, 2);
    const float inv0 = 1.f / lr0, inv1 = 1.f / lr1;
#pragma unroll
    for (int j = 0; j < 8; j++) {
        const int dh = h * DHH + 8 * j + lc;
        if (qr0 < TQ_) {
            const float v0 = o[j][0] * inv0, v1 = o[j][1] * inv0;
            const size_t ad = ((size_t)qr0 * BB + b) * DD + dh;
            *(uint32_t*)&g_a_hi[ad] = pk_hi(v0, v1);
            *(uint32_t*)&g_a_lo[ad] = pk_lo(v0, v1);
        }
        if (qr1 < TQ_) {
            const float v0 = o[j][2] * inv1, v1 = o[j][3] * inv1;
            const size_t ad = ((size_t)qr1 * BB + b) * DD + dh;
            *(uint32_t*)&g_a_hi[ad] = pk_hi(v0, v1);
            *(uint32_t*)&g_a_lo[ad] = pk_lo(v0, v1);
        }
    }
}

// ---------------------------------------------------------------------------
extern "C" void kernel_launch(void* const* d_in, const int* in_sizes, int n_in,
                              void* d_out, int out_size)
{
    const float* utt = (const float*)d_in[0];
    const float* rc  = (const float*)d_in[1];
    const float* smr = (const float*)d_in[2];
    const float* mem = (const float*)d_in[3];
    const float* Wq  = (const float*)d_in[4];
    const float* bq  = (const float*)d_in[5];
    const float* Wkv = (const float*)d_in[6];
    const float* bkv = (const float*)d_in[7];
    const float* Wo  = (const float*)d_in[8];
    const float* bo  = (const float*)d_in[9];
    const int*   len = (const int*)d_in[10];
    const unsigned char* am = (const unsigned char*)d_in[11];
    float* out = (float*)d_out;

    const int gemm_smem = 98304;
    const int attn_smem = 32768;   // Q 16K + K 8K + V 8K
    cudaFuncSetAttribute(qkv_gemm, cudaFuncAttributeMaxDynamicSharedMemorySize, gemm_smem);
    cudaFuncSetAttribute(o_gemm,   cudaFuncAttributeMaxDynamicSharedMemorySize, gemm_smem);
    cudaFuncSetAttribute(attn_kernel, cudaFuncAttributeMaxDynamicSharedMemorySize, attn_smem);

    bf16 *qinh, *qinl, *kvinh, *kvinl, *ah, *al, *wh, *wl;
    cudaGetSymbolAddress((void**)&qinh,  g_qin_hi);
    cudaGetSymbolAddress((void**)&qinl,  g_qin_lo);
    cudaGetSymbolAddress((void**)&kvinh, g_kvin_hi);
    cudaGetSymbolAddress((void**)&kvinl, g_kvin_lo);
    cudaGetSymbolAddress((void**)&ah,    g_a_hi);
    cudaGetSymbolAddress((void**)&al,    g_a_lo);
    cudaGetSymbolAddress((void**)&wh,    g_w_hi);
    cudaGetSymbolAddress((void**)&wl,    g_w_lo);

    mask_kernel<<<(TQ_ * TK_ + 255) / 256, 256>>>(am);
    convert_all_kernel<<<dim3((TQ_ * BB * DD / 4 + 255) / 256, 3), 256>>>(
        utt, rc, smr, mem, Wq, Wkv, Wo);
    qkv_gemm<<<dim3(16, 69, 2), 256, gemm_smem>>>(qinh, qinl, kvinh, kvinl, wh, wl, bq, bkv);
    attn_kernel<<<dim3(9, 64), 256, attn_smem>>>(len);
    o_gemm<<<dim3(8, 69), 256, gemm_smem>>>(ah, al, wh + (size_t)1536 * DD,
                                            wl + (size_t)1536 * DD, bo, out);
}

// round 17
// speedup vs baseline: 2.2996x; 1.1373x over previous
#include <cuda_runtime.h>
#include <cuda_fp16.h>
#include <cstdint>

#define TT 1024
#define RR 64
#define SS 16
#define MMEM 16
#define BB 8
#define DD 512
#define HH 8
#define DHH 64
#define TQ_ 1104
#define TK_ 1104
// SCALE * log2(e): scores produced directly in base-2 domain
#define SCALE2_ 0.18033688011112042591f
// -1e8 * log2(e): finite mask value in base-2 domain
#define NEGINF2_ (-1.4426950408889634e8f)

// ---------------- scratch (device globals; allocation-free rule) ----------------
__device__ __half g_qin_h [(size_t)TQ_ * BB * DD];
__device__ __half g_qin_l [(size_t)TQ_ * BB * DD];
__device__ __half g_kvin_h[(size_t)TK_ * BB * DD];
__device__ __half g_kvin_l[(size_t)TK_ * BB * DD];
__device__ __half g_w16[(size_t)2048 * DD];   // Wq | Wkv | Wo rows, single fp16
__device__ __half g_q16[(size_t)TQ_ * BB * DD];
__device__ __half g_k16[(size_t)TK_ * BB * DD];
__device__ __half g_v16[(size_t)TK_ * BB * DD];
__device__ __half g_a16h[(size_t)TQ_ * BB * DD];
__device__ __half g_a16l[(size_t)TQ_ * BB * DD];
__device__ unsigned char g_mask[(size_t)TQ_ * TK_];

__device__ __forceinline__ float neg_inf_f() { return __int_as_float(0xff800000); }
__device__ __forceinline__ float ex2f(float x) {
    float r; asm("ex2.approx.f32 %0, %1;" : "=f"(r) : "f"(x)); return r;
}

// ---------------- low-level helpers (sm_80-era only; no 'a' features) ----------------
__device__ __forceinline__ uint32_t smem_to_u32(const void* p) {
    uint32_t a;
    asm("{ .reg .u64 t; cvta.to.shared.u64 t, %1; cvt.u32.u64 %0, t; }" : "=r"(a) : "l"(p));
    return a;
}
__device__ __forceinline__ void ldmat4(uint32_t r[4], uint32_t addr) {
    asm volatile("ldmatrix.sync.aligned.m8n8.x4.shared.b16 {%0,%1,%2,%3}, [%4];"
                 : "=r"(r[0]), "=r"(r[1]), "=r"(r[2]), "=r"(r[3]) : "r"(addr));
}
__device__ __forceinline__ void ldmat4t(uint32_t r[4], uint32_t addr) {
    asm volatile("ldmatrix.sync.aligned.m8n8.x4.trans.shared.b16 {%0,%1,%2,%3}, [%4];"
                 : "=r"(r[0]), "=r"(r[1]), "=r"(r[2]), "=r"(r[3]) : "r"(addr));
}
__device__ __forceinline__ void mma16816h(float d[4], const uint32_t a[4],
                                          uint32_t b0, uint32_t b1) {
    asm volatile("mma.sync.aligned.m16n8k16.row.col.f32.f16.f16.f32 "
                 "{%0,%1,%2,%3}, {%4,%5,%6,%7}, {%8,%9}, {%0,%1,%2,%3};"
                 : "+f"(d[0]), "+f"(d[1]), "+f"(d[2]), "+f"(d[3])
                 : "r"(a[0]), "r"(a[1]), "r"(a[2]), "r"(a[3]), "r"(b0), "r"(b1));
}
__device__ __forceinline__ void cp16(uint32_t dst, const void* src, int bytes) {
    asm volatile("cp.async.cg.shared.global [%0], [%1], 16, %2;"
                 :: "r"(dst), "l"(src), "r"(bytes));
}
#define CP_COMMIT() asm volatile("cp.async.commit_group;" ::: "memory")
#define CP_WAIT0()  asm volatile("cp.async.wait_group 0;" ::: "memory")
#define CP_WAIT1()  asm volatile("cp.async.wait_group 1;" ::: "memory")

#define SWZ(o) ((o) ^ (((o) >> 3) & 0x70))

// fp16 packs
__device__ __forceinline__ uint32_t ph16(float a, float b) {
    __half2 t = __floats2half2_rn(a, b);
    return *(uint32_t*)&t;
}
__device__ __forceinline__ uint32_t pl16(float a, float b) {
    __half2 t = __floats2half2_rn(a, b);
    const float la = a - __half2float(__low2half(t));
    const float lb = b - __half2float(__high2half(t));
    return ph16(la, lb);
}

// ---------------------------------------------------------------------------
// LAUNCH 1: mask detect + canonicalize (unchanged).
// ---------------------------------------------------------------------------
__global__ void __launch_bounds__(256) mask_kernel(const unsigned char* __restrict__ buf)
{
    __shared__ int s_large, s_nzoff;
    if (threadIdx.x == 0) { s_large = 0; s_nzoff = 0; }
    __syncthreads();
    int l = 0, z = 0;
    {
        const int base = threadIdx.x * 16;
#pragma unroll
        for (int j = 0; j < 16; j++) {
            unsigned char v = buf[base + j];
            if (v > 1) l = 1;
            if (((base + j) & 3) && v != 0) z = 1;
        }
    }
    if (l) atomicOr(&s_large, 1);
    if (z) atomicOr(&s_nzoff, 1);
    __syncthreads();
    const int mode = s_large ? 2 : (s_nzoff ? 0 : 1);

    const int idx = blockIdx.x * blockDim.x + threadIdx.x;
    if (idx >= TQ_ * TK_) return;
    unsigned char m;
    if (mode == 0)      m = buf[idx] ? 1 : 0;
    else if (mode == 1) m = (((const int*)buf)[idx] != 0) ? 1 : 0;
    else                m = (((const float*)buf)[idx] != 0.f) ? 1 : 0;
    g_mask[idx] = m;
}

// ---------------------------------------------------------------------------
// LAUNCH 2: fp32 -> fp16 conversions. Inputs split (hi+lo), weights single.
// ---------------------------------------------------------------------------
__global__ void __launch_bounds__(256) convert_all_kernel(
    const float* __restrict__ utt, const float* __restrict__ rc,
    const float* __restrict__ smr, const float* __restrict__ mem,
    const float* __restrict__ Wq, const float* __restrict__ Wkv,
    const float* __restrict__ Wo)
{
    const int y = blockIdx.y;
    const size_t e = ((size_t)blockIdx.x * blockDim.x + threadIdx.x) * 4;
    if (y < 2) {
        if (e >= (size_t)TQ_ * BB * DD) return;
        const int r = (int)(e >> 9);
        const int k = (int)(e & 511);
        const int t = r >> 3, b = r & 7;
        const float* src;
        if (y == 0) {
            if (t < RR)           src = rc  + ((size_t)t * BB + b) * DD;
            else if (t < RR + TT) src = utt + ((size_t)(t - RR) * BB + b) * DD;
            else                  src = smr + ((size_t)(t - RR - TT) * BB + b) * DD;
        } else {
            if (t < MMEM)           src = mem + ((size_t)t * BB + b) * DD;
            else if (t < MMEM + RR) src = rc  + ((size_t)(t - MMEM) * BB + b) * DD;
            else                    src = utt + ((size_t)(t - MMEM - RR) * BB + b) * DD;
        }
        float4 v = *(const float4*)(src + k);
        __half* dh = y ? g_kvin_h : g_qin_h;
        __half* dl = y ? g_kvin_l : g_qin_l;
        *(uint2*)&dh[e] = make_uint2(ph16(v.x, v.y), ph16(v.z, v.w));
        *(uint2*)&dl[e] = make_uint2(pl16(v.x, v.y), pl16(v.z, v.w));
    } else {
        if (e >= (size_t)2048 * DD) return;
        const int r = (int)(e >> 9);
        const int k = (int)(e & 511);
        const float* src;
        if (r < 512)       src = Wq  + (size_t)r * DD;
        else if (r < 1536) src = Wkv + (size_t)(r - 512) * DD;
        else               src = Wo  + (size_t)(r - 1536) * DD;
        float4 v = *(const float4*)(src + k);
        *(uint2*)&g_w16[e] = make_uint2(ph16(v.x, v.y), ph16(v.z, v.w));
    }
}

// ---------------------------------------------------------------------------
// GEMM core — 128m x 64n, 256 threads / 8 warps, K=512.
// fp16 2-MMA: D = (Ah + Al) . B^T,  A split fp16 (exact), B single fp16.
// smem/stage: Ah 16K | Al 16K | B 8K = 40KB; 2 stages = 80KB.
// ---------------------------------------------------------------------------
__device__ __forceinline__ void gemm_core(
    const __half* __restrict__ a_hi, const __half* __restrict__ a_lo,
    const __half* __restrict__ bmat,
    const float* __restrict__ bias, float* __restrict__ dout,
    int mode, int m0, int n0, char* smc)
{
    const uint32_t smb = smem_to_u32(smc);
    const int tid = threadIdx.x, w = tid >> 5, lane = tid & 31;
    const int wm = w >> 1, wn = w & 1;

    const int ra  = tid >> 1;          // 0..127 (A rows)
    const int ca0 = (tid & 1) * 4;
    const int rb  = tid >> 2;          // 0..63  (B rows)
    const int cb0 = (tid & 3) * 2;

    auto stage = [&](int kc) {
        const uint32_t sb = smb + (kc & 1) * 40960;
        const __half* As_h = a_hi + (size_t)(m0 + ra) * DD + kc * 64 + ca0 * 8;
        const __half* As_l = a_lo + (size_t)(m0 + ra) * DD + kc * 64 + ca0 * 8;
#pragma unroll
        for (int i = 0; i < 4; i++) {
            uint32_t so = SWZ((uint32_t)(ra * 128 + (ca0 + i) * 16));
            cp16(sb + so,         As_h + i * 8, 16);
            cp16(sb + 16384 + so, As_l + i * 8, 16);
        }
        const __half* Bs = bmat + (size_t)(n0 + rb) * DD + kc * 64 + cb0 * 8;
#pragma unroll
        for (int i = 0; i < 2; i++) {
            uint32_t so = SWZ((uint32_t)(rb * 128 + (cb0 + i) * 16));
            cp16(sb + 32768 + so, Bs + i * 8, 16);
        }
        CP_COMMIT();
    };

    float acc[2][4][4];
#pragma unroll
    for (int a = 0; a < 2; a++)
#pragma unroll
        for (int c = 0; c < 4; c++)
#pragma unroll
            for (int d = 0; d < 4; d++) acc[a][c][d] = 0.f;

    const int rr  = (lane & 7) + ((lane >> 3) & 1) * 8;
    const int kk8 = (lane >> 4) * 8;

    stage(0);
    for (int c = 0; c < 8; c++) {
        CP_WAIT0();
        __syncthreads();
        if (c < 7) stage(c + 1);
        const uint32_t sb = smb + (c & 1) * 40960;
#pragma unroll
        for (int kd = 0; kd < 4; kd++) {
            const uint32_t ko = (uint32_t)((kd * 16 + kk8) * 2);
            uint32_t ah[2][4], al[2][4], bh[2][4];
#pragma unroll
            for (int mt = 0; mt < 2; mt++) {
                uint32_t off = SWZ((uint32_t)((wm * 32 + mt * 16 + rr) * 128) + ko);
                ldmat4(ah[mt], sb + off);
                ldmat4(al[mt], sb + 16384 + off);
            }
#pragma unroll
            for (int p = 0; p < 2; p++) {
                uint32_t off = SWZ((uint32_t)((wn * 32 + p * 16 + rr) * 128) + ko);
                ldmat4(bh[p], sb + 32768 + off);
            }
            // term-major: Ah.B x8, then Al.B x8
#pragma unroll
            for (int mt = 0; mt < 2; mt++)
#pragma unroll
                for (int nt = 0; nt < 4; nt++)
                    mma16816h(acc[mt][nt], ah[mt],
                              bh[nt >> 1][nt & 1], bh[nt >> 1][2 + (nt & 1)]);
#pragma unroll
            for (int mt = 0; mt < 2; mt++)
#pragma unroll
                for (int nt = 0; nt < 4; nt++)
                    mma16816h(acc[mt][nt], al[mt],
                              bh[nt >> 1][nt & 1], bh[nt >> 1][2 + (nt & 1)]);
        }
    }

    const int lq = lane >> 2, lc = (lane & 3) * 2;
#pragma unroll
    for (int mt = 0; mt < 2; mt++) {
#pragma unroll
        for (int nt = 0; nt < 4; nt++) {
            const int col = n0 + wn * 32 + nt * 8 + lc;
            const float b0 = bias[col], b1 = bias[col + 1];
#pragma unroll
            for (int hrow = 0; hrow < 2; hrow++) {
                const int m = m0 + wm * 32 + mt * 16 + lq + hrow * 8;
                float v0 = acc[mt][nt][hrow * 2 + 0] + b0;
                float v1 = acc[mt][nt][hrow * 2 + 1] + b1;
                if (mode == 0) {
                    v0 *= SCALE2_; v1 *= SCALE2_;
                    *(uint32_t*)&g_q16[(size_t)m * DD + col] = ph16(v0, v1);
                } else if (mode == 1) {
                    if (col < DD) {
                        *(uint32_t*)&g_k16[(size_t)m * DD + col] = ph16(v0, v1);
                    } else {
                        *(uint32_t*)&g_v16[(size_t)m * DD + col - DD] = ph16(v0, v1);
                    }
                } else {
                    const int tt = m >> 3, rbb = m & 7;
                    if (tt < TQ_ - SS) {
                        *(float2*)&dout[(size_t)m * DD + col] = make_float2(v0, v1);
                    } else if (tt < TQ_ - 1) {
                        v0 = fminf(10.f, fmaxf(-10.f, v0));
                        v1 = fminf(10.f, fmaxf(-10.f, v1));
                        *(float2*)&dout[(size_t)(TQ_ - SS) * BB * DD +
                                        ((size_t)(tt - (TQ_ - SS)) * BB + rbb) * DD + col] =
                            make_float2(v0, v1);
                    }
                }
            }
        }
    }
}

// LAUNCH 3: Q-proj (z=0) + KV-proj (z=1) merged.
__global__ void __launch_bounds__(256, 2) qkv_gemm(
    const __half* __restrict__ qinh, const __half* __restrict__ qinl,
    const __half* __restrict__ kvinh, const __half* __restrict__ kvinl,
    const __half* __restrict__ wmat,
    const float* __restrict__ bq, const float* __restrict__ bkv)
{
    extern __shared__ char smc[];
    const int z = blockIdx.z;
    if (z == 0 && blockIdx.x >= 8) return;
    const __half* a_hi = z ? kvinh : qinh;
    const __half* a_lo = z ? kvinl : qinl;
    const __half* b    = wmat + (z ? (size_t)512 * DD : 0);
    const float* bias  = z ? bkv : bq;
    gemm_core(a_hi, a_lo, b, bias, nullptr, z, blockIdx.y * 128, blockIdx.x * 64, smc);
}

// LAUNCH 5: O projection.
__global__ void __launch_bounds__(256, 2) o_gemm(
    const __half* __restrict__ ah, const __half* __restrict__ al,
    const __half* __restrict__ b,
    const float* __restrict__ bias, float* __restrict__ dout)
{
    extern __shared__ char smc[];
    gemm_core(ah, al, b, bias, dout, 2, blockIdx.y * 128, blockIdx.x * 64, smc);
}

// ---------------------------------------------------------------------------
// LAUNCH 4: HMMA flash attention — R16 verbatim except epilogue emits fp16
// hi/lo pairs for the fp16 O projection.
// ---------------------------------------------------------------------------
__global__ void __launch_bounds__(256, 2) attn_kernel(const int* __restrict__ lengths)
{
    extern __shared__ char smc[];
    const uint32_t smb = smem_to_u32(smc);
    const uint32_t Qs = smb;
    const uint32_t Ks = smb + 16384;
    const uint32_t Vs = smb + 24576;

    const int tid = threadIdx.x, w = tid >> 5, lane = tid & 31;
    const int b = blockIdx.y >> 3, h = blockIdx.y & 7;
    const int q0 = blockIdx.x * 128;

    int maxlen = 0;
#pragma unroll
    for (int i = 0; i < BB; i++) maxlen = max(maxlen, lengths[i]);
    const int klen = lengths[b] + MMEM + (TQ_ - maxlen - SS);
    const int kend = min(TK_, (klen + 63) & ~63);

    const int rkv  = tid >> 2;
    const int ckv0 = (tid & 3) * 2;

    auto stageK = [&](int k0c) {
        const int tk = k0c + rkv;
        const int bytes = (tk < TK_) ? 16 : 0;
        const size_t go = ((size_t)tk * BB + b) * DD + h * DHH + ckv0 * 8;
#pragma unroll
        for (int i = 0; i < 2; i++) {
            uint32_t so = SWZ((uint32_t)(rkv * 128 + (ckv0 + i) * 16));
            cp16(Ks + so, g_k16 + go + i * 8, bytes);
        }
        CP_COMMIT();
    };
    auto stageV = [&](int k0c) {
        const int tk = k0c + rkv;
        const int bytes = (tk < TK_) ? 16 : 0;
        const size_t go = ((size_t)tk * BB + b) * DD + h * DHH + ckv0 * 8;
#pragma unroll
        for (int i = 0; i < 2; i++) {
            uint32_t so = SWZ((uint32_t)(rkv * 128 + (ckv0 + i) * 16));
            cp16(Vs + so, g_v16 + go + i * 8, bytes);
        }
        CP_COMMIT();
    };

    // stage Q then K(0)
    {
        const int rq  = tid >> 1;
        const int cq0 = (tid & 1) * 4;
        const int q = q0 + rq;
        const int bytes = (q < TQ_) ? 16 : 0;
        const size_t go = ((size_t)q * BB + b) * DD + h * DHH + cq0 * 8;
#pragma unroll
        for (int i = 0; i < 4; i++) {
            uint32_t so = SWZ((uint32_t)(rq * 128 + (cq0 + i) * 16));
            cp16(Qs + so, g_q16 + go + i * 8, bytes);
        }
        CP_COMMIT();
    }
    stageK(0);
    CP_WAIT1();
    __syncthreads();

    const int rr  = (lane & 7) + ((lane >> 3) & 1) * 8;
    const int kk8 = (lane >> 4) * 8;

    float o[8][4];
#pragma unroll
    for (int j = 0; j < 8; j++)
#pragma unroll
        for (int d = 0; d < 4; d++) o[j][d] = 0.f;
    float mr0 = neg_inf_f(), mr1 = neg_inf_f(), lr0 = 0.f, lr1 = 0.f;

    const int lq = lane >> 2, lc = (lane & 3) * 2;
    const int qr0 = q0 + 16 * w + lq, qr1 = qr0 + 8;

    for (int k0 = 0; k0 < kend; k0 += 64) {
        CP_WAIT0();
        __syncthreads();
        stageV(k0);

        // ---- mask prefetch (hidden behind S MMAs) ----
        uint32_t mAp[4], mBp[4];
#pragma unroll
        for (int j = 0; j < 8; j++) {
            const int kc = k0 + 8 * j + lc;
            uint32_t a = 0x0101u, bm = 0x0101u;
            if (kc < TK_ - 1) {
                if (qr0 < TQ_) a  = *(const unsigned short*)&g_mask[(size_t)qr0 * TK_ + kc];
                if (qr1 < TQ_) bm = *(const unsigned short*)&g_mask[(size_t)qr1 * TK_ + kc];
            }
            if (j & 1) { mAp[j >> 1] |= a << 16; mBp[j >> 1] |= bm << 16; }
            else       { mAp[j >> 1]  = a;       mBp[j >> 1]  = bm;       }
        }

        // ---- S = q . k ----
        float s[8][4];
#pragma unroll
        for (int j = 0; j < 8; j++)
#pragma unroll
            for (int d = 0; d < 4; d++) s[j][d] = 0.f;

#pragma unroll
        for (int kd = 0; kd < 4; kd++) {
            const uint32_t ko = (uint32_t)((kd * 16 + kk8) * 2);
            uint32_t qf[4];
            ldmat4(qf, Qs + SWZ((uint32_t)((16 * w + rr) * 128) + ko));
#pragma unroll
            for (int p = 0; p < 4; p++) {
                uint32_t k4[4];
                ldmat4(k4, Ks + SWZ((uint32_t)((p * 16 + rr) * 128) + ko));
                mma16816h(s[2 * p],     qf, k4[0], k4[2]);
                mma16816h(s[2 * p + 1], qf, k4[1], k4[3]);
            }
        }

        CP_WAIT0();          // V(k0) ready
        __syncthreads();     // all warps past S: K buffer free

        // ---- mask apply ----
#pragma unroll
        for (int j = 0; j < 8; j++) {
            const int kc = k0 + 8 * j + lc;
            const uint32_t av = (mAp[j >> 1] >> ((j & 1) * 16));
            const uint32_t bv = (mBp[j >> 1] >> ((j & 1) * 16));
            const unsigned char mAx = av & 0xFF, mAy = (av >> 8) & 0xFF;
            const unsigned char mBx = bv & 0xFF, mBy = (bv >> 8) & 0xFF;
            if (kc >= TK_) {
                s[j][0] = s[j][2] = neg_inf_f();
            } else {
                if (mAx || kc >= klen) s[j][0] = NEGINF2_;
                if (mBx || kc >= klen) s[j][2] = NEGINF2_;
            }
            if (kc + 1 >= TK_) {
                s[j][1] = s[j][3] = neg_inf_f();
            } else {
                if (mAy || kc + 1 >= klen) s[j][1] = NEGINF2_;
                if (mBy || kc + 1 >= klen) s[j][3] = NEGINF2_;
            }
        }

        // ---- online softmax (base-2; max quad-reduced, l per-lane) ----
        float mx0 = NEGINF2_, mx1 = NEGINF2_;
#pragma unroll
        for (int j = 0; j < 8; j++) {
            mx0 = fmaxf(mx0, fmaxf(s[j][0], s[j][1]));
            mx1 = fmaxf(mx1, fmaxf(s[j][2], s[j][3]));
        }
        mx0 = fmaxf(mx0, __shfl_xor_sync(0xffffffffu, mx0, 1));
        mx0 = fmaxf(mx0, __shfl_xor_sync(0xffffffffu, mx0, 2));
        mx1 = fmaxf(mx1, __shfl_xor_sync(0xffffffffu, mx1, 1));
        mx1 = fmaxf(mx1, __shfl_xor_sync(0xffffffffu, mx1, 2));
        const float mn0 = fmaxf(mr0, mx0), mn1 = fmaxf(mr1, mx1);
        const float a0 = ex2f(mr0 - mn0), a1 = ex2f(mr1 - mn1);
        float su0 = 0.f, su1 = 0.f;
#pragma unroll
        for (int j = 0; j < 8; j++) {
            s[j][0] = ex2f(s[j][0] - mn0);
            s[j][1] = ex2f(s[j][1] - mn0);
            s[j][2] = ex2f(s[j][2] - mn1);
            s[j][3] = ex2f(s[j][3] - mn1);
            su0 += s[j][0] + s[j][1];
            su1 += s[j][2] + s[j][3];
        }
        lr0 = lr0 * a0 + su0;  mr0 = mn0;
        lr1 = lr1 * a1 + su1;  mr1 = mn1;
#pragma unroll
        for (int j = 0; j < 8; j++) {
            o[j][0] *= a0; o[j][1] *= a0;
            o[j][2] *= a1; o[j][3] *= a1;
        }

        if (k0 + 64 < kend) stageK(k0 + 64);   // async K load overlaps PV MMAs

        // ---- O += p . v ----
#pragma unroll
        for (int kd = 0; kd < 4; kd++) {
            const uint32_t pa[4] = { ph16(s[2 * kd][0],     s[2 * kd][1]),
                                     ph16(s[2 * kd][2],     s[2 * kd][3]),
                                     ph16(s[2 * kd + 1][0], s[2 * kd + 1][1]),
                                     ph16(s[2 * kd + 1][2], s[2 * kd + 1][3]) };
#pragma unroll
            for (int p = 0; p < 4; p++) {
                uint32_t v4[4];
                ldmat4t(v4, Vs + SWZ((uint32_t)((kd * 16 + rr) * 128 + (p * 16 + kk8) * 2)));
                mma16816h(o[2 * p],     pa, v4[0], v4[1]);
                mma16816h(o[2 * p + 1], pa, v4[2], v4[3]);
            }
        }
    }

    // ---- epilogue: quad-sum per-lane l, normalize, split-fp16 store ----
    lr0 += __shfl_xor_sync(0xffffffffu, lr0, 1);
    lr0 += __shfl_xor_sync(0xffffffffu, lr0, 2);
    lr1 += __shfl_xor_sync(0xffffffffu, lr1, 1);
    lr1 += __shfl_xor_sync(0xffffffffu, lr1, 2);
    const float inv0 = 1.f / lr0, inv1 = 1.f / lr1;
#pragma unroll
    for (int j = 0; j < 8; j++) {
        const int dh = h * DHH + 8 * j + lc;
        if (qr0 < TQ_) {
            const float v0 = o[j][0] * inv0, v1 = o[j][1] * inv0;
            const size_t ad = ((size_t)qr0 * BB + b) * DD + dh;
            *(uint32_t*)&g_a16h[ad] = ph16(v0, v1);
            *(uint32_t*)&g_a16l[ad] = pl16(v0, v1);
        }
        if (qr1 < TQ_) {
            const float v0 = o[j][2] * inv1, v1 = o[j][3] * inv1;
            const size_t ad = ((size_t)qr1 * BB + b) * DD + dh;
            *(uint32_t*)&g_a16h[ad] = ph16(v0, v1);
            *(uint32_t*)&g_a16l[ad] = pl16(v0, v1);
        }
    }
}

// ---------------------------------------------------------------------------
extern "C" void kernel_launch(void* const* d_in, const int* in_sizes, int n_in,
                              void* d_out, int out_size)
{
    const float* utt = (const float*)d_in[0];
    const float* rc  = (const float*)d_in[1];
    const float* smr = (const float*)d_in[2];
    const float* mem = (const float*)d_in[3];
    const float* Wq  = (const float*)d_in[4];
    const float* bq  = (const float*)d_in[5];
    const float* Wkv = (const float*)d_in[6];
    const float* bkv = (const float*)d_in[7];
    const float* Wo  = (const float*)d_in[8];
    const float* bo  = (const float*)d_in[9];
    const int*   len = (const int*)d_in[10];
    const unsigned char* am = (const unsigned char*)d_in[11];
    float* out = (float*)d_out;

    const int gemm_smem = 81920;   // 2 stages x 40KB
    const int attn_smem = 32768;   // Q 16K + K 8K + V 8K
    cudaFuncSetAttribute(qkv_gemm, cudaFuncAttributeMaxDynamicSharedMemorySize, gemm_smem);
    cudaFuncSetAttribute(o_gemm,   cudaFuncAttributeMaxDynamicSharedMemorySize, gemm_smem);
    cudaFuncSetAttribute(attn_kernel, cudaFuncAttributeMaxDynamicSharedMemorySize, attn_smem);

    __half *qinh, *qinl, *kvinh, *kvinl, *ah, *al, *wm;
    cudaGetSymbolAddress((void**)&qinh,  g_qin_h);
    cudaGetSymbolAddress((void**)&qinl,  g_qin_l);
    cudaGetSymbolAddress((void**)&kvinh, g_kvin_h);
    cudaGetSymbolAddress((void**)&kvinl, g_kvin_l);
    cudaGetSymbolAddress((void**)&ah,    g_a16h);
    cudaGetSymbolAddress((void**)&al,    g_a16l);
    cudaGetSymbolAddress((void**)&wm,    g_w16);

    mask_kernel<<<(TQ_ * TK_ + 255) / 256, 256>>>(am);
    convert_all_kernel<<<dim3((TQ_ * BB * DD / 4 + 255) / 256, 3), 256>>>(
        utt, rc, smr, mem, Wq, Wkv, Wo);
    qkv_gemm<<<dim3(16, 69, 2), 256, gemm_smem>>>(qinh, qinl, kvinh, kvinl, wm, bq, bkv);
    attn_kernel<<<dim3(9, 64), 256, attn_smem>>>(len);
    o_gemm<<<dim3(8, 69), 256, gemm_smem>>>(ah, al, wm + (size_t)1536 * DD, bo, out);
}